// round 3
// baseline (speedup 1.0000x reference)
#include <cuda_runtime.h>

#define NN 100000
#define NE 800000

// ---------------- scratch (static __device__ globals; no allocs) ----------------
__device__ __align__(16) float g_msg2[7 * NN * 32];   // 89.6 MB
__device__ __align__(16) float g_msg1[2 * NN * 16];
__device__ __align__(16) float g_msg0[2 * NN * 6];
__device__ __align__(16) float g_cnt [3 * NN];
__device__ __align__(16) float g_h0  [NN * 16];
__device__ __align__(16) float g_h1  [NN * 32];
__device__ __align__(16) float g_Wc0[3 * 6 * 16];
__device__ __align__(16) float g_Wc1[3 * 16 * 32];
__device__ __align__(16) float g_Wc2[8 * 32 * 64];
__device__ __align__(16) float g_bc0[16];
__device__ __align__(16) float g_bc1[32];
__device__ __align__(16) float g_bc2[64];

// ---------------- helpers ----------------
__device__ __forceinline__ void red_add_v4(float* a, float4 v) {
    asm volatile("red.global.add.v4.f32 [%0], {%1,%2,%3,%4};"
                 :: "l"(a), "f"(v.x), "f"(v.y), "f"(v.z), "f"(v.w) : "memory");
}
__device__ __forceinline__ void red_add_v2(float* a, float2 v) {
    asm volatile("red.global.add.v2.f32 [%0], {%1,%2};"
                 :: "l"(a), "f"(v.x), "f"(v.y) : "memory");
}
__device__ __forceinline__ void red_add_f(float* a, float v) {
    asm volatile("red.global.add.f32 [%0], %1;" :: "l"(a), "f"(v) : "memory");
}
__device__ __forceinline__ unsigned long long pack2(float a, float b) {
    unsigned long long r;
    asm("mov.b64 %0, {%1, %2};" : "=l"(r) : "f"(a), "f"(b));
    return r;
}
__device__ __forceinline__ void unpack2(float& a, float& b, unsigned long long r) {
    asm("mov.b64 {%0, %1}, %2;" : "=f"(a), "=f"(b) : "l"(r));
}
// packed dual-FMA: acc(2xf32) += w(2xf32) * m(2xf32)
__device__ __forceinline__ void ffma2(unsigned long long& acc, unsigned long long w,
                                      unsigned long long m) {
    asm("fma.rn.f32x2 %0, %1, %2, %0;" : "+l"(acc) : "l"(w), "l"(m));
}

struct ESet { const int* e[7]; float* cnt[7]; };
struct GSrc { const float* p[8]; const float* cnt[8]; };

// ---------------- zero scratch ----------------
__global__ void k_zero() {
    int tid = blockIdx.x * blockDim.x + threadIdx.x;
    int stride = gridDim.x * blockDim.x;
    float4 z = make_float4(0.f, 0.f, 0.f, 0.f);
    float4* a2 = reinterpret_cast<float4*>(g_msg2);
    for (int i = tid; i < 7 * NN * 32 / 4; i += stride) a2[i] = z;
    float4* a1 = reinterpret_cast<float4*>(g_msg1);
    for (int i = tid; i < 2 * NN * 16 / 4; i += stride) a1[i] = z;
    float4* a0 = reinterpret_cast<float4*>(g_msg0);
    for (int i = tid; i < 2 * NN * 6 / 4; i += stride) a0[i] = z;
    float4* ac = reinterpret_cast<float4*>(g_cnt);
    for (int i = tid; i < 3 * NN / 4; i += stride) ac[i] = z;
}

// ---------------- combine weights (self terms + residual projections folded) ----------------
__global__ void k_prep(const float* __restrict__ W0n, const float* __restrict__ W0r,
                       const float* __restrict__ b0,
                       const float* __restrict__ W1n, const float* __restrict__ W1r,
                       const float* __restrict__ b1,  const float* __restrict__ P1,
                       const float* __restrict__ pb1,
                       const float* __restrict__ W2n, const float* __restrict__ W2r,
                       const float* __restrict__ b2,  const float* __restrict__ P2,
                       const float* __restrict__ pb2) {
    int i = blockIdx.x * blockDim.x + threadIdx.x;
    if (i < 192) g_Wc0[i] = W0n[i];
    if (i < 96)  g_Wc0[192 + i] = W0r[i] + W0r[96 + i];
    if (i < 16)  g_bc0[i] = b0[i] + b0[16 + i];
    if (i < 1024) g_Wc1[i] = W1n[i];
    if (i < 512)  g_Wc1[1024 + i] = W1r[i] + W1r[512 + i] + P1[i];
    if (i < 32)   g_bc1[i] = b1[i] + b1[32 + i] + pb1[i];
    if (i < 14336) g_Wc2[i] = W2n[i];
    if (i < 2048) {
        float s = P2[i];
        for (int r = 0; r < 7; r++) s += W2r[r * 2048 + i];
        g_Wc2[14336 + i] = s;
    }
    if (i < 64) {
        float s = pb2[i];
        for (int r = 0; r < 7; r++) s += b2[r * 64 + i];
        g_bc2[i] = s;
    }
}

// ---------------- scatter, lane-per-chunk: L lanes cooperate on one edge ----------------
// D = 4*L floats per node row; lane c handles float4 chunk c. Consecutive lanes
// touch consecutive 16B chunks of one 128B-aligned row -> 1 line per edge for
// both gather and RED (vs 32 lane-distinct lines in the edge-per-thread layout).
template <int L>
__global__ void __launch_bounds__(256)
k_scatter(ESet es, const float* __restrict__ feat, float* __restrict__ msg) {
    constexpr int EPB = 256 / L;
    int t = threadIdx.x;
    int e = blockIdx.x * EPB + t / L;
    int c = t % L;
    if (e >= NE) return;
    int r = blockIdx.y;
    const int* ei = es.e[r];
    int src = __ldg(ei + e);
    int dst = __ldg(ei + NE + e);
    constexpr int D = L * 4;
    float4 v = __ldg(reinterpret_cast<const float4*>(feat + (size_t)src * D) + c);
    red_add_v4(msg + ((size_t)r * NN + dst) * D + 4 * c, v);
    float* cp = es.cnt[r];
    if (cp && c == 0) red_add_f(cp + dst, 1.0f);
}

// ---------------- scatter D=6 (layer 0): 2 lanes per edge, 3 floats each ----------------
__global__ void __launch_bounds__(256)
k_scatter6(ESet es, const float* __restrict__ x, float* __restrict__ msg) {
    int t = threadIdx.x;
    int e = blockIdx.x * 128 + (t >> 1);
    int c = t & 1;
    if (e >= NE) return;
    int r = blockIdx.y;
    const int* ei = es.e[r];
    int src = __ldg(ei + e);
    int dst = __ldg(ei + NE + e);
    const float* xs = x + (size_t)src * 6;
    // lane c: float2 at +2c (8B aligned), scalar at +4+c
    float2 a = __ldg(reinterpret_cast<const float2*>(xs) + c);
    float  s = __ldg(xs + 4 + c);
    float* m = msg + ((size_t)r * NN + dst) * 6;
    red_add_v2(m + 2 * c, a);
    red_add_f(m + 4 + c, s);
}

// ---------------- node-parallel GEMM with packed f32x2 FMA ----------------
// out[node] = act( sum_ch scale_ch(node) * src_ch[node] @ W_ch + bias )
template <int CHUNK, int NCH, int OUT, bool RELU>
__global__ void __launch_bounds__(256)
k_gemm(GSrc s, const float* __restrict__ Wcat, const float* __restrict__ bias,
       float* __restrict__ out) {
    __shared__ __align__(16) float shW[CHUNK * OUT];
    __shared__ float shT[256 * (CHUNK + 1)];
    int tid  = threadIdx.x;
    int base = blockIdx.x * 256;
    int node = base + tid;

    unsigned long long acc[OUT / 2];
#pragma unroll
    for (int j = 0; j < OUT / 2; j++) acc[j] = pack2(bias[2 * j], bias[2 * j + 1]);

    for (int ch = 0; ch < NCH; ch++) {
        __syncthreads();
        for (int i = tid; i < CHUNK * OUT; i += 256)
            shW[i] = Wcat[ch * CHUNK * OUT + i];
        const float* src = s.p[ch];
        for (int i = tid; i < 256 * CHUNK; i += 256) {
            int nl = i / CHUNK, k = i - nl * CHUNK;
            int nd = base + nl;
            shT[nl * (CHUNK + 1) + k] = (nd < NN) ? src[(size_t)nd * CHUNK + k] : 0.f;
        }
        __syncthreads();
        float sc = 1.f;
        const float* cp = s.cnt[ch];
        if (cp != nullptr && node < NN) sc = 1.f / fmaxf(cp[node], 1.f);
#pragma unroll 4
        for (int k = 0; k < CHUNK; k++) {
            float m = shT[tid * (CHUNK + 1) + k] * sc;
            unsigned long long m2 = pack2(m, m);
            const ulonglong2* w = reinterpret_cast<const ulonglong2*>(shW + k * OUT);
#pragma unroll
            for (int j = 0; j < OUT / 4; j++) {
                ulonglong2 ww = w[j];
                ffma2(acc[2 * j],     ww.x, m2);
                ffma2(acc[2 * j + 1], ww.y, m2);
            }
        }
    }

    if (node < NN) {
        float4* o4 = reinterpret_cast<float4*>(out + (size_t)node * OUT);
#pragma unroll
        for (int j = 0; j < OUT / 4; j++) {
            float4 v;
            unpack2(v.x, v.y, acc[2 * j]);
            unpack2(v.z, v.w, acc[2 * j + 1]);
            if (RELU) {
                v.x = fmaxf(v.x, 0.f); v.y = fmaxf(v.y, 0.f);
                v.z = fmaxf(v.z, 0.f); v.w = fmaxf(v.w, 0.f);
            }
            o4[j] = v;
        }
    }
}

// ---------------- host ----------------
extern "C" void kernel_launch(void* const* d_in, const int* in_sizes, int n_in,
                              void* d_out, int out_size) {
    (void)n_in; (void)out_size;
    const float* x = (const float*)d_in[0];

    int eb, wb;
    if (in_sizes[1] == 2 * NE) { eb = 1; wb = 10; }
    else                        { wb = 1; eb = 14; }

    const int* E[9];
    for (int i = 0; i < 9; i++) E[i] = (const int*)d_in[eb + i];
    const float* W0n = (const float*)d_in[wb + 0];
    const float* W0r = (const float*)d_in[wb + 1];
    const float* b0  = (const float*)d_in[wb + 2];
    const float* W1n = (const float*)d_in[wb + 3];
    const float* W1r = (const float*)d_in[wb + 4];
    const float* b1  = (const float*)d_in[wb + 5];
    const float* P1  = (const float*)d_in[wb + 6];
    const float* pb1 = (const float*)d_in[wb + 7];
    const float* W2n = (const float*)d_in[wb + 8];
    const float* W2r = (const float*)d_in[wb + 9];
    const float* b2  = (const float*)d_in[wb + 10];
    const float* P2  = (const float*)d_in[wb + 11];
    const float* pb2 = (const float*)d_in[wb + 12];

    float *msg2, *msg1, *msg0, *cnt, *h0, *h1, *Wc0, *Wc1, *Wc2, *bc0, *bc1, *bc2;
    cudaGetSymbolAddress((void**)&msg2, g_msg2);
    cudaGetSymbolAddress((void**)&msg1, g_msg1);
    cudaGetSymbolAddress((void**)&msg0, g_msg0);
    cudaGetSymbolAddress((void**)&cnt,  g_cnt);
    cudaGetSymbolAddress((void**)&h0,   g_h0);
    cudaGetSymbolAddress((void**)&h1,   g_h1);
    cudaGetSymbolAddress((void**)&Wc0,  g_Wc0);
    cudaGetSymbolAddress((void**)&Wc1,  g_Wc1);
    cudaGetSymbolAddress((void**)&Wc2,  g_Wc2);
    cudaGetSymbolAddress((void**)&bc0,  g_bc0);
    cudaGetSymbolAddress((void**)&bc1,  g_bc1);
    cudaGetSymbolAddress((void**)&bc2,  g_bc2);

    k_zero<<<2048, 256>>>();
    k_prep<<<56, 256>>>(W0n, W0r, b0, W1n, W1r, b1, P1, pb1, W2n, W2r, b2, P2, pb2);

    // ---- layer 0: x(6) -> h0(16), relations {connected_to, ordered_next}, sum ----
    ESet es01 = {};
    es01.e[0] = E[0]; es01.e[1] = E[1];
    k_scatter6<<<dim3((NE + 127) / 128, 2), 256>>>(es01, x, msg0);

    GSrc s0 = {};
    s0.p[0] = msg0; s0.p[1] = msg0 + (size_t)NN * 6; s0.p[2] = x;
    k_gemm<6, 3, 16, false><<<(NN + 255) / 256, 256>>>(s0, Wc0, bc0, h0);

    // ---- layer 1: h0(16) -> h1(32), same relations, + P1 residual, relu ----
    k_scatter<4><<<dim3((NE + 63) / 64, 2), 256>>>(es01, h0, msg1);

    GSrc s1 = {};
    s1.p[0] = msg1; s1.p[1] = msg1 + (size_t)NN * 16; s1.p[2] = h0;
    k_gemm<16, 3, 32, true><<<(NN + 255) / 256, 256>>>(s1, Wc1, bc1, h1);

    // ---- layer 2: h1(32) -> out(64), 7 relations (mean at 2,3,6), + P2, relu ----
    ESet es2 = {};
    for (int r = 0; r < 7; r++) es2.e[r] = E[2 + r];
    es2.cnt[2] = cnt; es2.cnt[3] = cnt + NN; es2.cnt[6] = cnt + 2 * NN;
    k_scatter<8><<<dim3((NE + 31) / 32, 7), 256>>>(es2, h1, msg2);

    GSrc s2 = {};
    for (int r = 0; r < 7; r++) s2.p[r] = msg2 + (size_t)r * NN * 32;
    s2.p[7] = h1;
    s2.cnt[2] = cnt; s2.cnt[3] = cnt + NN; s2.cnt[6] = cnt + 2 * NN;
    k_gemm<32, 8, 64, true><<<(NN + 255) / 256, 256>>>(s2, Wc2, bc2, (float*)d_out);
}

// round 4
// speedup vs baseline: 1.0783x; 1.0783x over previous
#include <cuda_runtime.h>

#define NN 100000
#define NE 800000

// ---------------- scratch (static __device__ globals; no allocs) ----------------
__device__ __align__(16) float g_msg2[7 * NN * 32];   // 89.6 MB
__device__ __align__(16) float g_msg1[2 * NN * 16];
__device__ __align__(16) float g_msg0[2 * NN * 6];
__device__ __align__(16) float g_cnt [3 * NN];
__device__ __align__(16) float g_h0  [NN * 16];
__device__ __align__(16) float g_h1  [NN * 32];
__device__ __align__(16) float g_Wc0[3 * 6 * 16];
__device__ __align__(16) float g_Wc1[3 * 16 * 32];
__device__ __align__(16) float g_Wc2[8 * 32 * 64];
__device__ __align__(16) float g_bc0[16];
__device__ __align__(16) float g_bc1[32];
__device__ __align__(16) float g_bc2[64];

// ---------------- helpers ----------------
__device__ __forceinline__ void red_add_v4(float* a, float4 v) {
    asm volatile("red.global.add.v4.f32 [%0], {%1,%2,%3,%4};"
                 :: "l"(a), "f"(v.x), "f"(v.y), "f"(v.z), "f"(v.w) : "memory");
}
__device__ __forceinline__ void red_add_v2(float* a, float2 v) {
    asm volatile("red.global.add.v2.f32 [%0], {%1,%2};"
                 :: "l"(a), "f"(v.x), "f"(v.y) : "memory");
}
__device__ __forceinline__ void red_add_f(float* a, float v) {
    asm volatile("red.global.add.f32 [%0], %1;" :: "l"(a), "f"(v) : "memory");
}

struct ESet { const int* e[7]; float* cnt[7]; };
struct GSrc { const float* p[8]; const float* cnt[8]; };

// ---------------- zero scratch ----------------
__global__ void k_zero() {
    int tid = blockIdx.x * blockDim.x + threadIdx.x;
    int stride = gridDim.x * blockDim.x;
    float4 z = make_float4(0.f, 0.f, 0.f, 0.f);
    float4* a2 = reinterpret_cast<float4*>(g_msg2);
    for (int i = tid; i < 7 * NN * 32 / 4; i += stride) a2[i] = z;
    float4* a1 = reinterpret_cast<float4*>(g_msg1);
    for (int i = tid; i < 2 * NN * 16 / 4; i += stride) a1[i] = z;
    float4* a0 = reinterpret_cast<float4*>(g_msg0);
    for (int i = tid; i < 2 * NN * 6 / 4; i += stride) a0[i] = z;
    float4* ac = reinterpret_cast<float4*>(g_cnt);
    for (int i = tid; i < 3 * NN / 4; i += stride) ac[i] = z;
}

// ---------------- combine weights (self terms + residual projections folded) ----------------
__global__ void k_prep(const float* __restrict__ W0n, const float* __restrict__ W0r,
                       const float* __restrict__ b0,
                       const float* __restrict__ W1n, const float* __restrict__ W1r,
                       const float* __restrict__ b1,  const float* __restrict__ P1,
                       const float* __restrict__ pb1,
                       const float* __restrict__ W2n, const float* __restrict__ W2r,
                       const float* __restrict__ b2,  const float* __restrict__ P2,
                       const float* __restrict__ pb2) {
    int i = blockIdx.x * blockDim.x + threadIdx.x;
    if (i < 192) g_Wc0[i] = W0n[i];
    if (i < 96)  g_Wc0[192 + i] = W0r[i] + W0r[96 + i];
    if (i < 16)  g_bc0[i] = b0[i] + b0[16 + i];
    if (i < 1024) g_Wc1[i] = W1n[i];
    if (i < 512)  g_Wc1[1024 + i] = W1r[i] + W1r[512 + i] + P1[i];
    if (i < 32)   g_bc1[i] = b1[i] + b1[32 + i] + pb1[i];
    if (i < 14336) g_Wc2[i] = W2n[i];
    if (i < 2048) {
        float s = P2[i];
        for (int r = 0; r < 7; r++) s += W2r[r * 2048 + i];
        g_Wc2[14336 + i] = s;
    }
    if (i < 64) {
        float s = pb2[i];
        for (int r = 0; r < 7; r++) s += b2[r * 64 + i];
        g_bc2[i] = s;
    }
}

// ---------------- scatter, lane-per-chunk: L lanes cooperate on one edge ----------------
// D = 4*L floats per node row; lane c handles float4 chunk c. Consecutive lanes
// touch consecutive 16B chunks of one row -> coalesced gather + coalesced RED.
template <int L>
__global__ void __launch_bounds__(256)
k_scatter(ESet es, const float* __restrict__ feat, float* __restrict__ msg) {
    constexpr int EPB = 256 / L;
    int t = threadIdx.x;
    int e = blockIdx.x * EPB + t / L;
    int c = t % L;
    if (e >= NE) return;
    int r = blockIdx.y;
    const int* ei = es.e[r];
    int src = __ldg(ei + e);
    int dst = __ldg(ei + NE + e);
    constexpr int D = L * 4;
    float4 v = __ldg(reinterpret_cast<const float4*>(feat + (size_t)src * D) + c);
    red_add_v4(msg + ((size_t)r * NN + dst) * D + 4 * c, v);
    float* cp = es.cnt[r];
    if (cp && c == 0) red_add_f(cp + dst, 1.0f);
}

// ---------------- scatter D=6 (layer 0): 2 lanes per edge, 3 floats each ----------------
__global__ void __launch_bounds__(256)
k_scatter6(ESet es, const float* __restrict__ x, float* __restrict__ msg) {
    int t = threadIdx.x;
    int e = blockIdx.x * 128 + (t >> 1);
    int c = t & 1;
    if (e >= NE) return;
    int r = blockIdx.y;
    const int* ei = es.e[r];
    int src = __ldg(ei + e);
    int dst = __ldg(ei + NE + e);
    const float* xs = x + (size_t)src * 6;
    float2 a = __ldg(reinterpret_cast<const float2*>(xs) + c);
    float  s = __ldg(xs + 4 + c);
    float* m = msg + ((size_t)r * NN + dst) * 6;
    red_add_v2(m + 2 * c, a);
    red_add_f(m + 4 + c, s);
}

// ---------------- node-parallel GEMM (plain FFMA, R1-proven form) ----------------
// out[node] = act( sum_ch scale_ch(node) * src_ch[node] @ W_ch + bias )
template <int CHUNK, int NCH, int OUT, bool RELU>
__global__ void __launch_bounds__(256)
k_gemm(GSrc s, const float* __restrict__ Wcat, const float* __restrict__ bias,
       float* __restrict__ out) {
    __shared__ __align__(16) float shW[CHUNK * OUT];
    __shared__ float shT[256 * (CHUNK + 1)];
    int tid  = threadIdx.x;
    int base = blockIdx.x * 256;
    int node = base + tid;

    float acc[OUT];
#pragma unroll
    for (int j = 0; j < OUT; j++) acc[j] = bias[j];

    for (int ch = 0; ch < NCH; ch++) {
        __syncthreads();
        for (int i = tid; i < CHUNK * OUT; i += 256)
            shW[i] = Wcat[ch * CHUNK * OUT + i];
        const float* src = s.p[ch];
        for (int i = tid; i < 256 * CHUNK; i += 256) {
            int nl = i / CHUNK, k = i - nl * CHUNK;
            int nd = base + nl;
            shT[nl * (CHUNK + 1) + k] = (nd < NN) ? src[(size_t)nd * CHUNK + k] : 0.f;
        }
        __syncthreads();
        float sc = 1.f;
        const float* cp = s.cnt[ch];
        if (cp != nullptr && node < NN) sc = 1.f / fmaxf(cp[node], 1.f);
#pragma unroll 8
        for (int k = 0; k < CHUNK; k++) {
            float m = shT[tid * (CHUNK + 1) + k] * sc;
            const float4* w4 = reinterpret_cast<const float4*>(shW + k * OUT);
#pragma unroll
            for (int j = 0; j < OUT / 4; j++) {
                float4 w = w4[j];
                acc[4 * j + 0] += m * w.x;
                acc[4 * j + 1] += m * w.y;
                acc[4 * j + 2] += m * w.z;
                acc[4 * j + 3] += m * w.w;
            }
        }
    }

    if (node < NN) {
        float4* o4 = reinterpret_cast<float4*>(out + (size_t)node * OUT);
#pragma unroll
        for (int j = 0; j < OUT / 4; j++) {
            float4 v;
            v.x = acc[4 * j + 0]; v.y = acc[4 * j + 1];
            v.z = acc[4 * j + 2]; v.w = acc[4 * j + 3];
            if (RELU) {
                v.x = fmaxf(v.x, 0.f); v.y = fmaxf(v.y, 0.f);
                v.z = fmaxf(v.z, 0.f); v.w = fmaxf(v.w, 0.f);
            }
            o4[j] = v;
        }
    }
}

// ---------------- host ----------------
extern "C" void kernel_launch(void* const* d_in, const int* in_sizes, int n_in,
                              void* d_out, int out_size) {
    (void)n_in; (void)out_size;
    const float* x = (const float*)d_in[0];

    int eb, wb;
    if (in_sizes[1] == 2 * NE) { eb = 1; wb = 10; }
    else                        { wb = 1; eb = 14; }

    const int* E[9];
    for (int i = 0; i < 9; i++) E[i] = (const int*)d_in[eb + i];
    const float* W0n = (const float*)d_in[wb + 0];
    const float* W0r = (const float*)d_in[wb + 1];
    const float* b0  = (const float*)d_in[wb + 2];
    const float* W1n = (const float*)d_in[wb + 3];
    const float* W1r = (const float*)d_in[wb + 4];
    const float* b1  = (const float*)d_in[wb + 5];
    const float* P1  = (const float*)d_in[wb + 6];
    const float* pb1 = (const float*)d_in[wb + 7];
    const float* W2n = (const float*)d_in[wb + 8];
    const float* W2r = (const float*)d_in[wb + 9];
    const float* b2  = (const float*)d_in[wb + 10];
    const float* P2  = (const float*)d_in[wb + 11];
    const float* pb2 = (const float*)d_in[wb + 12];

    float *msg2, *msg1, *msg0, *cnt, *h0, *h1, *Wc0, *Wc1, *Wc2, *bc0, *bc1, *bc2;
    cudaGetSymbolAddress((void**)&msg2, g_msg2);
    cudaGetSymbolAddress((void**)&msg1, g_msg1);
    cudaGetSymbolAddress((void**)&msg0, g_msg0);
    cudaGetSymbolAddress((void**)&cnt,  g_cnt);
    cudaGetSymbolAddress((void**)&h0,   g_h0);
    cudaGetSymbolAddress((void**)&h1,   g_h1);
    cudaGetSymbolAddress((void**)&Wc0,  g_Wc0);
    cudaGetSymbolAddress((void**)&Wc1,  g_Wc1);
    cudaGetSymbolAddress((void**)&Wc2,  g_Wc2);
    cudaGetSymbolAddress((void**)&bc0,  g_bc0);
    cudaGetSymbolAddress((void**)&bc1,  g_bc1);
    cudaGetSymbolAddress((void**)&bc2,  g_bc2);

    k_zero<<<2048, 256>>>();
    k_prep<<<56, 256>>>(W0n, W0r, b0, W1n, W1r, b1, P1, pb1, W2n, W2r, b2, P2, pb2);

    // ---- layer 0: x(6) -> h0(16), relations {connected_to, ordered_next}, sum ----
    ESet es01 = {};
    es01.e[0] = E[0]; es01.e[1] = E[1];
    k_scatter6<<<dim3((NE + 127) / 128, 2), 256>>>(es01, x, msg0);

    GSrc s0 = {};
    s0.p[0] = msg0; s0.p[1] = msg0 + (size_t)NN * 6; s0.p[2] = x;
    k_gemm<6, 3, 16, false><<<(NN + 255) / 256, 256>>>(s0, Wc0, bc0, h0);

    // ---- layer 1: h0(16) -> h1(32), same relations, + P1 residual, relu ----
    k_scatter<4><<<dim3((NE + 63) / 64, 2), 256>>>(es01, h0, msg1);

    GSrc s1 = {};
    s1.p[0] = msg1; s1.p[1] = msg1 + (size_t)NN * 16; s1.p[2] = h0;
    k_gemm<16, 3, 32, true><<<(NN + 255) / 256, 256>>>(s1, Wc1, bc1, h1);

    // ---- layer 2: h1(32) -> out(64), 7 relations (mean at 2,3,6), + P2, relu ----
    ESet es2 = {};
    for (int r = 0; r < 7; r++) es2.e[r] = E[2 + r];
    es2.cnt[2] = cnt; es2.cnt[3] = cnt + NN; es2.cnt[6] = cnt + 2 * NN;
    k_scatter<8><<<dim3((NE + 31) / 32, 7), 256>>>(es2, h1, msg2);

    GSrc s2 = {};
    for (int r = 0; r < 7; r++) s2.p[r] = msg2 + (size_t)r * NN * 32;
    s2.p[7] = h1;
    s2.cnt[2] = cnt; s2.cnt[3] = cnt + NN; s2.cnt[6] = cnt + 2 * NN;
    k_gemm<32, 8, 64, true><<<(NN + 255) / 256, 256>>>(s2, Wc2, bc2, (float*)d_out);
}

// round 5
// speedup vs baseline: 1.9951x; 1.8503x over previous
#include <cuda_runtime.h>

#define NN 100000
#define NE 800000

// ---------------- scratch (static __device__ globals; no allocs) ----------------
__device__ __align__(16) float g_msg2[7 * NN * 32];   // 89.6 MB
__device__ __align__(16) float g_msg1[2 * NN * 16];
__device__ __align__(16) float g_msg0[2 * NN * 6];
__device__ __align__(16) float g_cnt [3 * NN];
__device__ __align__(16) float g_h0  [NN * 16];
__device__ __align__(16) float g_h1  [NN * 32];
__device__ __align__(16) float g_Wc0[3 * 6 * 16];
__device__ __align__(16) float g_Wc1[3 * 16 * 32];
__device__ __align__(16) float g_Wc2[8 * 32 * 64];
__device__ __align__(16) float g_bc0[16];
__device__ __align__(16) float g_bc1[32];
__device__ __align__(16) float g_bc2[64];

// ---------------- helpers ----------------
__device__ __forceinline__ void red_add_v4(float* a, float4 v) {
    asm volatile("red.global.add.v4.f32 [%0], {%1,%2,%3,%4};"
                 :: "l"(a), "f"(v.x), "f"(v.y), "f"(v.z), "f"(v.w) : "memory");
}
__device__ __forceinline__ void red_add_v2(float* a, float2 v) {
    asm volatile("red.global.add.v2.f32 [%0], {%1,%2};"
                 :: "l"(a), "f"(v.x), "f"(v.y) : "memory");
}
__device__ __forceinline__ void red_add_f(float* a, float v) {
    asm volatile("red.global.add.f32 [%0], %1;" :: "l"(a), "f"(v) : "memory");
}

struct ESet { const int* e[7]; float* cnt[7]; };
struct GSrc { const float* p[8]; const float* cnt[8]; };

// ---------------- zero scratch ----------------
__global__ void k_zero() {
    int tid = blockIdx.x * blockDim.x + threadIdx.x;
    int stride = gridDim.x * blockDim.x;
    float4 z = make_float4(0.f, 0.f, 0.f, 0.f);
    float4* a2 = reinterpret_cast<float4*>(g_msg2);
    for (int i = tid; i < 7 * NN * 32 / 4; i += stride) a2[i] = z;
    float4* a1 = reinterpret_cast<float4*>(g_msg1);
    for (int i = tid; i < 2 * NN * 16 / 4; i += stride) a1[i] = z;
    float4* a0 = reinterpret_cast<float4*>(g_msg0);
    for (int i = tid; i < 2 * NN * 6 / 4; i += stride) a0[i] = z;
    float4* ac = reinterpret_cast<float4*>(g_cnt);
    for (int i = tid; i < 3 * NN / 4; i += stride) ac[i] = z;
}

// ---------------- combine weights (self terms + residual projections folded) ----------------
__global__ void k_prep(const float* __restrict__ W0n, const float* __restrict__ W0r,
                       const float* __restrict__ b0,
                       const float* __restrict__ W1n, const float* __restrict__ W1r,
                       const float* __restrict__ b1,  const float* __restrict__ P1,
                       const float* __restrict__ pb1,
                       const float* __restrict__ W2n, const float* __restrict__ W2r,
                       const float* __restrict__ b2,  const float* __restrict__ P2,
                       const float* __restrict__ pb2) {
    int i = blockIdx.x * blockDim.x + threadIdx.x;
    if (i < 192) g_Wc0[i] = W0n[i];
    if (i < 96)  g_Wc0[192 + i] = W0r[i] + W0r[96 + i];
    if (i < 16)  g_bc0[i] = b0[i] + b0[16 + i];
    if (i < 1024) g_Wc1[i] = W1n[i];
    if (i < 512)  g_Wc1[1024 + i] = W1r[i] + W1r[512 + i] + P1[i];
    if (i < 32)   g_bc1[i] = b1[i] + b1[32 + i] + pb1[i];
    if (i < 14336) g_Wc2[i] = W2n[i];
    if (i < 2048) {
        float s = P2[i];
        for (int r = 0; r < 7; r++) s += W2r[r * 2048 + i];
        g_Wc2[14336 + i] = s;
    }
    if (i < 64) {
        float s = pb2[i];
        for (int r = 0; r < 7; r++) s += b2[r * 64 + i];
        g_bc2[i] = s;
    }
}

// ---------------- warp-cooperative scatter, D = 32 floats/row ----------------
// Warp owns 32 edges (NE % 32 == 0). Indices loaded coalesced once; 8 batches of
// 4 edges x 8 lanes; per batch each edge's 128B row is gathered and RED-added as
// ONE line (8 consecutive 16B chunks) instead of 8 scattered lines.
__global__ void __launch_bounds__(256)
k_scatter32(ESet es, const float* __restrict__ feat, float* __restrict__ msg) {
    int lane = threadIdx.x & 31;
    int warp = (blockIdx.x * 256 + threadIdx.x) >> 5;
    int e = warp * 32 + lane;
    int r = blockIdx.y;
    const int* ei = es.e[r];
    int src = __ldg(ei + e);
    int dst = __ldg(ei + NE + e);
    float* cp = es.cnt[r];
    if (cp) red_add_f(cp + dst, 1.0f);
    int sub = lane >> 3;   // edge-within-batch 0..3
    int c   = lane & 7;    // chunk 0..7
#pragma unroll
    for (int j = 0; j < 8; j++) {
        int el = j * 4 + sub;
        int s = __shfl_sync(0xffffffffu, src, el);
        int d = __shfl_sync(0xffffffffu, dst, el);
        float4 v = __ldg(reinterpret_cast<const float4*>(feat + (size_t)s * 32) + c);
        red_add_v4(msg + ((size_t)r * NN + d) * 32 + 4 * c, v);
    }
}

// ---------------- warp-cooperative scatter, D = 16 floats/row ----------------
// 4 batches of 8 edges x 4 lanes; each row = one 64B half-line per edge.
__global__ void __launch_bounds__(256)
k_scatter16(ESet es, const float* __restrict__ feat, float* __restrict__ msg) {
    int lane = threadIdx.x & 31;
    int warp = (blockIdx.x * 256 + threadIdx.x) >> 5;
    int e = warp * 32 + lane;
    int r = blockIdx.y;
    const int* ei = es.e[r];
    int src = __ldg(ei + e);
    int dst = __ldg(ei + NE + e);
    int sub = lane >> 2;   // edge-within-batch 0..7
    int c   = lane & 3;    // chunk 0..3
#pragma unroll
    for (int j = 0; j < 4; j++) {
        int el = j * 8 + sub;
        int s = __shfl_sync(0xffffffffu, src, el);
        int d = __shfl_sync(0xffffffffu, dst, el);
        float4 v = __ldg(reinterpret_cast<const float4*>(feat + (size_t)s * 16) + c);
        red_add_v4(msg + ((size_t)r * NN + d) * 16 + 4 * c, v);
    }
}

// ---------------- warp-cooperative scatter, D = 6 floats/row (layer 0) ----------------
// 2 batches of 16 edges x 2 lanes; lane c handles float2@2c + scalar@4+c.
__global__ void __launch_bounds__(256)
k_scatter6(ESet es, const float* __restrict__ x, float* __restrict__ msg) {
    int lane = threadIdx.x & 31;
    int warp = (blockIdx.x * 256 + threadIdx.x) >> 5;
    int e = warp * 32 + lane;
    int r = blockIdx.y;
    const int* ei = es.e[r];
    int src = __ldg(ei + e);
    int dst = __ldg(ei + NE + e);
    int sub = lane >> 1;   // edge-within-batch 0..15
    int c   = lane & 1;    // half 0..1
#pragma unroll
    for (int j = 0; j < 2; j++) {
        int el = j * 16 + sub;
        int s = __shfl_sync(0xffffffffu, src, el);
        int d = __shfl_sync(0xffffffffu, dst, el);
        const float* xs = x + (size_t)s * 6;
        float2 a = __ldg(reinterpret_cast<const float2*>(xs) + c);
        float  v = __ldg(xs + 4 + c);
        float* m = msg + ((size_t)r * NN + d) * 6;
        red_add_v2(m + 2 * c, a);
        red_add_f(m + 4 + c, v);
    }
}

// ---------------- node-parallel GEMM (plain FFMA, R1-proven form) ----------------
template <int CHUNK, int NCH, int OUT, bool RELU>
__global__ void __launch_bounds__(256)
k_gemm(GSrc s, const float* __restrict__ Wcat, const float* __restrict__ bias,
       float* __restrict__ out) {
    __shared__ __align__(16) float shW[CHUNK * OUT];
    __shared__ float shT[256 * (CHUNK + 1)];
    int tid  = threadIdx.x;
    int base = blockIdx.x * 256;
    int node = base + tid;

    float acc[OUT];
#pragma unroll
    for (int j = 0; j < OUT; j++) acc[j] = bias[j];

    for (int ch = 0; ch < NCH; ch++) {
        __syncthreads();
        for (int i = tid; i < CHUNK * OUT; i += 256)
            shW[i] = Wcat[ch * CHUNK * OUT + i];
        const float* src = s.p[ch];
        for (int i = tid; i < 256 * CHUNK; i += 256) {
            int nl = i / CHUNK, k = i - nl * CHUNK;
            int nd = base + nl;
            shT[nl * (CHUNK + 1) + k] = (nd < NN) ? src[(size_t)nd * CHUNK + k] : 0.f;
        }
        __syncthreads();
        float sc = 1.f;
        const float* cp = s.cnt[ch];
        if (cp != nullptr && node < NN) sc = 1.f / fmaxf(cp[node], 1.f);
#pragma unroll 8
        for (int k = 0; k < CHUNK; k++) {
            float m = shT[tid * (CHUNK + 1) + k] * sc;
            const float4* w4 = reinterpret_cast<const float4*>(shW + k * OUT);
#pragma unroll
            for (int j = 0; j < OUT / 4; j++) {
                float4 w = w4[j];
                acc[4 * j + 0] += m * w.x;
                acc[4 * j + 1] += m * w.y;
                acc[4 * j + 2] += m * w.z;
                acc[4 * j + 3] += m * w.w;
            }
        }
    }

    if (node < NN) {
        float4* o4 = reinterpret_cast<float4*>(out + (size_t)node * OUT);
#pragma unroll
        for (int j = 0; j < OUT / 4; j++) {
            float4 v;
            v.x = acc[4 * j + 0]; v.y = acc[4 * j + 1];
            v.z = acc[4 * j + 2]; v.w = acc[4 * j + 3];
            if (RELU) {
                v.x = fmaxf(v.x, 0.f); v.y = fmaxf(v.y, 0.f);
                v.z = fmaxf(v.z, 0.f); v.w = fmaxf(v.w, 0.f);
            }
            o4[j] = v;
        }
    }
}

// ---------------- host ----------------
extern "C" void kernel_launch(void* const* d_in, const int* in_sizes, int n_in,
                              void* d_out, int out_size) {
    (void)n_in; (void)out_size;
    const float* x = (const float*)d_in[0];

    int eb, wb;
    if (in_sizes[1] == 2 * NE) { eb = 1; wb = 10; }
    else                        { wb = 1; eb = 14; }

    const int* E[9];
    for (int i = 0; i < 9; i++) E[i] = (const int*)d_in[eb + i];
    const float* W0n = (const float*)d_in[wb + 0];
    const float* W0r = (const float*)d_in[wb + 1];
    const float* b0  = (const float*)d_in[wb + 2];
    const float* W1n = (const float*)d_in[wb + 3];
    const float* W1r = (const float*)d_in[wb + 4];
    const float* b1  = (const float*)d_in[wb + 5];
    const float* P1  = (const float*)d_in[wb + 6];
    const float* pb1 = (const float*)d_in[wb + 7];
    const float* W2n = (const float*)d_in[wb + 8];
    const float* W2r = (const float*)d_in[wb + 9];
    const float* b2  = (const float*)d_in[wb + 10];
    const float* P2  = (const float*)d_in[wb + 11];
    const float* pb2 = (const float*)d_in[wb + 12];

    float *msg2, *msg1, *msg0, *cnt, *h0, *h1, *Wc0, *Wc1, *Wc2, *bc0, *bc1, *bc2;
    cudaGetSymbolAddress((void**)&msg2, g_msg2);
    cudaGetSymbolAddress((void**)&msg1, g_msg1);
    cudaGetSymbolAddress((void**)&msg0, g_msg0);
    cudaGetSymbolAddress((void**)&cnt,  g_cnt);
    cudaGetSymbolAddress((void**)&h0,   g_h0);
    cudaGetSymbolAddress((void**)&h1,   g_h1);
    cudaGetSymbolAddress((void**)&Wc0,  g_Wc0);
    cudaGetSymbolAddress((void**)&Wc1,  g_Wc1);
    cudaGetSymbolAddress((void**)&Wc2,  g_Wc2);
    cudaGetSymbolAddress((void**)&bc0,  g_bc0);
    cudaGetSymbolAddress((void**)&bc1,  g_bc1);
    cudaGetSymbolAddress((void**)&bc2,  g_bc2);

    k_zero<<<2048, 256>>>();
    k_prep<<<56, 256>>>(W0n, W0r, b0, W1n, W1r, b1, P1, pb1, W2n, W2r, b2, P2, pb2);

    // ---- layer 0: x(6) -> h0(16), relations {connected_to, ordered_next}, sum ----
    ESet es01 = {};
    es01.e[0] = E[0]; es01.e[1] = E[1];
    k_scatter6<<<dim3(NE / 256, 2), 256>>>(es01, x, msg0);

    GSrc s0 = {};
    s0.p[0] = msg0; s0.p[1] = msg0 + (size_t)NN * 6; s0.p[2] = x;
    k_gemm<6, 3, 16, false><<<(NN + 255) / 256, 256>>>(s0, Wc0, bc0, h0);

    // ---- layer 1: h0(16) -> h1(32), same relations, + P1 residual, relu ----
    k_scatter16<<<dim3(NE / 256, 2), 256>>>(es01, h0, msg1);

    GSrc s1 = {};
    s1.p[0] = msg1; s1.p[1] = msg1 + (size_t)NN * 16; s1.p[2] = h0;
    k_gemm<16, 3, 32, true><<<(NN + 255) / 256, 256>>>(s1, Wc1, bc1, h1);

    // ---- layer 2: h1(32) -> out(64), 7 relations (mean at 2,3,6), + P2, relu ----
    ESet es2 = {};
    for (int r = 0; r < 7; r++) es2.e[r] = E[2 + r];
    es2.cnt[2] = cnt; es2.cnt[3] = cnt + NN; es2.cnt[6] = cnt + 2 * NN;
    k_scatter32<<<dim3(NE / 256, 7), 256>>>(es2, h1, msg2);

    GSrc s2 = {};
    for (int r = 0; r < 7; r++) s2.p[r] = msg2 + (size_t)r * NN * 32;
    s2.p[7] = h1;
    s2.cnt[2] = cnt; s2.cnt[3] = cnt + NN; s2.cnt[6] = cnt + 2 * NN;
    k_gemm<32, 8, 64, true><<<(NN + 255) / 256, 256>>>(s2, Wc2, bc2, (float*)d_out);
}

// round 6
// speedup vs baseline: 2.8632x; 1.4351x over previous
#include <cuda_runtime.h>

#define NN 100000
#define NE 800000

// ---------------- scratch (static __device__ globals; no allocs) ----------------
__device__ __align__(16) float g_msg2[7 * NN * 32];   // 89.6 MB
__device__ __align__(16) float g_msg1[2 * NN * 16];
__device__ __align__(16) float g_msg0[2 * NN * 6];
__device__ __align__(16) float g_cnt [3 * NN];
__device__ __align__(16) float g_h0  [NN * 16];
__device__ __align__(16) float g_h1  [NN * 32];
__device__ __align__(16) float g_Wc0[3 * 6 * 16];
__device__ __align__(16) float g_Wc1[3 * 16 * 32];
__device__ __align__(16) float g_Wc2[8 * 32 * 64];
__device__ __align__(16) float g_bc0[16];
__device__ __align__(16) float g_bc1[32];
__device__ __align__(16) float g_bc2[64];

// ---------------- helpers ----------------
__device__ __forceinline__ void red_add_v4(float* a, float4 v) {
    asm volatile("red.global.add.v4.f32 [%0], {%1,%2,%3,%4};"
                 :: "l"(a), "f"(v.x), "f"(v.y), "f"(v.z), "f"(v.w) : "memory");
}
__device__ __forceinline__ void red_add_v2(float* a, float2 v) {
    asm volatile("red.global.add.v2.f32 [%0], {%1,%2};"
                 :: "l"(a), "f"(v.x), "f"(v.y) : "memory");
}
__device__ __forceinline__ void red_add_f(float* a, float v) {
    asm volatile("red.global.add.f32 [%0], %1;" :: "l"(a), "f"(v) : "memory");
}

struct ESet { const int* e[7]; float* cnt[7]; };
struct GSrc { const float* p[8]; const float* cnt[8]; };

// ---------------- zero scratch ----------------
__global__ void k_zero() {
    int tid = blockIdx.x * blockDim.x + threadIdx.x;
    int stride = gridDim.x * blockDim.x;
    float4 z = make_float4(0.f, 0.f, 0.f, 0.f);
    float4* a2 = reinterpret_cast<float4*>(g_msg2);
    for (int i = tid; i < 7 * NN * 32 / 4; i += stride) a2[i] = z;
    float4* a1 = reinterpret_cast<float4*>(g_msg1);
    for (int i = tid; i < 2 * NN * 16 / 4; i += stride) a1[i] = z;
    float4* a0 = reinterpret_cast<float4*>(g_msg0);
    for (int i = tid; i < 2 * NN * 6 / 4; i += stride) a0[i] = z;
    float4* ac = reinterpret_cast<float4*>(g_cnt);
    for (int i = tid; i < 3 * NN / 4; i += stride) ac[i] = z;
}

// ---------------- combine weights (self terms + residual projections folded) ----------------
__global__ void k_prep(const float* __restrict__ W0n, const float* __restrict__ W0r,
                       const float* __restrict__ b0,
                       const float* __restrict__ W1n, const float* __restrict__ W1r,
                       const float* __restrict__ b1,  const float* __restrict__ P1,
                       const float* __restrict__ pb1,
                       const float* __restrict__ W2n, const float* __restrict__ W2r,
                       const float* __restrict__ b2,  const float* __restrict__ P2,
                       const float* __restrict__ pb2) {
    int i = blockIdx.x * blockDim.x + threadIdx.x;
    if (i < 192) g_Wc0[i] = W0n[i];
    if (i < 96)  g_Wc0[192 + i] = W0r[i] + W0r[96 + i];
    if (i < 16)  g_bc0[i] = b0[i] + b0[16 + i];
    if (i < 1024) g_Wc1[i] = W1n[i];
    if (i < 512)  g_Wc1[1024 + i] = W1r[i] + W1r[512 + i] + P1[i];
    if (i < 32)   g_bc1[i] = b1[i] + b1[32 + i] + pb1[i];
    if (i < 14336) g_Wc2[i] = W2n[i];
    if (i < 2048) {
        float s = P2[i];
        for (int r = 0; r < 7; r++) s += W2r[r * 2048 + i];
        g_Wc2[14336 + i] = s;
    }
    if (i < 64) {
        float s = pb2[i];
        for (int r = 0; r < 7; r++) s += b2[r * 64 + i];
        g_bc2[i] = s;
    }
}

// ---------------- warp-cooperative scatters (R4-proven) ----------------
__global__ void __launch_bounds__(256)
k_scatter32(ESet es, const float* __restrict__ feat, float* __restrict__ msg) {
    int lane = threadIdx.x & 31;
    int warp = (blockIdx.x * 256 + threadIdx.x) >> 5;
    int e = warp * 32 + lane;
    int r = blockIdx.y;
    const int* ei = es.e[r];
    int src = __ldg(ei + e);
    int dst = __ldg(ei + NE + e);
    float* cp = es.cnt[r];
    if (cp) red_add_f(cp + dst, 1.0f);
    int sub = lane >> 3;
    int c   = lane & 7;
#pragma unroll
    for (int j = 0; j < 8; j++) {
        int el = j * 4 + sub;
        int s = __shfl_sync(0xffffffffu, src, el);
        int d = __shfl_sync(0xffffffffu, dst, el);
        float4 v = __ldg(reinterpret_cast<const float4*>(feat + (size_t)s * 32) + c);
        red_add_v4(msg + ((size_t)r * NN + d) * 32 + 4 * c, v);
    }
}

__global__ void __launch_bounds__(256)
k_scatter16(ESet es, const float* __restrict__ feat, float* __restrict__ msg) {
    int lane = threadIdx.x & 31;
    int warp = (blockIdx.x * 256 + threadIdx.x) >> 5;
    int e = warp * 32 + lane;
    int r = blockIdx.y;
    const int* ei = es.e[r];
    int src = __ldg(ei + e);
    int dst = __ldg(ei + NE + e);
    int sub = lane >> 2;
    int c   = lane & 3;
#pragma unroll
    for (int j = 0; j < 4; j++) {
        int el = j * 8 + sub;
        int s = __shfl_sync(0xffffffffu, src, el);
        int d = __shfl_sync(0xffffffffu, dst, el);
        float4 v = __ldg(reinterpret_cast<const float4*>(feat + (size_t)s * 16) + c);
        red_add_v4(msg + ((size_t)r * NN + d) * 16 + 4 * c, v);
    }
}

__global__ void __launch_bounds__(256)
k_scatter6(ESet es, const float* __restrict__ x, float* __restrict__ msg) {
    int lane = threadIdx.x & 31;
    int warp = (blockIdx.x * 256 + threadIdx.x) >> 5;
    int e = warp * 32 + lane;
    int r = blockIdx.y;
    const int* ei = es.e[r];
    int src = __ldg(ei + e);
    int dst = __ldg(ei + NE + e);
    int sub = lane >> 1;
    int c   = lane & 1;
#pragma unroll
    for (int j = 0; j < 2; j++) {
        int el = j * 16 + sub;
        int s = __shfl_sync(0xffffffffu, src, el);
        int d = __shfl_sync(0xffffffffu, dst, el);
        const float* xs = x + (size_t)s * 6;
        float2 a = __ldg(reinterpret_cast<const float2*>(xs) + c);
        float  v = __ldg(xs + 4 + c);
        float* m = msg + ((size_t)r * NN + d) * 6;
        red_add_v2(m + 2 * c, a);
        red_add_f(m + 4 + c, v);
    }
}

// ---------------- pipelined node-parallel GEMM (CHUNK % 4 == 0) ----------------
// Register-prefetch pipeline: channel ch+1's tile+weights load (coalesced
// LDG.128) while channel ch computes. shT stride CHUNK+1 => conflict-free LDS.
template <int CHUNK, int NCH, int OUT, bool RELU>
__global__ void __launch_bounds__(256)
k_gemm(GSrc s, const float* __restrict__ Wcat, const float* __restrict__ bias,
       float* __restrict__ out) {
    constexpr int LDT = CHUNK + 1;
    constexpr int NF4 = CHUNK / 4;                       // float4 per node row
    constexpr int WTOT4 = CHUNK * OUT / 4;               // float4 per weight chunk
    constexpr int WPT = (WTOT4 + 255) / 256;             // weight float4 per thread
    __shared__ __align__(16) float shW[CHUNK * OUT];
    __shared__ float shT[256 * LDT];
    int tid  = threadIdx.x;
    int base = blockIdx.x * 256;
    int node = base + tid;

    float acc[OUT];
#pragma unroll
    for (int j = 0; j < OUT; j++) acc[j] = __ldg(bias + j);

    // prefetch channel 0
    float4 pre[NF4];
    float4 preW[WPT];
    {
        const float4* src4 = reinterpret_cast<const float4*>(s.p[0]);
#pragma unroll
        for (int j = 0; j < NF4; j++) {
            int f = j * 256 + tid;                       // flat float4 idx in tile
            int g = base * NF4 + f;
            pre[j] = __ldg(src4 + (g < NN * NF4 ? g : NN * NF4 - 1));
        }
        const float4* w4 = reinterpret_cast<const float4*>(Wcat);
#pragma unroll
        for (int j = 0; j < WPT; j++) {
            int f = j * 256 + tid;
            preW[j] = (f < WTOT4) ? __ldg(w4 + f) : make_float4(0.f, 0.f, 0.f, 0.f);
        }
    }

    for (int ch = 0; ch < NCH; ch++) {
        __syncthreads();   // WAR: previous channel's compute done with shT/shW
#pragma unroll
        for (int j = 0; j < NF4; j++) {
            int f = j * 256 + tid;
            int nl = f / NF4, c = f % NF4;
            float4 v = pre[j];
            float* t = shT + nl * LDT + 4 * c;
            t[0] = v.x; t[1] = v.y; t[2] = v.z; t[3] = v.w;
        }
#pragma unroll
        for (int j = 0; j < WPT; j++) {
            int f = j * 256 + tid;
            if (f < WTOT4) reinterpret_cast<float4*>(shW)[f] = preW[j];
        }
        __syncthreads();   // RAW: tiles visible

        // prefetch next channel while computing this one
        if (ch + 1 < NCH) {
            const float4* src4 = reinterpret_cast<const float4*>(s.p[ch + 1]);
#pragma unroll
            for (int j = 0; j < NF4; j++) {
                int f = j * 256 + tid;
                int g = base * NF4 + f;
                pre[j] = __ldg(src4 + (g < NN * NF4 ? g : NN * NF4 - 1));
            }
            const float4* w4 = reinterpret_cast<const float4*>(Wcat + (size_t)(ch + 1) * CHUNK * OUT);
#pragma unroll
            for (int j = 0; j < WPT; j++) {
                int f = j * 256 + tid;
                preW[j] = (f < WTOT4) ? __ldg(w4 + f) : make_float4(0.f, 0.f, 0.f, 0.f);
            }
        }

        float sc = 1.f;
        const float* cp = s.cnt[ch];
        if (cp != nullptr && node < NN) sc = 1.f / fmaxf(__ldg(cp + node), 1.f);
#pragma unroll 8
        for (int k = 0; k < CHUNK; k++) {
            float m = shT[tid * LDT + k] * sc;
            const float4* w4 = reinterpret_cast<const float4*>(shW + k * OUT);
#pragma unroll
            for (int j = 0; j < OUT / 4; j++) {
                float4 w = w4[j];
                acc[4 * j + 0] += m * w.x;
                acc[4 * j + 1] += m * w.y;
                acc[4 * j + 2] += m * w.z;
                acc[4 * j + 3] += m * w.w;
            }
        }
    }

    if (node < NN) {
        float4* o4 = reinterpret_cast<float4*>(out + (size_t)node * OUT);
#pragma unroll
        for (int j = 0; j < OUT / 4; j++) {
            float4 v;
            v.x = acc[4 * j + 0]; v.y = acc[4 * j + 1];
            v.z = acc[4 * j + 2]; v.w = acc[4 * j + 3];
            if (RELU) {
                v.x = fmaxf(v.x, 0.f); v.y = fmaxf(v.y, 0.f);
                v.z = fmaxf(v.z, 0.f); v.w = fmaxf(v.w, 0.f);
            }
            o4[j] = v;
        }
    }
}

// ---------------- simple GEMM for CHUNK=6 (layer 0; small, proven) ----------------
template <int CHUNK, int NCH, int OUT, bool RELU>
__global__ void __launch_bounds__(256)
k_gemm_s(GSrc s, const float* __restrict__ Wcat, const float* __restrict__ bias,
         float* __restrict__ out) {
    __shared__ __align__(16) float shW[CHUNK * OUT];
    __shared__ float shT[256 * (CHUNK + 1)];
    int tid  = threadIdx.x;
    int base = blockIdx.x * 256;
    int node = base + tid;

    float acc[OUT];
#pragma unroll
    for (int j = 0; j < OUT; j++) acc[j] = bias[j];

    for (int ch = 0; ch < NCH; ch++) {
        __syncthreads();
        for (int i = tid; i < CHUNK * OUT; i += 256)
            shW[i] = Wcat[ch * CHUNK * OUT + i];
        const float* src = s.p[ch];
        for (int i = tid; i < 256 * CHUNK; i += 256) {
            int nl = i / CHUNK, k = i - nl * CHUNK;
            int nd = base + nl;
            shT[nl * (CHUNK + 1) + k] = (nd < NN) ? src[(size_t)nd * CHUNK + k] : 0.f;
        }
        __syncthreads();
#pragma unroll
        for (int k = 0; k < CHUNK; k++) {
            float m = shT[tid * (CHUNK + 1) + k];
            const float4* w4 = reinterpret_cast<const float4*>(shW + k * OUT);
#pragma unroll
            for (int j = 0; j < OUT / 4; j++) {
                float4 w = w4[j];
                acc[4 * j + 0] += m * w.x;
                acc[4 * j + 1] += m * w.y;
                acc[4 * j + 2] += m * w.z;
                acc[4 * j + 3] += m * w.w;
            }
        }
    }

    if (node < NN) {
        float4* o4 = reinterpret_cast<float4*>(out + (size_t)node * OUT);
#pragma unroll
        for (int j = 0; j < OUT / 4; j++) {
            float4 v;
            v.x = acc[4 * j + 0]; v.y = acc[4 * j + 1];
            v.z = acc[4 * j + 2]; v.w = acc[4 * j + 3];
            if (RELU) {
                v.x = fmaxf(v.x, 0.f); v.y = fmaxf(v.y, 0.f);
                v.z = fmaxf(v.z, 0.f); v.w = fmaxf(v.w, 0.f);
            }
            o4[j] = v;
        }
    }
}

// ---------------- host ----------------
extern "C" void kernel_launch(void* const* d_in, const int* in_sizes, int n_in,
                              void* d_out, int out_size) {
    (void)n_in; (void)out_size;
    const float* x = (const float*)d_in[0];

    int eb, wb;
    if (in_sizes[1] == 2 * NE) { eb = 1; wb = 10; }
    else                        { wb = 1; eb = 14; }

    const int* E[9];
    for (int i = 0; i < 9; i++) E[i] = (const int*)d_in[eb + i];
    const float* W0n = (const float*)d_in[wb + 0];
    const float* W0r = (const float*)d_in[wb + 1];
    const float* b0  = (const float*)d_in[wb + 2];
    const float* W1n = (const float*)d_in[wb + 3];
    const float* W1r = (const float*)d_in[wb + 4];
    const float* b1  = (const float*)d_in[wb + 5];
    const float* P1  = (const float*)d_in[wb + 6];
    const float* pb1 = (const float*)d_in[wb + 7];
    const float* W2n = (const float*)d_in[wb + 8];
    const float* W2r = (const float*)d_in[wb + 9];
    const float* b2  = (const float*)d_in[wb + 10];
    const float* P2  = (const float*)d_in[wb + 11];
    const float* pb2 = (const float*)d_in[wb + 12];

    float *msg2, *msg1, *msg0, *cnt, *h0, *h1, *Wc0, *Wc1, *Wc2, *bc0, *bc1, *bc2;
    cudaGetSymbolAddress((void**)&msg2, g_msg2);
    cudaGetSymbolAddress((void**)&msg1, g_msg1);
    cudaGetSymbolAddress((void**)&msg0, g_msg0);
    cudaGetSymbolAddress((void**)&cnt,  g_cnt);
    cudaGetSymbolAddress((void**)&h0,   g_h0);
    cudaGetSymbolAddress((void**)&h1,   g_h1);
    cudaGetSymbolAddress((void**)&Wc0,  g_Wc0);
    cudaGetSymbolAddress((void**)&Wc1,  g_Wc1);
    cudaGetSymbolAddress((void**)&Wc2,  g_Wc2);
    cudaGetSymbolAddress((void**)&bc0,  g_bc0);
    cudaGetSymbolAddress((void**)&bc1,  g_bc1);
    cudaGetSymbolAddress((void**)&bc2,  g_bc2);

    k_zero<<<2048, 256>>>();
    k_prep<<<56, 256>>>(W0n, W0r, b0, W1n, W1r, b1, P1, pb1, W2n, W2r, b2, P2, pb2);

    // ---- layer 0: x(6) -> h0(16), relations {connected_to, ordered_next}, sum ----
    ESet es01 = {};
    es01.e[0] = E[0]; es01.e[1] = E[1];
    k_scatter6<<<dim3(NE / 256, 2), 256>>>(es01, x, msg0);

    GSrc s0 = {};
    s0.p[0] = msg0; s0.p[1] = msg0 + (size_t)NN * 6; s0.p[2] = x;
    k_gemm_s<6, 3, 16, false><<<(NN + 255) / 256, 256>>>(s0, Wc0, bc0, h0);

    // ---- layer 1: h0(16) -> h1(32), same relations, + P1 residual, relu ----
    k_scatter16<<<dim3(NE / 256, 2), 256>>>(es01, h0, msg1);

    GSrc s1 = {};
    s1.p[0] = msg1; s1.p[1] = msg1 + (size_t)NN * 16; s1.p[2] = h0;
    k_gemm<16, 3, 32, true><<<(NN + 255) / 256, 256>>>(s1, Wc1, bc1, h1);

    // ---- layer 2: h1(32) -> out(64), 7 relations (mean at 2,3,6), + P2, relu ----
    ESet es2 = {};
    for (int r = 0; r < 7; r++) es2.e[r] = E[2 + r];
    es2.cnt[2] = cnt; es2.cnt[3] = cnt + NN; es2.cnt[6] = cnt + 2 * NN;
    k_scatter32<<<dim3(NE / 256, 7), 256>>>(es2, h1, msg2);

    GSrc s2 = {};
    for (int r = 0; r < 7; r++) s2.p[r] = msg2 + (size_t)r * NN * 32;
    s2.p[7] = h1;
    s2.cnt[2] = cnt; s2.cnt[3] = cnt + NN; s2.cnt[6] = cnt + 2 * NN;
    k_gemm<32, 8, 64, true><<<(NN + 255) / 256, 256>>>(s2, Wc2, bc2, (float*)d_out);
}

// round 7
// speedup vs baseline: 3.4031x; 1.1886x over previous
#include <cuda_runtime.h>

#define NN 100000
#define NE 800000

// ---------------- scratch (static __device__ globals; no allocs) ----------------
__device__ __align__(16) float g_msg2[7 * NN * 32];   // 89.6 MB
__device__ __align__(16) float g_msg1[2 * NN * 16];
__device__ __align__(16) float g_msg0[2 * NN * 6];
__device__ __align__(16) float g_cnt [3 * NN];
__device__ __align__(16) float g_h0  [NN * 16];
__device__ __align__(16) float g_h1  [NN * 32];
__device__ __align__(16) float g_Wc0[3 * 6 * 16];
__device__ __align__(16) float g_Wc1[3 * 16 * 32];
__device__ __align__(16) float g_W2hi[8 * 64 * 32];   // [ch][n][k], tf32-exact
__device__ __align__(16) float g_W2lo[8 * 64 * 32];
__device__ __align__(16) float g_bc0[16];
__device__ __align__(16) float g_bc1[32];
__device__ __align__(16) float g_bc2[64];

// ---------------- helpers ----------------
__device__ __forceinline__ void red_add_v4(float* a, float4 v) {
    asm volatile("red.global.add.v4.f32 [%0], {%1,%2,%3,%4};"
                 :: "l"(a), "f"(v.x), "f"(v.y), "f"(v.z), "f"(v.w) : "memory");
}
__device__ __forceinline__ void red_add_v2(float* a, float2 v) {
    asm volatile("red.global.add.v2.f32 [%0], {%1,%2};"
                 :: "l"(a), "f"(v.x), "f"(v.y) : "memory");
}
__device__ __forceinline__ void red_add_f(float* a, float v) {
    asm volatile("red.global.add.f32 [%0], %1;" :: "l"(a), "f"(v) : "memory");
}
__device__ __forceinline__ unsigned tf32_of(float f) {
    unsigned r;
    asm("cvt.rna.tf32.f32 %0, %1;" : "=r"(r) : "f"(f));
    return r;
}
__device__ __forceinline__ void mma_tf32(float* d, unsigned a0, unsigned a1,
                                         unsigned a2, unsigned a3,
                                         unsigned b0, unsigned b1) {
    asm("mma.sync.aligned.m16n8k8.row.col.f32.tf32.tf32.f32 "
        "{%0,%1,%2,%3}, {%4,%5,%6,%7}, {%8,%9}, {%0,%1,%2,%3};"
        : "+f"(d[0]), "+f"(d[1]), "+f"(d[2]), "+f"(d[3])
        : "r"(a0), "r"(a1), "r"(a2), "r"(a3), "r"(b0), "r"(b1));
}

struct ESet { const int* e[7]; float* cnt[7]; };
struct GSrc { const float* p[8]; const float* cnt[8]; };

// ---------------- zero scratch ----------------
__global__ void k_zero() {
    int tid = blockIdx.x * blockDim.x + threadIdx.x;
    int stride = gridDim.x * blockDim.x;
    float4 z = make_float4(0.f, 0.f, 0.f, 0.f);
    float4* a2 = reinterpret_cast<float4*>(g_msg2);
    for (int i = tid; i < 7 * NN * 32 / 4; i += stride) a2[i] = z;
    float4* a1 = reinterpret_cast<float4*>(g_msg1);
    for (int i = tid; i < 2 * NN * 16 / 4; i += stride) a1[i] = z;
    float4* a0 = reinterpret_cast<float4*>(g_msg0);
    for (int i = tid; i < 2 * NN * 6 / 4; i += stride) a0[i] = z;
    float4* ac = reinterpret_cast<float4*>(g_cnt);
    for (int i = tid; i < 3 * NN / 4; i += stride) ac[i] = z;
}

// ---------------- combine weights (self terms + residual projections folded) ----------------
__global__ void k_prep(const float* __restrict__ W0n, const float* __restrict__ W0r,
                       const float* __restrict__ b0,
                       const float* __restrict__ W1n, const float* __restrict__ W1r,
                       const float* __restrict__ b1,  const float* __restrict__ P1,
                       const float* __restrict__ pb1,
                       const float* __restrict__ W2n, const float* __restrict__ W2r,
                       const float* __restrict__ b2,  const float* __restrict__ P2,
                       const float* __restrict__ pb2) {
    int i = blockIdx.x * blockDim.x + threadIdx.x;
    if (i < 192) g_Wc0[i] = W0n[i];
    if (i < 96)  g_Wc0[192 + i] = W0r[i] + W0r[96 + i];
    if (i < 16)  g_bc0[i] = b0[i] + b0[16 + i];
    if (i < 1024) g_Wc1[i] = W1n[i];
    if (i < 512)  g_Wc1[1024 + i] = W1r[i] + W1r[512 + i] + P1[i];
    if (i < 32)   g_bc1[i] = b1[i] + b1[32 + i] + pb1[i];
    // layer 2: 8 chunks [W2n[0..6], sum(W2r)+P2], split to tf32 hi/lo, [ch][n][k]
    if (i < 16384) {
        int ch = i >> 11, j = i & 2047;
        int k = j >> 6, n = j & 63;
        float w;
        if (ch < 7) w = W2n[i];
        else {
            w = P2[j];
            for (int r = 0; r < 7; r++) w += W2r[r * 2048 + j];
        }
        unsigned hi = tf32_of(w);
        unsigned lo = tf32_of(w - __uint_as_float(hi));
        int o = ch * 2048 + n * 32 + k;
        g_W2hi[o] = __uint_as_float(hi);
        g_W2lo[o] = __uint_as_float(lo);
    }
    if (i < 64) {
        float s = pb2[i];
        for (int r = 0; r < 7; r++) s += b2[r * 64 + i];
        g_bc2[i] = s;
    }
}

// ---------------- warp-cooperative scatters (R4-proven) ----------------
__global__ void __launch_bounds__(256)
k_scatter32(ESet es, const float* __restrict__ feat, float* __restrict__ msg) {
    int lane = threadIdx.x & 31;
    int warp = (blockIdx.x * 256 + threadIdx.x) >> 5;
    int e = warp * 32 + lane;
    int r = blockIdx.y;
    const int* ei = es.e[r];
    int src = __ldg(ei + e);
    int dst = __ldg(ei + NE + e);
    float* cp = es.cnt[r];
    if (cp) red_add_f(cp + dst, 1.0f);
    int sub = lane >> 3;
    int c   = lane & 7;
#pragma unroll
    for (int j = 0; j < 8; j++) {
        int el = j * 4 + sub;
        int s = __shfl_sync(0xffffffffu, src, el);
        int d = __shfl_sync(0xffffffffu, dst, el);
        float4 v = __ldg(reinterpret_cast<const float4*>(feat + (size_t)s * 32) + c);
        red_add_v4(msg + ((size_t)r * NN + d) * 32 + 4 * c, v);
    }
}

__global__ void __launch_bounds__(256)
k_scatter16(ESet es, const float* __restrict__ feat, float* __restrict__ msg) {
    int lane = threadIdx.x & 31;
    int warp = (blockIdx.x * 256 + threadIdx.x) >> 5;
    int e = warp * 32 + lane;
    int r = blockIdx.y;
    const int* ei = es.e[r];
    int src = __ldg(ei + e);
    int dst = __ldg(ei + NE + e);
    int sub = lane >> 2;
    int c   = lane & 3;
#pragma unroll
    for (int j = 0; j < 4; j++) {
        int el = j * 8 + sub;
        int s = __shfl_sync(0xffffffffu, src, el);
        int d = __shfl_sync(0xffffffffu, dst, el);
        float4 v = __ldg(reinterpret_cast<const float4*>(feat + (size_t)s * 16) + c);
        red_add_v4(msg + ((size_t)r * NN + d) * 16 + 4 * c, v);
    }
}

__global__ void __launch_bounds__(256)
k_scatter6(ESet es, const float* __restrict__ x, float* __restrict__ msg) {
    int lane = threadIdx.x & 31;
    int warp = (blockIdx.x * 256 + threadIdx.x) >> 5;
    int e = warp * 32 + lane;
    int r = blockIdx.y;
    const int* ei = es.e[r];
    int src = __ldg(ei + e);
    int dst = __ldg(ei + NE + e);
    int sub = lane >> 1;
    int c   = lane & 1;
#pragma unroll
    for (int j = 0; j < 2; j++) {
        int el = j * 16 + sub;
        int s = __shfl_sync(0xffffffffu, src, el);
        int d = __shfl_sync(0xffffffffu, dst, el);
        const float* xs = x + (size_t)s * 6;
        float2 a = __ldg(reinterpret_cast<const float2*>(xs) + c);
        float  v = __ldg(xs + 4 + c);
        float* m = msg + ((size_t)r * NN + d) * 6;
        red_add_v2(m + 2 * c, a);
        red_add_f(m + 4 + c, v);
    }
}

// ---------------- pipelined node-parallel GEMM (scalar FFMA; layer 1) ----------------
template <int CHUNK, int NCH, int OUT, bool RELU>
__global__ void __launch_bounds__(256)
k_gemm(GSrc s, const float* __restrict__ Wcat, const float* __restrict__ bias,
       float* __restrict__ out) {
    constexpr int LDT = CHUNK + 1;
    constexpr int NF4 = CHUNK / 4;
    constexpr int WTOT4 = CHUNK * OUT / 4;
    constexpr int WPT = (WTOT4 + 255) / 256;
    __shared__ __align__(16) float shW[CHUNK * OUT];
    __shared__ float shT[256 * LDT];
    int tid  = threadIdx.x;
    int base = blockIdx.x * 256;
    int node = base + tid;

    float acc[OUT];
#pragma unroll
    for (int j = 0; j < OUT; j++) acc[j] = __ldg(bias + j);

    float4 pre[NF4];
    float4 preW[WPT];
    {
        const float4* src4 = reinterpret_cast<const float4*>(s.p[0]);
#pragma unroll
        for (int j = 0; j < NF4; j++) {
            int f = j * 256 + tid;
            int g = base * NF4 + f;
            pre[j] = __ldg(src4 + (g < NN * NF4 ? g : NN * NF4 - 1));
        }
        const float4* w4 = reinterpret_cast<const float4*>(Wcat);
#pragma unroll
        for (int j = 0; j < WPT; j++) {
            int f = j * 256 + tid;
            preW[j] = (f < WTOT4) ? __ldg(w4 + f) : make_float4(0.f, 0.f, 0.f, 0.f);
        }
    }

    for (int ch = 0; ch < NCH; ch++) {
        __syncthreads();
#pragma unroll
        for (int j = 0; j < NF4; j++) {
            int f = j * 256 + tid;
            int nl = f / NF4, c = f % NF4;
            float4 v = pre[j];
            float* t = shT + nl * LDT + 4 * c;
            t[0] = v.x; t[1] = v.y; t[2] = v.z; t[3] = v.w;
        }
#pragma unroll
        for (int j = 0; j < WPT; j++) {
            int f = j * 256 + tid;
            if (f < WTOT4) reinterpret_cast<float4*>(shW)[f] = preW[j];
        }
        __syncthreads();

        if (ch + 1 < NCH) {
            const float4* src4 = reinterpret_cast<const float4*>(s.p[ch + 1]);
#pragma unroll
            for (int j = 0; j < NF4; j++) {
                int f = j * 256 + tid;
                int g = base * NF4 + f;
                pre[j] = __ldg(src4 + (g < NN * NF4 ? g : NN * NF4 - 1));
            }
            const float4* w4 = reinterpret_cast<const float4*>(Wcat + (size_t)(ch + 1) * CHUNK * OUT);
#pragma unroll
            for (int j = 0; j < WPT; j++) {
                int f = j * 256 + tid;
                preW[j] = (f < WTOT4) ? __ldg(w4 + f) : make_float4(0.f, 0.f, 0.f, 0.f);
            }
        }

        float sc = 1.f;
        const float* cp = s.cnt[ch];
        if (cp != nullptr && node < NN) sc = 1.f / fmaxf(__ldg(cp + node), 1.f);
#pragma unroll 8
        for (int k = 0; k < CHUNK; k++) {
            float m = shT[tid * LDT + k] * sc;
            const float4* w4 = reinterpret_cast<const float4*>(shW + k * OUT);
#pragma unroll
            for (int j = 0; j < OUT / 4; j++) {
                float4 w = w4[j];
                acc[4 * j + 0] += m * w.x;
                acc[4 * j + 1] += m * w.y;
                acc[4 * j + 2] += m * w.z;
                acc[4 * j + 3] += m * w.w;
            }
        }
    }

    if (node < NN) {
        float4* o4 = reinterpret_cast<float4*>(out + (size_t)node * OUT);
#pragma unroll
        for (int j = 0; j < OUT / 4; j++) {
            float4 v;
            v.x = acc[4 * j + 0]; v.y = acc[4 * j + 1];
            v.z = acc[4 * j + 2]; v.w = acc[4 * j + 3];
            if (RELU) {
                v.x = fmaxf(v.x, 0.f); v.y = fmaxf(v.y, 0.f);
                v.z = fmaxf(v.z, 0.f); v.w = fmaxf(v.w, 0.f);
            }
            o4[j] = v;
        }
    }
}

// ---------------- simple GEMM for CHUNK=6 (layer 0; small, proven) ----------------
template <int CHUNK, int NCH, int OUT, bool RELU>
__global__ void __launch_bounds__(256)
k_gemm_s(GSrc s, const float* __restrict__ Wcat, const float* __restrict__ bias,
         float* __restrict__ out) {
    __shared__ __align__(16) float shW[CHUNK * OUT];
    __shared__ float shT[256 * (CHUNK + 1)];
    int tid  = threadIdx.x;
    int base = blockIdx.x * 256;
    int node = base + tid;

    float acc[OUT];
#pragma unroll
    for (int j = 0; j < OUT; j++) acc[j] = bias[j];

    for (int ch = 0; ch < NCH; ch++) {
        __syncthreads();
        for (int i = tid; i < CHUNK * OUT; i += 256)
            shW[i] = Wcat[ch * CHUNK * OUT + i];
        const float* src = s.p[ch];
        for (int i = tid; i < 256 * CHUNK; i += 256) {
            int nl = i / CHUNK, k = i - nl * CHUNK;
            int nd = base + nl;
            shT[nl * (CHUNK + 1) + k] = (nd < NN) ? src[(size_t)nd * CHUNK + k] : 0.f;
        }
        __syncthreads();
#pragma unroll
        for (int k = 0; k < CHUNK; k++) {
            float m = shT[tid * (CHUNK + 1) + k];
            const float4* w4 = reinterpret_cast<const float4*>(shW + k * OUT);
#pragma unroll
            for (int j = 0; j < OUT / 4; j++) {
                float4 w = w4[j];
                acc[4 * j + 0] += m * w.x;
                acc[4 * j + 1] += m * w.y;
                acc[4 * j + 2] += m * w.z;
                acc[4 * j + 3] += m * w.w;
            }
        }
    }

    if (node < NN) {
        float4* o4 = reinterpret_cast<float4*>(out + (size_t)node * OUT);
#pragma unroll
        for (int j = 0; j < OUT / 4; j++) {
            float4 v;
            v.x = acc[4 * j + 0]; v.y = acc[4 * j + 1];
            v.z = acc[4 * j + 2]; v.w = acc[4 * j + 3];
            if (RELU) {
                v.x = fmaxf(v.x, 0.f); v.y = fmaxf(v.y, 0.f);
                v.z = fmaxf(v.z, 0.f); v.w = fmaxf(v.w, 0.f);
            }
            o4[j] = v;
        }
    }
}

// ---------------- layer-2 GEMM: split-tf32 mma.sync (m16n8k8), M-tile 128 ----------------
// out[100000,64] = relu( sum_ch scale_ch(node) * X_ch[node,32] @ W_ch[32,64] + bias )
// 8 warps: warp w covers rows 16w..16w+15 of the 128-row tile, all 64 cols.
// W pre-split (tf32 hi/lo) and transposed [ch][n][k]; A split at frag-load.
__global__ void __launch_bounds__(256)
k_gemm2_tc(GSrc s, const float* __restrict__ Whi, const float* __restrict__ Wlo,
           const float* __restrict__ bias, float* __restrict__ out) {
    __shared__ float shA [128 * 36];
    __shared__ float shWh[64 * 36];
    __shared__ float shWl[64 * 36];
    __shared__ float shSc[3][128];
    __shared__ float shB[64];
    int tid  = threadIdx.x;
    int lane = tid & 31;
    int w    = tid >> 5;
    int base = blockIdx.x * 128;

    if (tid < 64) shB[tid] = __ldg(bias + tid);
    if (tid < 128) {
        int node = base + tid;
        const int mc[3] = {2, 3, 6};
#pragma unroll
        for (int m = 0; m < 3; m++) {
            float c = (node < NN) ? __ldg(s.cnt[mc[m]] + node) : 1.f;
            shSc[m][tid] = 1.f / fmaxf(c, 1.f);
        }
    }

    float d[8][4];
#pragma unroll
    for (int nt = 0; nt < 8; nt++)
#pragma unroll
        for (int j = 0; j < 4; j++) d[nt][j] = 0.f;

    // prefetch channel 0 (A: 1024 f4, W hi+lo: 512+512 f4)
    float4 pre[4];
    float4 preW[4];
    {
        const float4* src4 = reinterpret_cast<const float4*>(s.p[0]);
#pragma unroll
        for (int j = 0; j < 4; j++) {
            int f = j * 256 + tid;
            int g = base * 8 + f;
            pre[j] = __ldg(src4 + (g < NN * 8 ? g : NN * 8 - 1));
        }
        const float4* wh4 = reinterpret_cast<const float4*>(Whi);
        const float4* wl4 = reinterpret_cast<const float4*>(Wlo);
#pragma unroll
        for (int j = 0; j < 2; j++) preW[j]     = __ldg(wh4 + j * 256 + tid);
#pragma unroll
        for (int j = 0; j < 2; j++) preW[2 + j] = __ldg(wl4 + j * 256 + tid);
    }

    int rl1 = 16 * w + (lane >> 2);   // local row for a0/a2
    int rl2 = rl1 + 8;                // local row for a1/a3
    int kc  = lane & 3;               // k within k-step
    int nb  = lane >> 2;              // n within n-tile

    for (int ch = 0; ch < 8; ch++) {
        __syncthreads();   // WAR
        // msel: mean-channel slot or -1
        int msel = (ch == 2) ? 0 : (ch == 3) ? 1 : (ch == 6) ? 2 : -1;
#pragma unroll
        for (int j = 0; j < 4; j++) {
            int f = j * 256 + tid;
            int nl = f >> 3, c4 = f & 7;
            float4 v = pre[j];
            if (msel >= 0) {
                float sc = shSc[msel][nl];
                v.x *= sc; v.y *= sc; v.z *= sc; v.w *= sc;
            }
            float* t = shA + nl * 36 + 4 * c4;
            t[0] = v.x; t[1] = v.y; t[2] = v.z; t[3] = v.w;
        }
#pragma unroll
        for (int j = 0; j < 2; j++) {
            int f = j * 256 + tid;           // f4 idx: n = f>>3, k4 = f&7
            int n = f >> 3, k4 = f & 7;
            float4 vh = preW[j], vl = preW[2 + j];
            float* th = shWh + n * 36 + 4 * k4;
            float* tl = shWl + n * 36 + 4 * k4;
            th[0] = vh.x; th[1] = vh.y; th[2] = vh.z; th[3] = vh.w;
            tl[0] = vl.x; tl[1] = vl.y; tl[2] = vl.z; tl[3] = vl.w;
        }
        __syncthreads();   // RAW

        if (ch + 1 < 8) {
            const float4* src4 = reinterpret_cast<const float4*>(s.p[ch + 1]);
#pragma unroll
            for (int j = 0; j < 4; j++) {
                int f = j * 256 + tid;
                int g = base * 8 + f;
                pre[j] = __ldg(src4 + (g < NN * 8 ? g : NN * 8 - 1));
            }
            const float4* wh4 = reinterpret_cast<const float4*>(Whi + (ch + 1) * 2048);
            const float4* wl4 = reinterpret_cast<const float4*>(Wlo + (ch + 1) * 2048);
#pragma unroll
            for (int j = 0; j < 2; j++) preW[j]     = __ldg(wh4 + j * 256 + tid);
#pragma unroll
            for (int j = 0; j < 2; j++) preW[2 + j] = __ldg(wl4 + j * 256 + tid);
        }

#pragma unroll
        for (int k0 = 0; k0 < 32; k0 += 8) {
            int c = k0 + kc;
            float a0f = shA[rl1 * 36 + c];
            float a1f = shA[rl2 * 36 + c];
            float a2f = shA[rl1 * 36 + c + 4];
            float a3f = shA[rl2 * 36 + c + 4];
            unsigned ah0 = tf32_of(a0f), ah1 = tf32_of(a1f);
            unsigned ah2 = tf32_of(a2f), ah3 = tf32_of(a3f);
            unsigned al0 = tf32_of(a0f - __uint_as_float(ah0));
            unsigned al1 = tf32_of(a1f - __uint_as_float(ah1));
            unsigned al2 = tf32_of(a2f - __uint_as_float(ah2));
            unsigned al3 = tf32_of(a3f - __uint_as_float(ah3));
#pragma unroll
            for (int nt = 0; nt < 8; nt++) {
                int wr = (nt * 8 + nb) * 36 + k0 + kc;
                unsigned bh0 = __float_as_uint(shWh[wr]);
                unsigned bh1 = __float_as_uint(shWh[wr + 4]);
                unsigned bl0 = __float_as_uint(shWl[wr]);
                unsigned bl1 = __float_as_uint(shWl[wr + 4]);
                mma_tf32(d[nt], ah0, ah1, ah2, ah3, bh0, bh1);
                mma_tf32(d[nt], ah0, ah1, ah2, ah3, bl0, bl1);
                mma_tf32(d[nt], al0, al1, al2, al3, bh0, bh1);
            }
        }
    }

    // epilogue: bias + relu, float2 stores
    int r1 = base + rl1;
    int r2 = base + rl2;
#pragma unroll
    for (int nt = 0; nt < 8; nt++) {
        int c0 = nt * 8 + 2 * kc;
        float b0 = shB[c0], b1 = shB[c0 + 1];
        if (r1 < NN) {
            float2 v;
            v.x = fmaxf(d[nt][0] + b0, 0.f);
            v.y = fmaxf(d[nt][1] + b1, 0.f);
            *reinterpret_cast<float2*>(out + (size_t)r1 * 64 + c0) = v;
        }
        if (r2 < NN) {
            float2 v;
            v.x = fmaxf(d[nt][2] + b0, 0.f);
            v.y = fmaxf(d[nt][3] + b1, 0.f);
            *reinterpret_cast<float2*>(out + (size_t)r2 * 64 + c0) = v;
        }
    }
}

// ---------------- host ----------------
extern "C" void kernel_launch(void* const* d_in, const int* in_sizes, int n_in,
                              void* d_out, int out_size) {
    (void)n_in; (void)out_size;
    const float* x = (const float*)d_in[0];

    int eb, wb;
    if (in_sizes[1] == 2 * NE) { eb = 1; wb = 10; }
    else                        { wb = 1; eb = 14; }

    const int* E[9];
    for (int i = 0; i < 9; i++) E[i] = (const int*)d_in[eb + i];
    const float* W0n = (const float*)d_in[wb + 0];
    const float* W0r = (const float*)d_in[wb + 1];
    const float* b0  = (const float*)d_in[wb + 2];
    const float* W1n = (const float*)d_in[wb + 3];
    const float* W1r = (const float*)d_in[wb + 4];
    const float* b1  = (const float*)d_in[wb + 5];
    const float* P1  = (const float*)d_in[wb + 6];
    const float* pb1 = (const float*)d_in[wb + 7];
    const float* W2n = (const float*)d_in[wb + 8];
    const float* W2r = (const float*)d_in[wb + 9];
    const float* b2  = (const float*)d_in[wb + 10];
    const float* P2  = (const float*)d_in[wb + 11];
    const float* pb2 = (const float*)d_in[wb + 12];

    float *msg2, *msg1, *msg0, *cnt, *h0, *h1, *Wc0, *Wc1, *W2hi, *W2lo, *bc0, *bc1, *bc2;
    cudaGetSymbolAddress((void**)&msg2, g_msg2);
    cudaGetSymbolAddress((void**)&msg1, g_msg1);
    cudaGetSymbolAddress((void**)&msg0, g_msg0);
    cudaGetSymbolAddress((void**)&cnt,  g_cnt);
    cudaGetSymbolAddress((void**)&h0,   g_h0);
    cudaGetSymbolAddress((void**)&h1,   g_h1);
    cudaGetSymbolAddress((void**)&Wc0,  g_Wc0);
    cudaGetSymbolAddress((void**)&Wc1,  g_Wc1);
    cudaGetSymbolAddress((void**)&W2hi, g_W2hi);
    cudaGetSymbolAddress((void**)&W2lo, g_W2lo);
    cudaGetSymbolAddress((void**)&bc0,  g_bc0);
    cudaGetSymbolAddress((void**)&bc1,  g_bc1);
    cudaGetSymbolAddress((void**)&bc2,  g_bc2);

    k_zero<<<2048, 256>>>();
    k_prep<<<64, 256>>>(W0n, W0r, b0, W1n, W1r, b1, P1, pb1, W2n, W2r, b2, P2, pb2);

    // ---- layer 0: x(6) -> h0(16), relations {connected_to, ordered_next}, sum ----
    ESet es01 = {};
    es01.e[0] = E[0]; es01.e[1] = E[1];
    k_scatter6<<<dim3(NE / 256, 2), 256>>>(es01, x, msg0);

    GSrc s0 = {};
    s0.p[0] = msg0; s0.p[1] = msg0 + (size_t)NN * 6; s0.p[2] = x;
    k_gemm_s<6, 3, 16, false><<<(NN + 255) / 256, 256>>>(s0, Wc0, bc0, h0);

    // ---- layer 1: h0(16) -> h1(32), same relations, + P1 residual, relu ----
    k_scatter16<<<dim3(NE / 256, 2), 256>>>(es01, h0, msg1);

    GSrc s1 = {};
    s1.p[0] = msg1; s1.p[1] = msg1 + (size_t)NN * 16; s1.p[2] = h0;
    k_gemm<16, 3, 32, true><<<(NN + 255) / 256, 256>>>(s1, Wc1, bc1, h1);

    // ---- layer 2: h1(32) -> out(64), 7 relations (mean at 2,3,6), + P2, relu ----
    ESet es2 = {};
    for (int r = 0; r < 7; r++) es2.e[r] = E[2 + r];
    es2.cnt[2] = cnt; es2.cnt[3] = cnt + NN; es2.cnt[6] = cnt + 2 * NN;
    k_scatter32<<<dim3(NE / 256, 7), 256>>>(es2, h1, msg2);

    GSrc s2 = {};
    for (int r = 0; r < 7; r++) s2.p[r] = msg2 + (size_t)r * NN * 32;
    s2.p[7] = h1;
    s2.cnt[2] = cnt; s2.cnt[3] = cnt + NN; s2.cnt[6] = cnt + 2 * NN;
    k_gemm2_tc<<<(NN + 127) / 128, 256>>>(s2, W2hi, W2lo, bc2, (float*)d_out);
}

// round 8
// speedup vs baseline: 3.7695x; 1.1077x over previous
#include <cuda_runtime.h>
#include <cuda_fp16.h>

#define NN 100000
#define NE 800000

// ---------------- scratch (static __device__ globals; no allocs) ----------------
__device__ __align__(16) __half g_msg2h[7 * NN * 32];  // 44.8 MB fp16 messages
__device__ __align__(16) float g_msg1[2 * NN * 16];
__device__ __align__(16) float g_msg0[2 * NN * 6];
__device__ __align__(16) float g_cnt [3 * NN];
__device__ __align__(16) float g_h0  [NN * 16];
__device__ __align__(16) float g_h1  [NN * 32];
__device__ __align__(16) __half g_h1h[NN * 32];        // fp16 copy for gather
__device__ __align__(16) float g_Wc0[3 * 6 * 16];
__device__ __align__(16) float g_Wc1[3 * 16 * 32];
__device__ __align__(16) float g_W2hi[8 * 64 * 32];    // [ch][n][k], tf32-exact
__device__ __align__(16) float g_W2lo[8 * 64 * 32];
__device__ __align__(16) float g_bc0[16];
__device__ __align__(16) float g_bc1[32];
__device__ __align__(16) float g_bc2[64];

// ---------------- helpers ----------------
__device__ __forceinline__ void red_add_v4(float* a, float4 v) {
    asm volatile("red.global.add.v4.f32 [%0], {%1,%2,%3,%4};"
                 :: "l"(a), "f"(v.x), "f"(v.y), "f"(v.z), "f"(v.w) : "memory");
}
__device__ __forceinline__ void red_add_v2(float* a, float2 v) {
    asm volatile("red.global.add.v2.f32 [%0], {%1,%2};"
                 :: "l"(a), "f"(v.x), "f"(v.y) : "memory");
}
__device__ __forceinline__ void red_add_f(float* a, float v) {
    asm volatile("red.global.add.f32 [%0], %1;" :: "l"(a), "f"(v) : "memory");
}
// 16B of packed halves (8 halves) reduced in one lane-op
__device__ __forceinline__ void red_add_v4h(__half* a, float4 bits) {
    asm volatile("red.global.add.noftz.v4.f16x2 [%0], {%1,%2,%3,%4};"
                 :: "l"(a), "r"(__float_as_uint(bits.x)), "r"(__float_as_uint(bits.y)),
                    "r"(__float_as_uint(bits.z)), "r"(__float_as_uint(bits.w)) : "memory");
}
__device__ __forceinline__ unsigned tf32_of(float f) {
    unsigned r;
    asm("cvt.rna.tf32.f32 %0, %1;" : "=r"(r) : "f"(f));
    return r;
}
__device__ __forceinline__ void mma_tf32(float* d, unsigned a0, unsigned a1,
                                         unsigned a2, unsigned a3,
                                         unsigned b0, unsigned b1) {
    asm("mma.sync.aligned.m16n8k8.row.col.f32.tf32.tf32.f32 "
        "{%0,%1,%2,%3}, {%4,%5,%6,%7}, {%8,%9}, {%0,%1,%2,%3};"
        : "+f"(d[0]), "+f"(d[1]), "+f"(d[2]), "+f"(d[3])
        : "r"(a0), "r"(a1), "r"(a2), "r"(a3), "r"(b0), "r"(b1));
}

struct ESet { const int* e[7]; float* cnt[7]; };
struct GSrc { const float* p[8]; const float* cnt[8]; };

// ---------------- zero scratch ----------------
__global__ void k_zero() {
    int tid = blockIdx.x * blockDim.x + threadIdx.x;
    int stride = gridDim.x * blockDim.x;
    float4 z = make_float4(0.f, 0.f, 0.f, 0.f);
    float4* a2 = reinterpret_cast<float4*>(g_msg2h);
    for (int i = tid; i < 7 * NN * 32 / 8; i += stride) a2[i] = z;  // halves: /8 per f4
    float4* a1 = reinterpret_cast<float4*>(g_msg1);
    for (int i = tid; i < 2 * NN * 16 / 4; i += stride) a1[i] = z;
    float4* a0 = reinterpret_cast<float4*>(g_msg0);
    for (int i = tid; i < 2 * NN * 6 / 4; i += stride) a0[i] = z;
    float4* ac = reinterpret_cast<float4*>(g_cnt);
    for (int i = tid; i < 3 * NN / 4; i += stride) ac[i] = z;
}

// ---------------- combine weights (self terms + residual projections folded) ----------------
__global__ void k_prep(const float* __restrict__ W0n, const float* __restrict__ W0r,
                       const float* __restrict__ b0,
                       const float* __restrict__ W1n, const float* __restrict__ W1r,
                       const float* __restrict__ b1,  const float* __restrict__ P1,
                       const float* __restrict__ pb1,
                       const float* __restrict__ W2n, const float* __restrict__ W2r,
                       const float* __restrict__ b2,  const float* __restrict__ P2,
                       const float* __restrict__ pb2) {
    int i = blockIdx.x * blockDim.x + threadIdx.x;
    if (i < 192) g_Wc0[i] = W0n[i];
    if (i < 96)  g_Wc0[192 + i] = W0r[i] + W0r[96 + i];
    if (i < 16)  g_bc0[i] = b0[i] + b0[16 + i];
    if (i < 1024) g_Wc1[i] = W1n[i];
    if (i < 512)  g_Wc1[1024 + i] = W1r[i] + W1r[512 + i] + P1[i];
    if (i < 32)   g_bc1[i] = b1[i] + b1[32 + i] + pb1[i];
    if (i < 16384) {
        int ch = i >> 11, j = i & 2047;
        int k = j >> 6, n = j & 63;
        float w;
        if (ch < 7) w = W2n[i];
        else {
            w = P2[j];
            for (int r = 0; r < 7; r++) w += W2r[r * 2048 + j];
        }
        unsigned hi = tf32_of(w);
        unsigned lo = tf32_of(w - __uint_as_float(hi));
        int o = ch * 2048 + n * 32 + k;
        g_W2hi[o] = __uint_as_float(hi);
        g_W2lo[o] = __uint_as_float(lo);
    }
    if (i < 64) {
        float s = pb2[i];
        for (int r = 0; r < 7; r++) s += b2[r * 64 + i];
        g_bc2[i] = s;
    }
}

// ---------------- warp-cooperative scatter, fp16 msgs, D = 32 halves (64B/row) ----------------
// 4 lanes per edge, 4 batches of 8 edges; one 64B gather + one 64B RMW per edge.
__global__ void __launch_bounds__(256)
k_scatter32h(ESet es, const __half* __restrict__ feat, __half* __restrict__ msg) {
    int lane = threadIdx.x & 31;
    int warp = (blockIdx.x * 256 + threadIdx.x) >> 5;
    int e = warp * 32 + lane;
    int r = blockIdx.y;
    const int* ei = es.e[r];
    int src = __ldg(ei + e);
    int dst = __ldg(ei + NE + e);
    float* cp = es.cnt[r];
    if (cp) red_add_f(cp + dst, 1.0f);
    int sub = lane >> 2;   // edge-within-batch 0..7
    int c   = lane & 3;    // 16B chunk 0..3
#pragma unroll
    for (int j = 0; j < 4; j++) {
        int el = j * 8 + sub;
        int s = __shfl_sync(0xffffffffu, src, el);
        int d = __shfl_sync(0xffffffffu, dst, el);
        float4 v = __ldg(reinterpret_cast<const float4*>(feat + (size_t)s * 32) + c);
        red_add_v4h(msg + ((size_t)r * NN + d) * 32 + 8 * c, v);
    }
}

// ---------------- warp-cooperative scatters (f32, layers 0/1; R4-proven) ----------------
__global__ void __launch_bounds__(256)
k_scatter16(ESet es, const float* __restrict__ feat, float* __restrict__ msg) {
    int lane = threadIdx.x & 31;
    int warp = (blockIdx.x * 256 + threadIdx.x) >> 5;
    int e = warp * 32 + lane;
    int r = blockIdx.y;
    const int* ei = es.e[r];
    int src = __ldg(ei + e);
    int dst = __ldg(ei + NE + e);
    int sub = lane >> 2;
    int c   = lane & 3;
#pragma unroll
    for (int j = 0; j < 4; j++) {
        int el = j * 8 + sub;
        int s = __shfl_sync(0xffffffffu, src, el);
        int d = __shfl_sync(0xffffffffu, dst, el);
        float4 v = __ldg(reinterpret_cast<const float4*>(feat + (size_t)s * 16) + c);
        red_add_v4(msg + ((size_t)r * NN + d) * 16 + 4 * c, v);
    }
}

__global__ void __launch_bounds__(256)
k_scatter6(ESet es, const float* __restrict__ x, float* __restrict__ msg) {
    int lane = threadIdx.x & 31;
    int warp = (blockIdx.x * 256 + threadIdx.x) >> 5;
    int e = warp * 32 + lane;
    int r = blockIdx.y;
    const int* ei = es.e[r];
    int src = __ldg(ei + e);
    int dst = __ldg(ei + NE + e);
    int sub = lane >> 1;
    int c   = lane & 1;
#pragma unroll
    for (int j = 0; j < 2; j++) {
        int el = j * 16 + sub;
        int s = __shfl_sync(0xffffffffu, src, el);
        int d = __shfl_sync(0xffffffffu, dst, el);
        const float* xs = x + (size_t)s * 6;
        float2 a = __ldg(reinterpret_cast<const float2*>(xs) + c);
        float  v = __ldg(xs + 4 + c);
        float* m = msg + ((size_t)r * NN + d) * 6;
        red_add_v2(m + 2 * c, a);
        red_add_f(m + 4 + c, v);
    }
}

// ---------------- pipelined node-parallel GEMM (scalar FFMA; layer 1) ----------------
// HOUT: also emit fp16 copy of the output (for the fp16 layer-2 gather).
template <int CHUNK, int NCH, int OUT, bool RELU, bool HOUT>
__global__ void __launch_bounds__(256)
k_gemm(GSrc s, const float* __restrict__ Wcat, const float* __restrict__ bias,
       float* __restrict__ out, __half* __restrict__ hout) {
    constexpr int LDT = CHUNK + 1;
    constexpr int NF4 = CHUNK / 4;
    constexpr int WTOT4 = CHUNK * OUT / 4;
    constexpr int WPT = (WTOT4 + 255) / 256;
    __shared__ __align__(16) float shW[CHUNK * OUT];
    __shared__ float shT[256 * LDT];
    int tid  = threadIdx.x;
    int base = blockIdx.x * 256;
    int node = base + tid;

    float acc[OUT];
#pragma unroll
    for (int j = 0; j < OUT; j++) acc[j] = __ldg(bias + j);

    float4 pre[NF4];
    float4 preW[WPT];
    {
        const float4* src4 = reinterpret_cast<const float4*>(s.p[0]);
#pragma unroll
        for (int j = 0; j < NF4; j++) {
            int f = j * 256 + tid;
            int g = base * NF4 + f;
            pre[j] = __ldg(src4 + (g < NN * NF4 ? g : NN * NF4 - 1));
        }
        const float4* w4 = reinterpret_cast<const float4*>(Wcat);
#pragma unroll
        for (int j = 0; j < WPT; j++) {
            int f = j * 256 + tid;
            preW[j] = (f < WTOT4) ? __ldg(w4 + f) : make_float4(0.f, 0.f, 0.f, 0.f);
        }
    }

    for (int ch = 0; ch < NCH; ch++) {
        __syncthreads();
#pragma unroll
        for (int j = 0; j < NF4; j++) {
            int f = j * 256 + tid;
            int nl = f / NF4, c = f % NF4;
            float4 v = pre[j];
            float* t = shT + nl * LDT + 4 * c;
            t[0] = v.x; t[1] = v.y; t[2] = v.z; t[3] = v.w;
        }
#pragma unroll
        for (int j = 0; j < WPT; j++) {
            int f = j * 256 + tid;
            if (f < WTOT4) reinterpret_cast<float4*>(shW)[f] = preW[j];
        }
        __syncthreads();

        if (ch + 1 < NCH) {
            const float4* src4 = reinterpret_cast<const float4*>(s.p[ch + 1]);
#pragma unroll
            for (int j = 0; j < NF4; j++) {
                int f = j * 256 + tid;
                int g = base * NF4 + f;
                pre[j] = __ldg(src4 + (g < NN * NF4 ? g : NN * NF4 - 1));
            }
            const float4* w4 = reinterpret_cast<const float4*>(Wcat + (size_t)(ch + 1) * CHUNK * OUT);
#pragma unroll
            for (int j = 0; j < WPT; j++) {
                int f = j * 256 + tid;
                preW[j] = (f < WTOT4) ? __ldg(w4 + f) : make_float4(0.f, 0.f, 0.f, 0.f);
            }
        }

        float sc = 1.f;
        const float* cp = s.cnt[ch];
        if (cp != nullptr && node < NN) sc = 1.f / fmaxf(__ldg(cp + node), 1.f);
#pragma unroll 8
        for (int k = 0; k < CHUNK; k++) {
            float m = shT[tid * LDT + k] * sc;
            const float4* w4 = reinterpret_cast<const float4*>(shW + k * OUT);
#pragma unroll
            for (int j = 0; j < OUT / 4; j++) {
                float4 w = w4[j];
                acc[4 * j + 0] += m * w.x;
                acc[4 * j + 1] += m * w.y;
                acc[4 * j + 2] += m * w.z;
                acc[4 * j + 3] += m * w.w;
            }
        }
    }

    if (node < NN) {
        float4* o4 = reinterpret_cast<float4*>(out + (size_t)node * OUT);
        __half2* h2 = HOUT ? reinterpret_cast<__half2*>(hout + (size_t)node * OUT) : nullptr;
#pragma unroll
        for (int j = 0; j < OUT / 4; j++) {
            float4 v;
            v.x = acc[4 * j + 0]; v.y = acc[4 * j + 1];
            v.z = acc[4 * j + 2]; v.w = acc[4 * j + 3];
            if (RELU) {
                v.x = fmaxf(v.x, 0.f); v.y = fmaxf(v.y, 0.f);
                v.z = fmaxf(v.z, 0.f); v.w = fmaxf(v.w, 0.f);
            }
            o4[j] = v;
            if (HOUT) {
                h2[2 * j]     = __floats2half2_rn(v.x, v.y);
                h2[2 * j + 1] = __floats2half2_rn(v.z, v.w);
            }
        }
    }
}

// ---------------- simple GEMM for CHUNK=6 (layer 0; small, proven) ----------------
template <int CHUNK, int NCH, int OUT, bool RELU>
__global__ void __launch_bounds__(256)
k_gemm_s(GSrc s, const float* __restrict__ Wcat, const float* __restrict__ bias,
         float* __restrict__ out) {
    __shared__ __align__(16) float shW[CHUNK * OUT];
    __shared__ float shT[256 * (CHUNK + 1)];
    int tid  = threadIdx.x;
    int base = blockIdx.x * 256;
    int node = base + tid;

    float acc[OUT];
#pragma unroll
    for (int j = 0; j < OUT; j++) acc[j] = bias[j];

    for (int ch = 0; ch < NCH; ch++) {
        __syncthreads();
        for (int i = tid; i < CHUNK * OUT; i += 256)
            shW[i] = Wcat[ch * CHUNK * OUT + i];
        const float* src = s.p[ch];
        for (int i = tid; i < 256 * CHUNK; i += 256) {
            int nl = i / CHUNK, k = i - nl * CHUNK;
            int nd = base + nl;
            shT[nl * (CHUNK + 1) + k] = (nd < NN) ? src[(size_t)nd * CHUNK + k] : 0.f;
        }
        __syncthreads();
#pragma unroll
        for (int k = 0; k < CHUNK; k++) {
            float m = shT[tid * (CHUNK + 1) + k];
            const float4* w4 = reinterpret_cast<const float4*>(shW + k * OUT);
#pragma unroll
            for (int j = 0; j < OUT / 4; j++) {
                float4 w = w4[j];
                acc[4 * j + 0] += m * w.x;
                acc[4 * j + 1] += m * w.y;
                acc[4 * j + 2] += m * w.z;
                acc[4 * j + 3] += m * w.w;
            }
        }
    }

    if (node < NN) {
        float4* o4 = reinterpret_cast<float4*>(out + (size_t)node * OUT);
#pragma unroll
        for (int j = 0; j < OUT / 4; j++) {
            float4 v;
            v.x = acc[4 * j + 0]; v.y = acc[4 * j + 1];
            v.z = acc[4 * j + 2]; v.w = acc[4 * j + 3];
            if (RELU) {
                v.x = fmaxf(v.x, 0.f); v.y = fmaxf(v.y, 0.f);
                v.z = fmaxf(v.z, 0.f); v.w = fmaxf(v.w, 0.f);
            }
            o4[j] = v;
        }
    }
}

// ---------------- layer-2 GEMM: split-tf32 mma.sync, fp16 msg channels ----------------
// Channels 0..6: fp16 messages (fp16 exactly tf32-representable; A-lo needed only
// where the per-node mean scale is applied: ch 2,3,6). Channel 7: f32 self (full split).
__global__ void __launch_bounds__(256)
k_gemm2_tc(const __half* __restrict__ msgh, const float* __restrict__ h1,
           const float* __restrict__ cnt,
           const float* __restrict__ Whi, const float* __restrict__ Wlo,
           const float* __restrict__ bias, float* __restrict__ out) {
    __shared__ float shA [128 * 36];
    __shared__ float shWh[64 * 36];
    __shared__ float shWl[64 * 36];
    __shared__ float shSc[3][128];
    __shared__ float shB[64];
    int tid  = threadIdx.x;
    int lane = tid & 31;
    int w    = tid >> 5;
    int base = blockIdx.x * 128;

    if (tid < 64) shB[tid] = __ldg(bias + tid);
    if (tid < 128) {
        int node = base + tid;
#pragma unroll
        for (int m = 0; m < 3; m++) {
            float c = (node < NN) ? __ldg(cnt + m * NN + node) : 1.f;
            shSc[m][tid] = 1.f / fmaxf(c, 1.f);
        }
    }

    float d[8][4];
#pragma unroll
    for (int nt = 0; nt < 8; nt++)
#pragma unroll
        for (int j = 0; j < 4; j++) d[nt][j] = 0.f;

    float4 pre[4];
    float4 preW[4];
    // prefetch channel 0 (fp16: 128 rows x 64B = 512 f4)
    {
        const float4* src4 = reinterpret_cast<const float4*>(msgh);
#pragma unroll
        for (int j = 0; j < 2; j++) {
            int f = j * 256 + tid;
            int g = base * 4 + f;
            pre[j] = __ldg(src4 + (g < NN * 4 ? g : NN * 4 - 1));
        }
        const float4* wh4 = reinterpret_cast<const float4*>(Whi);
        const float4* wl4 = reinterpret_cast<const float4*>(Wlo);
#pragma unroll
        for (int j = 0; j < 2; j++) preW[j]     = __ldg(wh4 + j * 256 + tid);
#pragma unroll
        for (int j = 0; j < 2; j++) preW[2 + j] = __ldg(wl4 + j * 256 + tid);
    }

    int rl1 = 16 * w + (lane >> 2);
    int rl2 = rl1 + 8;
    int kc  = lane & 3;
    int nb  = lane >> 2;

    for (int ch = 0; ch < 8; ch++) {
        __syncthreads();   // WAR
        int msel = (ch == 2) ? 0 : (ch == 3) ? 1 : (ch == 6) ? 2 : -1;
        if (ch < 7) {
            // stage fp16: each f4 = 8 halves = 8 consecutive k of one row
#pragma unroll
            for (int j = 0; j < 2; j++) {
                int f = j * 256 + tid;
                int nl = f >> 2, c4 = f & 3;
                const __half2* hp = reinterpret_cast<const __half2*>(&pre[j]);
                float sc = (msel >= 0) ? shSc[msel][nl] : 1.f;
                float* t = shA + nl * 36 + 8 * c4;
#pragma unroll
                for (int q = 0; q < 4; q++) {
                    float2 f2 = __half22float2(hp[q]);
                    t[2 * q]     = f2.x * sc;
                    t[2 * q + 1] = f2.y * sc;
                }
            }
        } else {
#pragma unroll
            for (int j = 0; j < 4; j++) {
                int f = j * 256 + tid;
                int nl = f >> 3, c4 = f & 7;
                float4 v = pre[j];
                float* t = shA + nl * 36 + 4 * c4;
                t[0] = v.x; t[1] = v.y; t[2] = v.z; t[3] = v.w;
            }
        }
#pragma unroll
        for (int j = 0; j < 2; j++) {
            int f = j * 256 + tid;
            int n = f >> 3, k4 = f & 7;
            float4 vh = preW[j], vl = preW[2 + j];
            float* th = shWh + n * 36 + 4 * k4;
            float* tl = shWl + n * 36 + 4 * k4;
            th[0] = vh.x; th[1] = vh.y; th[2] = vh.z; th[3] = vh.w;
            tl[0] = vl.x; tl[1] = vl.y; tl[2] = vl.z; tl[3] = vl.w;
        }
        __syncthreads();   // RAW

        if (ch + 1 < 8) {
            if (ch + 1 < 7) {
                const float4* src4 = reinterpret_cast<const float4*>(msgh + (size_t)(ch + 1) * NN * 32);
#pragma unroll
                for (int j = 0; j < 2; j++) {
                    int f = j * 256 + tid;
                    int g = base * 4 + f;
                    pre[j] = __ldg(src4 + (g < NN * 4 ? g : NN * 4 - 1));
                }
            } else {
                const float4* src4 = reinterpret_cast<const float4*>(h1);
#pragma unroll
                for (int j = 0; j < 4; j++) {
                    int f = j * 256 + tid;
                    int g = base * 8 + f;
                    pre[j] = __ldg(src4 + (g < NN * 8 ? g : NN * 8 - 1));
                }
            }
            const float4* wh4 = reinterpret_cast<const float4*>(Whi + (ch + 1) * 2048);
            const float4* wl4 = reinterpret_cast<const float4*>(Wlo + (ch + 1) * 2048);
#pragma unroll
            for (int j = 0; j < 2; j++) preW[j]     = __ldg(wh4 + j * 256 + tid);
#pragma unroll
            for (int j = 0; j < 2; j++) preW[2 + j] = __ldg(wl4 + j * 256 + tid);
        }

        bool needLo = (msel >= 0) || (ch == 7);   // A has sub-tf32 bits only when scaled or f32
#pragma unroll
        for (int k0 = 0; k0 < 32; k0 += 8) {
            int c = k0 + kc;
            float a0f = shA[rl1 * 36 + c];
            float a1f = shA[rl2 * 36 + c];
            float a2f = shA[rl1 * 36 + c + 4];
            float a3f = shA[rl2 * 36 + c + 4];
            unsigned ah0 = tf32_of(a0f), ah1 = tf32_of(a1f);
            unsigned ah2 = tf32_of(a2f), ah3 = tf32_of(a3f);
            unsigned al0 = 0, al1 = 0, al2 = 0, al3 = 0;
            if (needLo) {
                al0 = tf32_of(a0f - __uint_as_float(ah0));
                al1 = tf32_of(a1f - __uint_as_float(ah1));
                al2 = tf32_of(a2f - __uint_as_float(ah2));
                al3 = tf32_of(a3f - __uint_as_float(ah3));
            }
#pragma unroll
            for (int nt = 0; nt < 8; nt++) {
                int wr = (nt * 8 + nb) * 36 + k0 + kc;
                unsigned bh0 = __float_as_uint(shWh[wr]);
                unsigned bh1 = __float_as_uint(shWh[wr + 4]);
                unsigned bl0 = __float_as_uint(shWl[wr]);
                unsigned bl1 = __float_as_uint(shWl[wr + 4]);
                mma_tf32(d[nt], ah0, ah1, ah2, ah3, bh0, bh1);
                mma_tf32(d[nt], ah0, ah1, ah2, ah3, bl0, bl1);
                if (needLo) mma_tf32(d[nt], al0, al1, al2, al3, bh0, bh1);
            }
        }
    }

    int r1 = base + rl1;
    int r2 = base + rl2;
#pragma unroll
    for (int nt = 0; nt < 8; nt++) {
        int c0 = nt * 8 + 2 * kc;
        float b0 = shB[c0], b1 = shB[c0 + 1];
        if (r1 < NN) {
            float2 v;
            v.x = fmaxf(d[nt][0] + b0, 0.f);
            v.y = fmaxf(d[nt][1] + b1, 0.f);
            *reinterpret_cast<float2*>(out + (size_t)r1 * 64 + c0) = v;
        }
        if (r2 < NN) {
            float2 v;
            v.x = fmaxf(d[nt][2] + b0, 0.f);
            v.y = fmaxf(d[nt][3] + b1, 0.f);
            *reinterpret_cast<float2*>(out + (size_t)r2 * 64 + c0) = v;
        }
    }
}

// ---------------- host ----------------
extern "C" void kernel_launch(void* const* d_in, const int* in_sizes, int n_in,
                              void* d_out, int out_size) {
    (void)n_in; (void)out_size;
    const float* x = (const float*)d_in[0];

    int eb, wb;
    if (in_sizes[1] == 2 * NE) { eb = 1; wb = 10; }
    else                        { wb = 1; eb = 14; }

    const int* E[9];
    for (int i = 0; i < 9; i++) E[i] = (const int*)d_in[eb + i];
    const float* W0n = (const float*)d_in[wb + 0];
    const float* W0r = (const float*)d_in[wb + 1];
    const float* b0  = (const float*)d_in[wb + 2];
    const float* W1n = (const float*)d_in[wb + 3];
    const float* W1r = (const float*)d_in[wb + 4];
    const float* b1  = (const float*)d_in[wb + 5];
    const float* P1  = (const float*)d_in[wb + 6];
    const float* pb1 = (const float*)d_in[wb + 7];
    const float* W2n = (const float*)d_in[wb + 8];
    const float* W2r = (const float*)d_in[wb + 9];
    const float* b2  = (const float*)d_in[wb + 10];
    const float* P2  = (const float*)d_in[wb + 11];
    const float* pb2 = (const float*)d_in[wb + 12];

    float *msg1, *msg0, *cnt, *h0, *h1, *Wc0, *Wc1, *W2hi, *W2lo, *bc0, *bc1, *bc2;
    __half *msg2h, *h1h;
    cudaGetSymbolAddress((void**)&msg2h, g_msg2h);
    cudaGetSymbolAddress((void**)&msg1, g_msg1);
    cudaGetSymbolAddress((void**)&msg0, g_msg0);
    cudaGetSymbolAddress((void**)&cnt,  g_cnt);
    cudaGetSymbolAddress((void**)&h0,   g_h0);
    cudaGetSymbolAddress((void**)&h1,   g_h1);
    cudaGetSymbolAddress((void**)&h1h,  g_h1h);
    cudaGetSymbolAddress((void**)&Wc0,  g_Wc0);
    cudaGetSymbolAddress((void**)&Wc1,  g_Wc1);
    cudaGetSymbolAddress((void**)&W2hi, g_W2hi);
    cudaGetSymbolAddress((void**)&W2lo, g_W2lo);
    cudaGetSymbolAddress((void**)&bc0,  g_bc0);
    cudaGetSymbolAddress((void**)&bc1,  g_bc1);
    cudaGetSymbolAddress((void**)&bc2,  g_bc2);

    k_zero<<<2048, 256>>>();
    k_prep<<<64, 256>>>(W0n, W0r, b0, W1n, W1r, b1, P1, pb1, W2n, W2r, b2, P2, pb2);

    // ---- layer 0: x(6) -> h0(16), relations {connected_to, ordered_next}, sum ----
    ESet es01 = {};
    es01.e[0] = E[0]; es01.e[1] = E[1];
    k_scatter6<<<dim3(NE / 256, 2), 256>>>(es01, x, msg0);

    GSrc s0 = {};
    s0.p[0] = msg0; s0.p[1] = msg0 + (size_t)NN * 6; s0.p[2] = x;
    k_gemm_s<6, 3, 16, false><<<(NN + 255) / 256, 256>>>(s0, Wc0, bc0, h0);

    // ---- layer 1: h0(16) -> h1(32), same relations, + P1 residual, relu ----
    k_scatter16<<<dim3(NE / 256, 2), 256>>>(es01, h0, msg1);

    GSrc s1 = {};
    s1.p[0] = msg1; s1.p[1] = msg1 + (size_t)NN * 16; s1.p[2] = h0;
    k_gemm<16, 3, 32, true, true><<<(NN + 255) / 256, 256>>>(s1, Wc1, bc1, h1, h1h);

    // ---- layer 2: h1(32) -> out(64), 7 relations (mean at 2,3,6), + P2, relu ----
    ESet es2 = {};
    for (int r = 0; r < 7; r++) es2.e[r] = E[2 + r];
    es2.cnt[2] = cnt; es2.cnt[3] = cnt + NN; es2.cnt[6] = cnt + 2 * NN;
    k_scatter32h<<<dim3(NE / 256, 7), 256>>>(es2, h1h, msg2h);

    k_gemm2_tc<<<(NN + 127) / 128, 256>>>(msg2h, h1, cnt, W2hi, W2lo, bc2, (float*)d_out);
}

// round 12
// speedup vs baseline: 3.8045x; 1.0093x over previous
#include <cuda_runtime.h>
#include <cuda_fp16.h>

#define NN 100000
#define NE 800000

// ---------------- scratch (static __device__ globals; no allocs) ----------------
__device__ __align__(16) __half g_msg2h[7 * NN * 32];  // 44.8 MB fp16 messages
__device__ __align__(16) __half g_msg1h[2 * NN * 16];  // 6.4 MB fp16 messages
__device__ __align__(16) float g_msg0[2 * NN * 6];
__device__ __align__(16) float g_cnt [3 * NN];
__device__ __align__(16) float g_h0  [NN * 16];
__device__ __align__(16) __half g_h0h[NN * 16];        // fp16 copy for layer-1 gather
__device__ __align__(16) float g_h1  [NN * 32];
__device__ __align__(16) __half g_h1h[NN * 32];        // fp16 copy for layer-2 gather
__device__ __align__(16) float g_Wc0[3 * 6 * 16];
__device__ __align__(16) float g_Wc1[3 * 16 * 32];
__device__ __align__(16) float g_W2hi[8 * 64 * 32];    // [ch][n][k], tf32-exact
__device__ __align__(16) float g_W2lo[8 * 64 * 32];
__device__ __align__(16) float g_bc0[16];
__device__ __align__(16) float g_bc1[32];
__device__ __align__(16) float g_bc2[64];

// ---------------- helpers ----------------
__device__ __forceinline__ void red_add_v2(float* a, float2 v) {
    asm volatile("red.global.add.v2.f32 [%0], {%1,%2};"
                 :: "l"(a), "f"(v.x), "f"(v.y) : "memory");
}
__device__ __forceinline__ void red_add_f(float* a, float v) {
    asm volatile("red.global.add.f32 [%0], %1;" :: "l"(a), "f"(v) : "memory");
}
// 16B of packed halves (8 halves) reduced in one lane-op (max RED width: 128 bits)
__device__ __forceinline__ void red_add_v4h(__half* a, float4 bits) {
    asm volatile("red.global.add.noftz.v4.f16x2 [%0], {%1,%2,%3,%4};"
                 :: "l"(a), "r"(__float_as_uint(bits.x)), "r"(__float_as_uint(bits.y)),
                    "r"(__float_as_uint(bits.z)), "r"(__float_as_uint(bits.w)) : "memory");
}
__device__ __forceinline__ unsigned tf32_of(float f) {
    unsigned r;
    asm("cvt.rna.tf32.f32 %0, %1;" : "=r"(r) : "f"(f));
    return r;
}
__device__ __forceinline__ void mma_tf32(float* d, unsigned a0, unsigned a1,
                                         unsigned a2, unsigned a3,
                                         unsigned b0, unsigned b1) {
    asm("mma.sync.aligned.m16n8k8.row.col.f32.tf32.tf32.f32 "
        "{%0,%1,%2,%3}, {%4,%5,%6,%7}, {%8,%9}, {%0,%1,%2,%3};"
        : "+f"(d[0]), "+f"(d[1]), "+f"(d[2]), "+f"(d[3])
        : "r"(a0), "r"(a1), "r"(a2), "r"(a3), "r"(b0), "r"(b1));
}

struct ESet { const int* e[7]; float* cnt[7]; };
struct GSrc { const float* p[8]; const float* cnt[8]; };

// ---------------- zero scratch ----------------
__global__ void k_zero() {
    int tid = blockIdx.x * blockDim.x + threadIdx.x;
    int stride = gridDim.x * blockDim.x;
    float4 z = make_float4(0.f, 0.f, 0.f, 0.f);
    float4* a2 = reinterpret_cast<float4*>(g_msg2h);
    for (int i = tid; i < 7 * NN * 32 / 8; i += stride) a2[i] = z;
    float4* a1 = reinterpret_cast<float4*>(g_msg1h);
    for (int i = tid; i < 2 * NN * 16 / 8; i += stride) a1[i] = z;
    float4* a0 = reinterpret_cast<float4*>(g_msg0);
    for (int i = tid; i < 2 * NN * 6 / 4; i += stride) a0[i] = z;
    float4* ac = reinterpret_cast<float4*>(g_cnt);
    for (int i = tid; i < 3 * NN / 4; i += stride) ac[i] = z;
}

// ---------------- combine weights (self terms + residual projections folded) ----------------
__global__ void k_prep(const float* __restrict__ W0n, const float* __restrict__ W0r,
                       const float* __restrict__ b0,
                       const float* __restrict__ W1n, const float* __restrict__ W1r,
                       const float* __restrict__ b1,  const float* __restrict__ P1,
                       const float* __restrict__ pb1,
                       const float* __restrict__ W2n, const float* __restrict__ W2r,
                       const float* __restrict__ b2,  const float* __restrict__ P2,
                       const float* __restrict__ pb2) {
    int i = blockIdx.x * blockDim.x + threadIdx.x;
    if (i < 192) g_Wc0[i] = W0n[i];
    if (i < 96)  g_Wc0[192 + i] = W0r[i] + W0r[96 + i];
    if (i < 16)  g_bc0[i] = b0[i] + b0[16 + i];
    if (i < 1024) g_Wc1[i] = W1n[i];
    if (i < 512)  g_Wc1[1024 + i] = W1r[i] + W1r[512 + i] + P1[i];
    if (i < 32)   g_bc1[i] = b1[i] + b1[32 + i] + pb1[i];
    if (i < 16384) {
        int ch = i >> 11, j = i & 2047;
        int k = j >> 6, n = j & 63;
        float w;
        if (ch < 7) w = W2n[i];
        else {
            w = P2[j];
            for (int r = 0; r < 7; r++) w += W2r[r * 2048 + j];
        }
        unsigned hi = tf32_of(w);
        unsigned lo = tf32_of(w - __uint_as_float(hi));
        int o = ch * 2048 + n * 32 + k;
        g_W2hi[o] = __uint_as_float(hi);
        g_W2lo[o] = __uint_as_float(lo);
    }
    if (i < 64) {
        float s = pb2[i];
        for (int r = 0; r < 7; r++) s += b2[r * 64 + i];
        g_bc2[i] = s;
    }
}

// ---------------- scatter layer 2: fp16, 4 lanes/edge, v4.f16x2 RED (R7-proven) ----------------
__global__ void __launch_bounds__(256)
k_scatter32h(ESet es, const __half* __restrict__ feat, __half* __restrict__ msg) {
    int lane = threadIdx.x & 31;
    int warp = (blockIdx.x * 256 + threadIdx.x) >> 5;
    int e = warp * 32 + lane;
    int r = blockIdx.y;
    const int* ei = es.e[r];
    int src = __ldg(ei + e);
    int dst = __ldg(ei + NE + e);
    float* cp = es.cnt[r];
    if (cp) red_add_f(cp + dst, 1.0f);
    int sub = lane >> 2;   // edge-within-batch 0..7
    int c   = lane & 3;    // 16B chunk 0..3
#pragma unroll
    for (int j = 0; j < 4; j++) {
        int el = j * 8 + sub;
        int s = __shfl_sync(0xffffffffu, src, el);
        int d = __shfl_sync(0xffffffffu, dst, el);
        float4 v = __ldg(reinterpret_cast<const float4*>(feat + (size_t)s * 32) + c);
        red_add_v4h(msg + ((size_t)r * NN + d) * 32 + 8 * c, v);
    }
}

// ---------------- scatter layer 1: fp16, edge-per-thread, 2x v4.f16x2 RED per edge ----------------
__global__ void __launch_bounds__(256)
k_scatter16h(ESet es, const __half* __restrict__ feat, __half* __restrict__ msg) {
    int e = blockIdx.x * 256 + threadIdx.x;
    int r = blockIdx.y;
    const int* ei = es.e[r];
    int src = __ldg(ei + e);
    int dst = __ldg(ei + NE + e);
    const float4* fp = reinterpret_cast<const float4*>(feat + (size_t)src * 16);
    float4 v0 = __ldg(fp), v1 = __ldg(fp + 1);
    __half* m = msg + ((size_t)r * NN + dst) * 16;
    red_add_v4h(m, v0);
    red_add_v4h(m + 8, v1);
}

// ---------------- scatter layer 0: f32 (R4-proven) ----------------
__global__ void __launch_bounds__(256)
k_scatter6(ESet es, const float* __restrict__ x, float* __restrict__ msg) {
    int lane = threadIdx.x & 31;
    int warp = (blockIdx.x * 256 + threadIdx.x) >> 5;
    int e = warp * 32 + lane;
    int r = blockIdx.y;
    const int* ei = es.e[r];
    int src = __ldg(ei + e);
    int dst = __ldg(ei + NE + e);
    int sub = lane >> 1;
    int c   = lane & 1;
#pragma unroll
    for (int j = 0; j < 2; j++) {
        int el = j * 16 + sub;
        int s = __shfl_sync(0xffffffffu, src, el);
        int d = __shfl_sync(0xffffffffu, dst, el);
        const float* xs = x + (size_t)s * 6;
        float2 a = __ldg(reinterpret_cast<const float2*>(xs) + c);
        float  v = __ldg(xs + 4 + c);
        float* m = msg + ((size_t)r * NN + d) * 6;
        red_add_v2(m + 2 * c, a);
        red_add_f(m + 4 + c, v);
    }
}

// ---------------- layer-0 GEMM (CHUNK=6, simple; emits h0 + fp16 h0h) ----------------
__global__ void __launch_bounds__(256)
k_gemm0(GSrc s, const float* __restrict__ Wcat, const float* __restrict__ bias,
        float* __restrict__ out, __half* __restrict__ hout) {
    constexpr int CHUNK = 6, NCH = 3, OUT = 16;
    __shared__ __align__(16) float shW[CHUNK * OUT];
    __shared__ float shT[256 * (CHUNK + 1)];
    int tid  = threadIdx.x;
    int base = blockIdx.x * 256;
    int node = base + tid;

    float acc[OUT];
#pragma unroll
    for (int j = 0; j < OUT; j++) acc[j] = bias[j];

    for (int ch = 0; ch < NCH; ch++) {
        __syncthreads();
        for (int i = tid; i < CHUNK * OUT; i += 256)
            shW[i] = Wcat[ch * CHUNK * OUT + i];
        const float* src = s.p[ch];
        for (int i = tid; i < 256 * CHUNK; i += 256) {
            int nl = i / CHUNK, k = i - nl * CHUNK;
            int nd = base + nl;
            shT[nl * (CHUNK + 1) + k] = (nd < NN) ? src[(size_t)nd * CHUNK + k] : 0.f;
        }
        __syncthreads();
#pragma unroll
        for (int k = 0; k < CHUNK; k++) {
            float m = shT[tid * (CHUNK + 1) + k];
            const float4* w4 = reinterpret_cast<const float4*>(shW + k * OUT);
#pragma unroll
            for (int j = 0; j < OUT / 4; j++) {
                float4 w = w4[j];
                acc[4 * j + 0] += m * w.x;
                acc[4 * j + 1] += m * w.y;
                acc[4 * j + 2] += m * w.z;
                acc[4 * j + 3] += m * w.w;
            }
        }
    }

    if (node < NN) {
        float4* o4 = reinterpret_cast<float4*>(out + (size_t)node * OUT);
        __half2* h2 = reinterpret_cast<__half2*>(hout + (size_t)node * OUT);
#pragma unroll
        for (int j = 0; j < OUT / 4; j++) {
            float4 v;
            v.x = acc[4 * j + 0]; v.y = acc[4 * j + 1];
            v.z = acc[4 * j + 2]; v.w = acc[4 * j + 3];
            o4[j] = v;
            h2[2 * j]     = __floats2half2_rn(v.x, v.y);
            h2[2 * j + 1] = __floats2half2_rn(v.z, v.w);
        }
    }
}

// ---------------- layer-1 GEMM: 2 fp16 msg channels + f32 self, pipelined ----------------
// out = relu( msg1h[0]@W0 + msg1h[1]@W1 + h0@Wself + bias ); emits h1 + fp16 h1h.
__global__ void __launch_bounds__(256)
k_gemm1(const __half* __restrict__ msgh, const float* __restrict__ h0,
        const float* __restrict__ Wcat, const float* __restrict__ bias,
        float* __restrict__ out, __half* __restrict__ hout) {
    constexpr int CHUNK = 16, OUT = 32, LDT = CHUNK + 1;
    __shared__ __align__(16) float shW[CHUNK * OUT];
    __shared__ float shT[256 * LDT];
    int tid  = threadIdx.x;
    int base = blockIdx.x * 256;
    int node = base + tid;

    float acc[OUT];
#pragma unroll
    for (int j = 0; j < OUT; j++) acc[j] = __ldg(bias + j);

    float4 pre[4];
    float4 preW[2];
    // prefetch fp16 channel 0: 256 rows x 32B = 512 f4 -> 2 f4/thread
    {
        const float4* src4 = reinterpret_cast<const float4*>(msgh);
#pragma unroll
        for (int j = 0; j < 2; j++) {
            int f = j * 256 + tid;
            int g = base * 2 + f;
            pre[j] = __ldg(src4 + (g < NN * 2 ? g : NN * 2 - 1));
        }
        const float4* w4 = reinterpret_cast<const float4*>(Wcat);
#pragma unroll
        for (int j = 0; j < 2; j++) {
            int f = j * 256 + tid;
            preW[j] = (f < 128) ? __ldg(w4 + f) : make_float4(0.f, 0.f, 0.f, 0.f);
        }
    }

    for (int ch = 0; ch < 3; ch++) {
        __syncthreads();   // WAR
        if (ch < 2) {
            // fp16 staging: each f4 = 8 halves of one row
#pragma unroll
            for (int j = 0; j < 2; j++) {
                int f = j * 256 + tid;
                int nl = f >> 1, c = f & 1;
                const __half2* hp = reinterpret_cast<const __half2*>(&pre[j]);
                float* t = shT + nl * LDT + 8 * c;
#pragma unroll
                for (int q = 0; q < 4; q++) {
                    float2 f2 = __half22float2(hp[q]);
                    t[2 * q]     = f2.x;
                    t[2 * q + 1] = f2.y;
                }
            }
        } else {
            // f32 staging: each f4 = 4 floats of one row (4 f4/row)
#pragma unroll
            for (int j = 0; j < 4; j++) {
                int f = j * 256 + tid;
                int nl = f >> 2, c = f & 3;
                float4 v = pre[j];
                float* t = shT + nl * LDT + 4 * c;
                t[0] = v.x; t[1] = v.y; t[2] = v.z; t[3] = v.w;
            }
        }
#pragma unroll
        for (int j = 0; j < 2; j++) {
            int f = j * 256 + tid;
            if (f < 128) reinterpret_cast<float4*>(shW)[f] = preW[j];
        }
        __syncthreads();   // RAW

        if (ch + 1 < 3) {
            if (ch + 1 < 2) {
                const float4* src4 = reinterpret_cast<const float4*>(msgh + (size_t)NN * 16);
#pragma unroll
                for (int j = 0; j < 2; j++) {
                    int f = j * 256 + tid;
                    int g = base * 2 + f;
                    pre[j] = __ldg(src4 + (g < NN * 2 ? g : NN * 2 - 1));
                }
            } else {
                const float4* src4 = reinterpret_cast<const float4*>(h0);
#pragma unroll
                for (int j = 0; j < 4; j++) {
                    int f = j * 256 + tid;
                    int g = base * 4 + f;
                    pre[j] = __ldg(src4 + (g < NN * 4 ? g : NN * 4 - 1));
                }
            }
            const float4* w4 = reinterpret_cast<const float4*>(Wcat + (ch + 1) * CHUNK * OUT);
#pragma unroll
            for (int j = 0; j < 2; j++) {
                int f = j * 256 + tid;
                preW[j] = (f < 128) ? __ldg(w4 + f) : make_float4(0.f, 0.f, 0.f, 0.f);
            }
        }

#pragma unroll 8
        for (int k = 0; k < CHUNK; k++) {
            float m = shT[tid * LDT + k];
            const float4* w4 = reinterpret_cast<const float4*>(shW + k * OUT);
#pragma unroll
            for (int j = 0; j < OUT / 4; j++) {
                float4 w = w4[j];
                acc[4 * j + 0] += m * w.x;
                acc[4 * j + 1] += m * w.y;
                acc[4 * j + 2] += m * w.z;
                acc[4 * j + 3] += m * w.w;
            }
        }
    }

    if (node < NN) {
        float4* o4 = reinterpret_cast<float4*>(out + (size_t)node * OUT);
        __half2* h2 = reinterpret_cast<__half2*>(hout + (size_t)node * OUT);
#pragma unroll
        for (int j = 0; j < OUT / 4; j++) {
            float4 v;
            v.x = fmaxf(acc[4 * j + 0], 0.f);
            v.y = fmaxf(acc[4 * j + 1], 0.f);
            v.z = fmaxf(acc[4 * j + 2], 0.f);
            v.w = fmaxf(acc[4 * j + 3], 0.f);
            o4[j] = v;
            h2[2 * j]     = __floats2half2_rn(v.x, v.y);
            h2[2 * j + 1] = __floats2half2_rn(v.z, v.w);
        }
    }
}

// ---------------- layer-2 GEMM: split-tf32 mma.sync, fp16 msg channels (R7-proven) ----------------
__global__ void __launch_bounds__(256)
k_gemm2_tc(const __half* __restrict__ msgh, const float* __restrict__ h1,
           const float* __restrict__ cnt,
           const float* __restrict__ Whi, const float* __restrict__ Wlo,
           const float* __restrict__ bias, float* __restrict__ out) {
    __shared__ float shA [128 * 36];
    __shared__ float shWh[64 * 36];
    __shared__ float shWl[64 * 36];
    __shared__ float shSc[3][128];
    __shared__ float shB[64];
    int tid  = threadIdx.x;
    int lane = tid & 31;
    int w    = tid >> 5;
    int base = blockIdx.x * 128;

    if (tid < 64) shB[tid] = __ldg(bias + tid);
    if (tid < 128) {
        int node = base + tid;
#pragma unroll
        for (int m = 0; m < 3; m++) {
            float c = (node < NN) ? __ldg(cnt + m * NN + node) : 1.f;
            shSc[m][tid] = 1.f / fmaxf(c, 1.f);
        }
    }

    float d[8][4];
#pragma unroll
    for (int nt = 0; nt < 8; nt++)
#pragma unroll
        for (int j = 0; j < 4; j++) d[nt][j] = 0.f;

    float4 pre[4];
    float4 preW[4];
    {
        const float4* src4 = reinterpret_cast<const float4*>(msgh);
#pragma unroll
        for (int j = 0; j < 2; j++) {
            int f = j * 256 + tid;
            int g = base * 4 + f;
            pre[j] = __ldg(src4 + (g < NN * 4 ? g : NN * 4 - 1));
        }
        const float4* wh4 = reinterpret_cast<const float4*>(Whi);
        const float4* wl4 = reinterpret_cast<const float4*>(Wlo);
#pragma unroll
        for (int j = 0; j < 2; j++) preW[j]     = __ldg(wh4 + j * 256 + tid);
#pragma unroll
        for (int j = 0; j < 2; j++) preW[2 + j] = __ldg(wl4 + j * 256 + tid);
    }

    int rl1 = 16 * w + (lane >> 2);
    int rl2 = rl1 + 8;
    int kc  = lane & 3;
    int nb  = lane >> 2;

    for (int ch = 0; ch < 8; ch++) {
        __syncthreads();   // WAR
        int msel = (ch == 2) ? 0 : (ch == 3) ? 1 : (ch == 6) ? 2 : -1;
        if (ch < 7) {
#pragma unroll
            for (int j = 0; j < 2; j++) {
                int f = j * 256 + tid;
                int nl = f >> 2, c4 = f & 3;
                const __half2* hp = reinterpret_cast<const __half2*>(&pre[j]);
                float sc = (msel >= 0) ? shSc[msel][nl] : 1.f;
                float* t = shA + nl * 36 + 8 * c4;
#pragma unroll
                for (int q = 0; q < 4; q++) {
                    float2 f2 = __half22float2(hp[q]);
                    t[2 * q]     = f2.x * sc;
                    t[2 * q + 1] = f2.y * sc;
                }
            }
        } else {
#pragma unroll
            for (int j = 0; j < 4; j++) {
                int f = j * 256 + tid;
                int nl = f >> 3, c4 = f & 7;
                float4 v = pre[j];
                float* t = shA + nl * 36 + 4 * c4;
                t[0] = v.x; t[1] = v.y; t[2] = v.z; t[3] = v.w;
            }
        }
#pragma unroll
        for (int j = 0; j < 2; j++) {
            int f = j * 256 + tid;
            int n = f >> 3, k4 = f & 7;
            float4 vh = preW[j], vl = preW[2 + j];
            float* th = shWh + n * 36 + 4 * k4;
            float* tl = shWl + n * 36 + 4 * k4;
            th[0] = vh.x; th[1] = vh.y; th[2] = vh.z; th[3] = vh.w;
            tl[0] = vl.x; tl[1] = vl.y; tl[2] = vl.z; tl[3] = vl.w;
        }
        __syncthreads();   // RAW

        if (ch + 1 < 8) {
            if (ch + 1 < 7) {
                const float4* src4 = reinterpret_cast<const float4*>(msgh + (size_t)(ch + 1) * NN * 32);
#pragma unroll
                for (int j = 0; j < 2; j++) {
                    int f = j * 256 + tid;
                    int g = base * 4 + f;
                    pre[j] = __ldg(src4 + (g < NN * 4 ? g : NN * 4 - 1));
                }
            } else {
                const float4* src4 = reinterpret_cast<const float4*>(h1);
#pragma unroll
                for (int j = 0; j < 4; j++) {
                    int f = j * 256 + tid;
                    int g = base * 8 + f;
                    pre[j] = __ldg(src4 + (g < NN * 8 ? g : NN * 8 - 1));
                }
            }
            const float4* wh4 = reinterpret_cast<const float4*>(Whi + (ch + 1) * 2048);
            const float4* wl4 = reinterpret_cast<const float4*>(Wlo + (ch + 1) * 2048);
#pragma unroll
            for (int j = 0; j < 2; j++) preW[j]     = __ldg(wh4 + j * 256 + tid);
#pragma unroll
            for (int j = 0; j < 2; j++) preW[2 + j] = __ldg(wl4 + j * 256 + tid);
        }

        bool needLo = (msel >= 0) || (ch == 7);
#pragma unroll
        for (int k0 = 0; k0 < 32; k0 += 8) {
            int c = k0 + kc;
            float a0f = shA[rl1 * 36 + c];
            float a1f = shA[rl2 * 36 + c];
            float a2f = shA[rl1 * 36 + c + 4];
            float a3f = shA[rl2 * 36 + c + 4];
            unsigned ah0 = tf32_of(a0f), ah1 = tf32_of(a1f);
            unsigned ah2 = tf32_of(a2f), ah3 = tf32_of(a3f);
            unsigned al0 = 0, al1 = 0, al2 = 0, al3 = 0;
            if (needLo) {
                al0 = tf32_of(a0f - __uint_as_float(ah0));
                al1 = tf32_of(a1f - __uint_as_float(ah1));
                al2 = tf32_of(a2f - __uint_as_float(ah2));
                al3 = tf32_of(a3f - __uint_as_float(ah3));
            }
#pragma unroll
            for (int nt = 0; nt < 8; nt++) {
                int wr = (nt * 8 + nb) * 36 + k0 + kc;
                unsigned bh0 = __float_as_uint(shWh[wr]);
                unsigned bh1 = __float_as_uint(shWh[wr + 4]);
                unsigned bl0 = __float_as_uint(shWl[wr]);
                unsigned bl1 = __float_as_uint(shWl[wr + 4]);
                mma_tf32(d[nt], ah0, ah1, ah2, ah3, bh0, bh1);
                mma_tf32(d[nt], ah0, ah1, ah2, ah3, bl0, bl1);
                if (needLo) mma_tf32(d[nt], al0, al1, al2, al3, bh0, bh1);
            }
        }
    }

    int r1 = base + rl1;
    int r2 = base + rl2;
#pragma unroll
    for (int nt = 0; nt < 8; nt++) {
        int c0 = nt * 8 + 2 * kc;
        float b0 = shB[c0], b1 = shB[c0 + 1];
        if (r1 < NN) {
            float2 v;
            v.x = fmaxf(d[nt][0] + b0, 0.f);
            v.y = fmaxf(d[nt][1] + b1, 0.f);
            *reinterpret_cast<float2*>(out + (size_t)r1 * 64 + c0) = v;
        }
        if (r2 < NN) {
            float2 v;
            v.x = fmaxf(d[nt][2] + b0, 0.f);
            v.y = fmaxf(d[nt][3] + b1, 0.f);
            *reinterpret_cast<float2*>(out + (size_t)r2 * 64 + c0) = v;
        }
    }
}

// ---------------- host ----------------
extern "C" void kernel_launch(void* const* d_in, const int* in_sizes, int n_in,
                              void* d_out, int out_size) {
    (void)n_in; (void)out_size;
    const float* x = (const float*)d_in[0];

    int eb, wb;
    if (in_sizes[1] == 2 * NE) { eb = 1; wb = 10; }
    else                        { wb = 1; eb = 14; }

    const int* E[9];
    for (int i = 0; i < 9; i++) E[i] = (const int*)d_in[eb + i];
    const float* W0n = (const float*)d_in[wb + 0];
    const float* W0r = (const float*)d_in[wb + 1];
    const float* b0  = (const float*)d_in[wb + 2];
    const float* W1n = (const float*)d_in[wb + 3];
    const float* W1r = (const float*)d_in[wb + 4];
    const float* b1  = (const float*)d_in[wb + 5];
    const float* P1  = (const float*)d_in[wb + 6];
    const float* pb1 = (const float*)d_in[wb + 7];
    const float* W2n = (const float*)d_in[wb + 8];
    const float* W2r = (const float*)d_in[wb + 9];
    const float* b2  = (const float*)d_in[wb + 10];
    const float* P2  = (const float*)d_in[wb + 11];
    const float* pb2 = (const float*)d_in[wb + 12];

    float *msg0, *cnt, *h0, *h1, *Wc0, *Wc1, *W2hi, *W2lo, *bc0, *bc1, *bc2;
    __half *msg2h, *msg1h, *h0h, *h1h;
    cudaGetSymbolAddress((void**)&msg2h, g_msg2h);
    cudaGetSymbolAddress((void**)&msg1h, g_msg1h);
    cudaGetSymbolAddress((void**)&msg0, g_msg0);
    cudaGetSymbolAddress((void**)&cnt,  g_cnt);
    cudaGetSymbolAddress((void**)&h0,   g_h0);
    cudaGetSymbolAddress((void**)&h0h,  g_h0h);
    cudaGetSymbolAddress((void**)&h1,   g_h1);
    cudaGetSymbolAddress((void**)&h1h,  g_h1h);
    cudaGetSymbolAddress((void**)&Wc0,  g_Wc0);
    cudaGetSymbolAddress((void**)&Wc1,  g_Wc1);
    cudaGetSymbolAddress((void**)&W2hi, g_W2hi);
    cudaGetSymbolAddress((void**)&W2lo, g_W2lo);
    cudaGetSymbolAddress((void**)&bc0,  g_bc0);
    cudaGetSymbolAddress((void**)&bc1,  g_bc1);
    cudaGetSymbolAddress((void**)&bc2,  g_bc2);

    k_zero<<<2048, 256>>>();
    k_prep<<<64, 256>>>(W0n, W0r, b0, W1n, W1r, b1, P1, pb1, W2n, W2r, b2, P2, pb2);

    // ---- layer 0: x(6) -> h0(16), relations {connected_to, ordered_next}, sum ----
    ESet es01 = {};
    es01.e[0] = E[0]; es01.e[1] = E[1];
    k_scatter6<<<dim3(NE / 256, 2), 256>>>(es01, x, msg0);

    GSrc s0 = {};
    s0.p[0] = msg0; s0.p[1] = msg0 + (size_t)NN * 6; s0.p[2] = x;
    k_gemm0<<<(NN + 255) / 256, 256>>>(s0, Wc0, bc0, h0, h0h);

    // ---- layer 1: h0(16) -> h1(32), same relations, + P1 residual, relu ----
    k_scatter16h<<<dim3(NE / 256, 2), 256>>>(es01, h0h, msg1h);

    k_gemm1<<<(NN + 255) / 256, 256>>>(msg1h, h0, Wc1, bc1, h1, h1h);

    // ---- layer 2: h1(32) -> out(64), 7 relations (mean at 2,3,6), + P2, relu ----
    ESet es2 = {};
    for (int r = 0; r < 7; r++) es2.e[r] = E[2 + r];
    es2.cnt[2] = cnt; es2.cnt[3] = cnt + NN; es2.cnt[6] = cnt + 2 * NN;
    k_scatter32h<<<dim3(NE / 256, 7), 256>>>(es2, h1h, msg2h);

    k_gemm2_tc<<<(NN + 127) / 128, 256>>>(msg2h, h1, cnt, W2hi, W2lo, bc2, (float*)d_out);
}

// round 13
// speedup vs baseline: 3.8479x; 1.0114x over previous
#include <cuda_runtime.h>
#include <cuda_fp16.h>

#define NN 100000
#define NE 800000

// ---------------- scratch (static __device__ globals; no allocs) ----------------
__device__ __align__(16) __half g_msg2h[7 * NN * 32];  // 44.8 MB fp16 messages
__device__ __align__(16) __half g_msg1h[2 * NN * 16];  // 6.4 MB fp16 messages
__device__ __align__(16) float g_msg0[2 * NN * 8];     // padded rows: 6 used + 2 pad
__device__ __align__(16) float g_cnt [3 * NN];
__device__ __align__(16) float g_h0  [NN * 16];
__device__ __align__(16) __half g_h0h[NN * 16];        // fp16 copy for layer-1 gather
__device__ __align__(16) float g_h1  [NN * 32];
__device__ __align__(16) __half g_h1h[NN * 32];        // fp16 copy for layer-2 gather
__device__ __align__(16) float g_Wc0[3 * 6 * 16];
__device__ __align__(16) float g_Wc1[3 * 16 * 32];
__device__ __align__(16) float g_W2hi[8 * 64 * 32];    // [ch][n][k], tf32-exact
__device__ __align__(16) float g_W2lo[8 * 64 * 32];
__device__ __align__(16) float g_bc0[16];
__device__ __align__(16) float g_bc1[32];
__device__ __align__(16) float g_bc2[64];

// ---------------- helpers ----------------
__device__ __forceinline__ void red_add_v4(float* a, float4 v) {
    asm volatile("red.global.add.v4.f32 [%0], {%1,%2,%3,%4};"
                 :: "l"(a), "f"(v.x), "f"(v.y), "f"(v.z), "f"(v.w) : "memory");
}
__device__ __forceinline__ void red_add_v2(float* a, float2 v) {
    asm volatile("red.global.add.v2.f32 [%0], {%1,%2};"
                 :: "l"(a), "f"(v.x), "f"(v.y) : "memory");
}
__device__ __forceinline__ void red_add_f(float* a, float v) {
    asm volatile("red.global.add.f32 [%0], %1;" :: "l"(a), "f"(v) : "memory");
}
// 16B of packed halves (8 halves) reduced in one lane-op (max RED width: 128 bits)
__device__ __forceinline__ void red_add_v4h(__half* a, float4 bits) {
    asm volatile("red.global.add.noftz.v4.f16x2 [%0], {%1,%2,%3,%4};"
                 :: "l"(a), "r"(__float_as_uint(bits.x)), "r"(__float_as_uint(bits.y)),
                    "r"(__float_as_uint(bits.z)), "r"(__float_as_uint(bits.w)) : "memory");
}
__device__ __forceinline__ unsigned tf32_of(float f) {
    unsigned r;
    asm("cvt.rna.tf32.f32 %0, %1;" : "=r"(r) : "f"(f));
    return r;
}
__device__ __forceinline__ void mma_tf32(float* d, unsigned a0, unsigned a1,
                                         unsigned a2, unsigned a3,
                                         unsigned b0, unsigned b1) {
    asm("mma.sync.aligned.m16n8k8.row.col.f32.tf32.tf32.f32 "
        "{%0,%1,%2,%3}, {%4,%5,%6,%7}, {%8,%9}, {%0,%1,%2,%3};"
        : "+f"(d[0]), "+f"(d[1]), "+f"(d[2]), "+f"(d[3])
        : "r"(a0), "r"(a1), "r"(a2), "r"(a3), "r"(b0), "r"(b1));
}

struct ESet { const int* e[7]; float* cnt[7]; };

// ---------------- zero scratch + fold weights (one launch) ----------------
__global__ void k_zero_prep(const float* __restrict__ W0n, const float* __restrict__ W0r,
                            const float* __restrict__ b0,
                            const float* __restrict__ W1n, const float* __restrict__ W1r,
                            const float* __restrict__ b1,  const float* __restrict__ P1,
                            const float* __restrict__ pb1,
                            const float* __restrict__ W2n, const float* __restrict__ W2r,
                            const float* __restrict__ b2,  const float* __restrict__ P2,
                            const float* __restrict__ pb2) {
    int i = blockIdx.x * blockDim.x + threadIdx.x;
    int stride = gridDim.x * blockDim.x;
    // ---- weight folding (low thread ids) ----
    if (i < 192) g_Wc0[i] = W0n[i];
    if (i < 96)  g_Wc0[192 + i] = W0r[i] + W0r[96 + i];
    if (i < 16)  g_bc0[i] = b0[i] + b0[16 + i];
    if (i < 1024) g_Wc1[i] = W1n[i];
    if (i < 512)  g_Wc1[1024 + i] = W1r[i] + W1r[512 + i] + P1[i];
    if (i < 32)   g_bc1[i] = b1[i] + b1[32 + i] + pb1[i];
    if (i < 16384) {
        int ch = i >> 11, j = i & 2047;
        int k = j >> 6, n = j & 63;
        float w;
        if (ch < 7) w = W2n[i];
        else {
            w = P2[j];
            for (int r = 0; r < 7; r++) w += W2r[r * 2048 + j];
        }
        unsigned hi = tf32_of(w);
        unsigned lo = tf32_of(w - __uint_as_float(hi));
        int o = ch * 2048 + n * 32 + k;
        g_W2hi[o] = __uint_as_float(hi);
        g_W2lo[o] = __uint_as_float(lo);
    }
    if (i < 64) {
        float s = pb2[i];
        for (int r = 0; r < 7; r++) s += b2[r * 64 + i];
        g_bc2[i] = s;
    }
    // ---- zeroing (grid-stride) ----
    float4 z = make_float4(0.f, 0.f, 0.f, 0.f);
    float4* a2 = reinterpret_cast<float4*>(g_msg2h);
    for (int t = i; t < 7 * NN * 32 / 8; t += stride) a2[t] = z;
    float4* a1 = reinterpret_cast<float4*>(g_msg1h);
    for (int t = i; t < 2 * NN * 16 / 8; t += stride) a1[t] = z;
    float4* a0 = reinterpret_cast<float4*>(g_msg0);
    for (int t = i; t < 2 * NN * 8 / 4; t += stride) a0[t] = z;
    float4* ac = reinterpret_cast<float4*>(g_cnt);
    for (int t = i; t < 3 * NN / 4; t += stride) ac[t] = z;
}

// ---------------- scatter layer 2: fp16, 4 lanes/edge, v4.f16x2 RED (R7-proven) ----------------
__global__ void __launch_bounds__(256)
k_scatter32h(ESet es, const __half* __restrict__ feat, __half* __restrict__ msg) {
    int lane = threadIdx.x & 31;
    int warp = (blockIdx.x * 256 + threadIdx.x) >> 5;
    int e = warp * 32 + lane;
    int r = blockIdx.y;
    const int* ei = es.e[r];
    int src = __ldg(ei + e);
    int dst = __ldg(ei + NE + e);
    float* cp = es.cnt[r];
    if (cp) red_add_f(cp + dst, 1.0f);
    int sub = lane >> 2;   // edge-within-batch 0..7
    int c   = lane & 3;    // 16B chunk 0..3
#pragma unroll
    for (int j = 0; j < 4; j++) {
        int el = j * 8 + sub;
        int s = __shfl_sync(0xffffffffu, src, el);
        int d = __shfl_sync(0xffffffffu, dst, el);
        float4 v = __ldg(reinterpret_cast<const float4*>(feat + (size_t)s * 32) + c);
        red_add_v4h(msg + ((size_t)r * NN + d) * 32 + 8 * c, v);
    }
}

// ---------------- scatter layer 1: fp16, edge-per-thread, 2x v4.f16x2 RED per edge ----------------
__global__ void __launch_bounds__(256)
k_scatter16h(ESet es, const __half* __restrict__ feat, __half* __restrict__ msg) {
    int e = blockIdx.x * 256 + threadIdx.x;
    int r = blockIdx.y;
    const int* ei = es.e[r];
    int src = __ldg(ei + e);
    int dst = __ldg(ei + NE + e);
    const float4* fp = reinterpret_cast<const float4*>(feat + (size_t)src * 16);
    float4 v0 = __ldg(fp), v1 = __ldg(fp + 1);
    __half* m = msg + ((size_t)r * NN + dst) * 16;
    red_add_v4h(m, v0);
    red_add_v4h(m + 8, v1);
}

// ---------------- scatter layer 0: f32, edge-per-thread, padded msg rows (stride 8) ----------------
__global__ void __launch_bounds__(256)
k_scatter6p(ESet es, const float* __restrict__ x, float* __restrict__ msg) {
    int e = blockIdx.x * 256 + threadIdx.x;
    int r = blockIdx.y;
    const int* ei = es.e[r];
    int src = __ldg(ei + e);
    int dst = __ldg(ei + NE + e);
    const float2* xs = reinterpret_cast<const float2*>(x + (size_t)src * 6);
    float2 a = __ldg(xs), b = __ldg(xs + 1), c = __ldg(xs + 2);
    float* m = msg + ((size_t)r * NN + dst) * 8;   // 32B-aligned row
    red_add_v4(m, make_float4(a.x, a.y, b.x, b.y));
    red_add_v2(m + 4, c);
}

// ---------------- layer-0 GEMM: padded msg channels (f4 staging + prefetch) + x self ----------------
// out = msg0[0]@W0 + msg0[1]@W1 + x@Wself + bias; emits h0 + fp16 h0h.
__global__ void __launch_bounds__(256)
k_gemm0(const float* __restrict__ msg0, const float* __restrict__ x,
        const float* __restrict__ Wcat, const float* __restrict__ bias,
        float* __restrict__ out, __half* __restrict__ hout) {
    constexpr int OUT = 16, LDT = 9;   // 8 payload (6 used) + 1 pad
    __shared__ __align__(16) float shW[6 * OUT];
    __shared__ float shT[256 * LDT];
    int tid  = threadIdx.x;
    int base = blockIdx.x * 256;
    int node = base + tid;

    float acc[OUT];
#pragma unroll
    for (int j = 0; j < OUT; j++) acc[j] = __ldg(bias + j);

    // prefetch msg channel 0: 256 rows x 8 floats = 512 f4
    float4 pre[2];
    {
        const float4* m4 = reinterpret_cast<const float4*>(msg0);
#pragma unroll
        for (int j = 0; j < 2; j++) {
            int f = j * 256 + tid;
            int g = base * 2 + f;
            pre[j] = __ldg(m4 + (g < NN * 2 ? g : NN * 2 - 1));
        }
    }

    for (int ch = 0; ch < 3; ch++) {
        __syncthreads();   // WAR
        if (ch < 2) {
#pragma unroll
            for (int j = 0; j < 2; j++) {
                int f = j * 256 + tid;
                int nl = f >> 1, c = f & 1;
                float4 v = pre[j];
                float* t = shT + nl * LDT + 4 * c;
                t[0] = v.x; t[1] = v.y; t[2] = v.z; t[3] = v.w;
            }
        } else {
            // x channel: each thread stages its own 6 floats (reads only its own row)
            if (node < NN) {
                const float2* xs = reinterpret_cast<const float2*>(x + (size_t)node * 6);
                float2 a = __ldg(xs), b = __ldg(xs + 1), c2 = __ldg(xs + 2);
                float* t = shT + tid * LDT;
                t[0] = a.x; t[1] = a.y; t[2] = b.x; t[3] = b.y; t[4] = c2.x; t[5] = c2.y;
            }
        }
        if (tid < 96) shW[tid] = __ldg(Wcat + ch * 96 + tid);
        __syncthreads();   // RAW

        if (ch == 0) {   // prefetch msg channel 1
            const float4* m4 = reinterpret_cast<const float4*>(msg0 + (size_t)NN * 8);
#pragma unroll
            for (int j = 0; j < 2; j++) {
                int f = j * 256 + tid;
                int g = base * 2 + f;
                pre[j] = __ldg(m4 + (g < NN * 2 ? g : NN * 2 - 1));
            }
        }

#pragma unroll
        for (int k = 0; k < 6; k++) {
            float m = shT[tid * LDT + k];
            const float4* w4 = reinterpret_cast<const float4*>(shW + k * OUT);
#pragma unroll
            for (int j = 0; j < OUT / 4; j++) {
                float4 w = w4[j];
                acc[4 * j + 0] += m * w.x;
                acc[4 * j + 1] += m * w.y;
                acc[4 * j + 2] += m * w.z;
                acc[4 * j + 3] += m * w.w;
            }
        }
    }

    if (node < NN) {
        float4* o4 = reinterpret_cast<float4*>(out + (size_t)node * OUT);
        __half2* h2 = reinterpret_cast<__half2*>(hout + (size_t)node * OUT);
#pragma unroll
        for (int j = 0; j < OUT / 4; j++) {
            float4 v;
            v.x = acc[4 * j + 0]; v.y = acc[4 * j + 1];
            v.z = acc[4 * j + 2]; v.w = acc[4 * j + 3];
            o4[j] = v;
            h2[2 * j]     = __floats2half2_rn(v.x, v.y);
            h2[2 * j + 1] = __floats2half2_rn(v.z, v.w);
        }
    }
}

// ---------------- layer-1 GEMM: 2 fp16 msg channels + f32 self, pipelined (R12-proven) ----------------
__global__ void __launch_bounds__(256)
k_gemm1(const __half* __restrict__ msgh, const float* __restrict__ h0,
        const float* __restrict__ Wcat, const float* __restrict__ bias,
        float* __restrict__ out, __half* __restrict__ hout) {
    constexpr int CHUNK = 16, OUT = 32, LDT = CHUNK + 1;
    __shared__ __align__(16) float shW[CHUNK * OUT];
    __shared__ float shT[256 * LDT];
    int tid  = threadIdx.x;
    int base = blockIdx.x * 256;
    int node = base + tid;

    float acc[OUT];
#pragma unroll
    for (int j = 0; j < OUT; j++) acc[j] = __ldg(bias + j);

    float4 pre[4];
    float4 preW[2];
    {
        const float4* src4 = reinterpret_cast<const float4*>(msgh);
#pragma unroll
        for (int j = 0; j < 2; j++) {
            int f = j * 256 + tid;
            int g = base * 2 + f;
            pre[j] = __ldg(src4 + (g < NN * 2 ? g : NN * 2 - 1));
        }
        const float4* w4 = reinterpret_cast<const float4*>(Wcat);
#pragma unroll
        for (int j = 0; j < 2; j++) {
            int f = j * 256 + tid;
            preW[j] = (f < 128) ? __ldg(w4 + f) : make_float4(0.f, 0.f, 0.f, 0.f);
        }
    }

    for (int ch = 0; ch < 3; ch++) {
        __syncthreads();   // WAR
        if (ch < 2) {
#pragma unroll
            for (int j = 0; j < 2; j++) {
                int f = j * 256 + tid;
                int nl = f >> 1, c = f & 1;
                const __half2* hp = reinterpret_cast<const __half2*>(&pre[j]);
                float* t = shT + nl * LDT + 8 * c;
#pragma unroll
                for (int q = 0; q < 4; q++) {
                    float2 f2 = __half22float2(hp[q]);
                    t[2 * q]     = f2.x;
                    t[2 * q + 1] = f2.y;
                }
            }
        } else {
#pragma unroll
            for (int j = 0; j < 4; j++) {
                int f = j * 256 + tid;
                int nl = f >> 2, c = f & 3;
                float4 v = pre[j];
                float* t = shT + nl * LDT + 4 * c;
                t[0] = v.x; t[1] = v.y; t[2] = v.z; t[3] = v.w;
            }
        }
#pragma unroll
        for (int j = 0; j < 2; j++) {
            int f = j * 256 + tid;
            if (f < 128) reinterpret_cast<float4*>(shW)[f] = preW[j];
        }
        __syncthreads();   // RAW

        if (ch + 1 < 3) {
            if (ch + 1 < 2) {
                const float4* src4 = reinterpret_cast<const float4*>(msgh + (size_t)NN * 16);
#pragma unroll
                for (int j = 0; j < 2; j++) {
                    int f = j * 256 + tid;
                    int g = base * 2 + f;
                    pre[j] = __ldg(src4 + (g < NN * 2 ? g : NN * 2 - 1));
                }
            } else {
                const float4* src4 = reinterpret_cast<const float4*>(h0);
#pragma unroll
                for (int j = 0; j < 4; j++) {
                    int f = j * 256 + tid;
                    int g = base * 4 + f;
                    pre[j] = __ldg(src4 + (g < NN * 4 ? g : NN * 4 - 1));
                }
            }
            const float4* w4 = reinterpret_cast<const float4*>(Wcat + (ch + 1) * CHUNK * OUT);
#pragma unroll
            for (int j = 0; j < 2; j++) {
                int f = j * 256 + tid;
                preW[j] = (f < 128) ? __ldg(w4 + f) : make_float4(0.f, 0.f, 0.f, 0.f);
            }
        }

#pragma unroll 8
        for (int k = 0; k < CHUNK; k++) {
            float m = shT[tid * LDT + k];
            const float4* w4 = reinterpret_cast<const float4*>(shW + k * OUT);
#pragma unroll
            for (int j = 0; j < OUT / 4; j++) {
                float4 w = w4[j];
                acc[4 * j + 0] += m * w.x;
                acc[4 * j + 1] += m * w.y;
                acc[4 * j + 2] += m * w.z;
                acc[4 * j + 3] += m * w.w;
            }
        }
    }

    if (node < NN) {
        float4* o4 = reinterpret_cast<float4*>(out + (size_t)node * OUT);
        __half2* h2 = reinterpret_cast<__half2*>(hout + (size_t)node * OUT);
#pragma unroll
        for (int j = 0; j < OUT / 4; j++) {
            float4 v;
            v.x = fmaxf(acc[4 * j + 0], 0.f);
            v.y = fmaxf(acc[4 * j + 1], 0.f);
            v.z = fmaxf(acc[4 * j + 2], 0.f);
            v.w = fmaxf(acc[4 * j + 3], 0.f);
            o4[j] = v;
            h2[2 * j]     = __floats2half2_rn(v.x, v.y);
            h2[2 * j + 1] = __floats2half2_rn(v.z, v.w);
        }
    }
}

// ---------------- layer-2 GEMM: split-tf32 mma.sync, fp16 msg channels (R7-proven) ----------------
__global__ void __launch_bounds__(256)
k_gemm2_tc(const __half* __restrict__ msgh, const float* __restrict__ h1,
           const float* __restrict__ cnt,
           const float* __restrict__ Whi, const float* __restrict__ Wlo,
           const float* __restrict__ bias, float* __restrict__ out) {
    __shared__ float shA [128 * 36];
    __shared__ float shWh[64 * 36];
    __shared__ float shWl[64 * 36];
    __shared__ float shSc[3][128];
    __shared__ float shB[64];
    int tid  = threadIdx.x;
    int lane = tid & 31;
    int w    = tid >> 5;
    int base = blockIdx.x * 128;

    if (tid < 64) shB[tid] = __ldg(bias + tid);
    if (tid < 128) {
        int node = base + tid;
#pragma unroll
        for (int m = 0; m < 3; m++) {
            float c = (node < NN) ? __ldg(cnt + m * NN + node) : 1.f;
            shSc[m][tid] = 1.f / fmaxf(c, 1.f);
        }
    }

    float d[8][4];
#pragma unroll
    for (int nt = 0; nt < 8; nt++)
#pragma unroll
        for (int j = 0; j < 4; j++) d[nt][j] = 0.f;

    float4 pre[4];
    float4 preW[4];
    {
        const float4* src4 = reinterpret_cast<const float4*>(msgh);
#pragma unroll
        for (int j = 0; j < 2; j++) {
            int f = j * 256 + tid;
            int g = base * 4 + f;
            pre[j] = __ldg(src4 + (g < NN * 4 ? g : NN * 4 - 1));
        }
        const float4* wh4 = reinterpret_cast<const float4*>(Whi);
        const float4* wl4 = reinterpret_cast<const float4*>(Wlo);
#pragma unroll
        for (int j = 0; j < 2; j++) preW[j]     = __ldg(wh4 + j * 256 + tid);
#pragma unroll
        for (int j = 0; j < 2; j++) preW[2 + j] = __ldg(wl4 + j * 256 + tid);
    }

    int rl1 = 16 * w + (lane >> 2);
    int rl2 = rl1 + 8;
    int kc  = lane & 3;
    int nb  = lane >> 2;

    for (int ch = 0; ch < 8; ch++) {
        __syncthreads();   // WAR
        int msel = (ch == 2) ? 0 : (ch == 3) ? 1 : (ch == 6) ? 2 : -1;
        if (ch < 7) {
#pragma unroll
            for (int j = 0; j < 2; j++) {
                int f = j * 256 + tid;
                int nl = f >> 2, c4 = f & 3;
                const __half2* hp = reinterpret_cast<const __half2*>(&pre[j]);
                float sc = (msel >= 0) ? shSc[msel][nl] : 1.f;
                float* t = shA + nl * 36 + 8 * c4;
#pragma unroll
                for (int q = 0; q < 4; q++) {
                    float2 f2 = __half22float2(hp[q]);
                    t[2 * q]     = f2.x * sc;
                    t[2 * q + 1] = f2.y * sc;
                }
            }
        } else {
#pragma unroll
            for (int j = 0; j < 4; j++) {
                int f = j * 256 + tid;
                int nl = f >> 3, c4 = f & 7;
                float4 v = pre[j];
                float* t = shA + nl * 36 + 4 * c4;
                t[0] = v.x; t[1] = v.y; t[2] = v.z; t[3] = v.w;
            }
        }
#pragma unroll
        for (int j = 0; j < 2; j++) {
            int f = j * 256 + tid;
            int n = f >> 3, k4 = f & 7;
            float4 vh = preW[j], vl = preW[2 + j];
            float* th = shWh + n * 36 + 4 * k4;
            float* tl = shWl + n * 36 + 4 * k4;
            th[0] = vh.x; th[1] = vh.y; th[2] = vh.z; th[3] = vh.w;
            tl[0] = vl.x; tl[1] = vl.y; tl[2] = vl.z; tl[3] = vl.w;
        }
        __syncthreads();   // RAW

        if (ch + 1 < 8) {
            if (ch + 1 < 7) {
                const float4* src4 = reinterpret_cast<const float4*>(msgh + (size_t)(ch + 1) * NN * 32);
#pragma unroll
                for (int j = 0; j < 2; j++) {
                    int f = j * 256 + tid;
                    int g = base * 4 + f;
                    pre[j] = __ldg(src4 + (g < NN * 4 ? g : NN * 4 - 1));
                }
            } else {
                const float4* src4 = reinterpret_cast<const float4*>(h1);
#pragma unroll
                for (int j = 0; j < 4; j++) {
                    int f = j * 256 + tid;
                    int g = base * 8 + f;
                    pre[j] = __ldg(src4 + (g < NN * 8 ? g : NN * 8 - 1));
                }
            }
            const float4* wh4 = reinterpret_cast<const float4*>(Whi + (ch + 1) * 2048);
            const float4* wl4 = reinterpret_cast<const float4*>(Wlo + (ch + 1) * 2048);
#pragma unroll
            for (int j = 0; j < 2; j++) preW[j]     = __ldg(wh4 + j * 256 + tid);
#pragma unroll
            for (int j = 0; j < 2; j++) preW[2 + j] = __ldg(wl4 + j * 256 + tid);
        }

        bool needLo = (msel >= 0) || (ch == 7);
#pragma unroll
        for (int k0 = 0; k0 < 32; k0 += 8) {
            int c = k0 + kc;
            float a0f = shA[rl1 * 36 + c];
            float a1f = shA[rl2 * 36 + c];
            float a2f = shA[rl1 * 36 + c + 4];
            float a3f = shA[rl2 * 36 + c + 4];
            unsigned ah0 = tf32_of(a0f), ah1 = tf32_of(a1f);
            unsigned ah2 = tf32_of(a2f), ah3 = tf32_of(a3f);
            unsigned al0 = 0, al1 = 0, al2 = 0, al3 = 0;
            if (needLo) {
                al0 = tf32_of(a0f - __uint_as_float(ah0));
                al1 = tf32_of(a1f - __uint_as_float(ah1));
                al2 = tf32_of(a2f - __uint_as_float(ah2));
                al3 = tf32_of(a3f - __uint_as_float(ah3));
            }
#pragma unroll
            for (int nt = 0; nt < 8; nt++) {
                int wr = (nt * 8 + nb) * 36 + k0 + kc;
                unsigned bh0 = __float_as_uint(shWh[wr]);
                unsigned bh1 = __float_as_uint(shWh[wr + 4]);
                unsigned bl0 = __float_as_uint(shWl[wr]);
                unsigned bl1 = __float_as_uint(shWl[wr + 4]);
                mma_tf32(d[nt], ah0, ah1, ah2, ah3, bh0, bh1);
                mma_tf32(d[nt], ah0, ah1, ah2, ah3, bl0, bl1);
                if (needLo) mma_tf32(d[nt], al0, al1, al2, al3, bh0, bh1);
            }
        }
    }

    int r1 = base + rl1;
    int r2 = base + rl2;
#pragma unroll
    for (int nt = 0; nt < 8; nt++) {
        int c0 = nt * 8 + 2 * kc;
        float b0 = shB[c0], b1 = shB[c0 + 1];
        if (r1 < NN) {
            float2 v;
            v.x = fmaxf(d[nt][0] + b0, 0.f);
            v.y = fmaxf(d[nt][1] + b1, 0.f);
            *reinterpret_cast<float2*>(out + (size_t)r1 * 64 + c0) = v;
        }
        if (r2 < NN) {
            float2 v;
            v.x = fmaxf(d[nt][2] + b0, 0.f);
            v.y = fmaxf(d[nt][3] + b1, 0.f);
            *reinterpret_cast<float2*>(out + (size_t)r2 * 64 + c0) = v;
        }
    }
}

// ---------------- host ----------------
extern "C" void kernel_launch(void* const* d_in, const int* in_sizes, int n_in,
                              void* d_out, int out_size) {
    (void)n_in; (void)out_size;
    const float* x = (const float*)d_in[0];

    int eb, wb;
    if (in_sizes[1] == 2 * NE) { eb = 1; wb = 10; }
    else                        { wb = 1; eb = 14; }

    const int* E[9];
    for (int i = 0; i < 9; i++) E[i] = (const int*)d_in[eb + i];
    const float* W0n = (const float*)d_in[wb + 0];
    const float* W0r = (const float*)d_in[wb + 1];
    const float* b0  = (const float*)d_in[wb + 2];
    const float* W1n = (const float*)d_in[wb + 3];
    const float* W1r = (const float*)d_in[wb + 4];
    const float* b1  = (const float*)d_in[wb + 5];
    const float* P1  = (const float*)d_in[wb + 6];
    const float* pb1 = (const float*)d_in[wb + 7];
    const float* W2n = (const float*)d_in[wb + 8];
    const float* W2r = (const float*)d_in[wb + 9];
    const float* b2  = (const float*)d_in[wb + 10];
    const float* P2  = (const float*)d_in[wb + 11];
    const float* pb2 = (const float*)d_in[wb + 12];

    float *msg0, *cnt, *h0, *h1, *Wc0, *Wc1, *W2hi, *W2lo, *bc0, *bc1, *bc2;
    __half *msg2h, *msg1h, *h0h, *h1h;
    cudaGetSymbolAddress((void**)&msg2h, g_msg2h);
    cudaGetSymbolAddress((void**)&msg1h, g_msg1h);
    cudaGetSymbolAddress((void**)&msg0, g_msg0);
    cudaGetSymbolAddress((void**)&cnt,  g_cnt);
    cudaGetSymbolAddress((void**)&h0,   g_h0);
    cudaGetSymbolAddress((void**)&h0h,  g_h0h);
    cudaGetSymbolAddress((void**)&h1,   g_h1);
    cudaGetSymbolAddress((void**)&h1h,  g_h1h);
    cudaGetSymbolAddress((void**)&Wc0,  g_Wc0);
    cudaGetSymbolAddress((void**)&Wc1,  g_Wc1);
    cudaGetSymbolAddress((void**)&W2hi, g_W2hi);
    cudaGetSymbolAddress((void**)&W2lo, g_W2lo);
    cudaGetSymbolAddress((void**)&bc0,  g_bc0);
    cudaGetSymbolAddress((void**)&bc1,  g_bc1);
    cudaGetSymbolAddress((void**)&bc2,  g_bc2);

    k_zero_prep<<<2048, 256>>>(W0n, W0r, b0, W1n, W1r, b1, P1, pb1, W2n, W2r, b2, P2, pb2);

    // ---- layer 0: x(6) -> h0(16), relations {connected_to, ordered_next}, sum ----
    ESet es01 = {};
    es01.e[0] = E[0]; es01.e[1] = E[1];
    k_scatter6p<<<dim3(NE / 256, 2), 256>>>(es01, x, msg0);

    k_gemm0<<<(NN + 255) / 256, 256>>>(msg0, x, Wc0, bc0, h0, h0h);

    // ---- layer 1: h0(16) -> h1(32), same relations, + P1 residual, relu ----
    k_scatter16h<<<dim3(NE / 256, 2), 256>>>(es01, h0h, msg1h);

    k_gemm1<<<(NN + 255) / 256, 256>>>(msg1h, h0, Wc1, bc1, h1, h1h);

    // ---- layer 2: h1(32) -> out(64), 7 relations (mean at 2,3,6), + P2, relu ----
    ESet es2 = {};
    for (int r = 0; r < 7; r++) es2.e[r] = E[2 + r];
    es2.cnt[2] = cnt; es2.cnt[3] = cnt + NN; es2.cnt[6] = cnt + 2 * NN;
    k_scatter32h<<<dim3(NE / 256, 7), 256>>>(es2, h1h, msg2h);

    k_gemm2_tc<<<(NN + 127) / 128, 256>>>(msg2h, h1, cnt, W2hi, W2lo, bc2, (float*)d_out);
}

// round 14
// speedup vs baseline: 3.9024x; 1.0142x over previous
#include <cuda_runtime.h>
#include <cuda_fp16.h>

#define NN 100000
#define NE 800000

// ---------------- scratch (static __device__ globals; no allocs) ----------------
__device__ __align__(16) __half g_msg2h[7 * NN * 32];  // 44.8 MB fp16 messages
__device__ __align__(16) __half g_msg1h[2 * NN * 16];  // 6.4 MB fp16 messages
__device__ __align__(16) float g_msg0[2 * NN * 8];     // padded rows: 6 used + 2 pad
__device__ __align__(16) float g_xp  [NN * 8];         // padded x copy (6 used + 2 zero)
__device__ __align__(16) float g_cnt [3 * NN];
__device__ __align__(16) float g_h0  [NN * 16];
__device__ __align__(16) __half g_h0h[NN * 16];        // fp16 copy for layer-1 gather
__device__ __align__(16) float g_h1  [NN * 32];
__device__ __align__(16) __half g_h1h[NN * 32];        // fp16 copy for layer-2 gather
__device__ __align__(16) float g_Wc0[3 * 6 * 16];
__device__ __align__(16) float g_Wc1[3 * 16 * 32];
__device__ __align__(16) float g_W2hi[8 * 64 * 32];    // [ch][n][k], tf32-exact
__device__ __align__(16) float g_W2lo[8 * 64 * 32];
__device__ __align__(16) float g_bc0[16];
__device__ __align__(16) float g_bc1[32];
__device__ __align__(16) float g_bc2[64];

// ---------------- helpers ----------------
__device__ __forceinline__ void red_add_v4(float* a, float4 v) {
    asm volatile("red.global.add.v4.f32 [%0], {%1,%2,%3,%4};"
                 :: "l"(a), "f"(v.x), "f"(v.y), "f"(v.z), "f"(v.w) : "memory");
}
__device__ __forceinline__ void red_add_f(float* a, float v) {
    asm volatile("red.global.add.f32 [%0], %1;" :: "l"(a), "f"(v) : "memory");
}
// 16B of packed halves (8 halves) reduced in one lane-op (max RED width: 128 bits)
__device__ __forceinline__ void red_add_v4h(__half* a, float4 bits) {
    asm volatile("red.global.add.noftz.v4.f16x2 [%0], {%1,%2,%3,%4};"
                 :: "l"(a), "r"(__float_as_uint(bits.x)), "r"(__float_as_uint(bits.y)),
                    "r"(__float_as_uint(bits.z)), "r"(__float_as_uint(bits.w)) : "memory");
}
__device__ __forceinline__ unsigned tf32_of(float f) {
    unsigned r;
    asm("cvt.rna.tf32.f32 %0, %1;" : "=r"(r) : "f"(f));
    return r;
}
__device__ __forceinline__ void mma_tf32(float* d, unsigned a0, unsigned a1,
                                         unsigned a2, unsigned a3,
                                         unsigned b0, unsigned b1) {
    asm("mma.sync.aligned.m16n8k8.row.col.f32.tf32.tf32.f32 "
        "{%0,%1,%2,%3}, {%4,%5,%6,%7}, {%8,%9}, {%0,%1,%2,%3};"
        : "+f"(d[0]), "+f"(d[1]), "+f"(d[2]), "+f"(d[3])
        : "r"(a0), "r"(a1), "r"(a2), "r"(a3), "r"(b0), "r"(b1));
}

struct ESet { const int* e[7]; float* cnt[7]; };

// ---------------- zero scratch + fold weights + pad x (one launch) ----------------
__global__ void k_zero_prep(const float* __restrict__ x,
                            const float* __restrict__ W0n, const float* __restrict__ W0r,
                            const float* __restrict__ b0,
                            const float* __restrict__ W1n, const float* __restrict__ W1r,
                            const float* __restrict__ b1,  const float* __restrict__ P1,
                            const float* __restrict__ pb1,
                            const float* __restrict__ W2n, const float* __restrict__ W2r,
                            const float* __restrict__ b2,  const float* __restrict__ P2,
                            const float* __restrict__ pb2) {
    int i = blockIdx.x * blockDim.x + threadIdx.x;
    int stride = gridDim.x * blockDim.x;
    // ---- weight folding (low thread ids) ----
    if (i < 192) g_Wc0[i] = W0n[i];
    if (i < 96)  g_Wc0[192 + i] = W0r[i] + W0r[96 + i];
    if (i < 16)  g_bc0[i] = b0[i] + b0[16 + i];
    if (i < 1024) g_Wc1[i] = W1n[i];
    if (i < 512)  g_Wc1[1024 + i] = W1r[i] + W1r[512 + i] + P1[i];
    if (i < 32)   g_bc1[i] = b1[i] + b1[32 + i] + pb1[i];
    if (i < 16384) {
        int ch = i >> 11, j = i & 2047;
        int k = j >> 6, n = j & 63;
        float w;
        if (ch < 7) w = W2n[i];
        else {
            w = P2[j];
            for (int r = 0; r < 7; r++) w += W2r[r * 2048 + j];
        }
        unsigned hi = tf32_of(w);
        unsigned lo = tf32_of(w - __uint_as_float(hi));
        int o = ch * 2048 + n * 32 + k;
        g_W2hi[o] = __uint_as_float(hi);
        g_W2lo[o] = __uint_as_float(lo);
    }
    if (i < 64) {
        float s = pb2[i];
        for (int r = 0; r < 7; r++) s += b2[r * 64 + i];
        g_bc2[i] = s;
    }
    // ---- padded x copy ----
    for (int t = i; t < NN * 8; t += stride) {
        int node = t >> 3, c = t & 7;
        g_xp[t] = (c < 6) ? __ldg(x + node * 6 + c) : 0.f;
    }
    // ---- zeroing (grid-stride) ----
    float4 z = make_float4(0.f, 0.f, 0.f, 0.f);
    float4* a2 = reinterpret_cast<float4*>(g_msg2h);
    for (int t = i; t < 7 * NN * 32 / 8; t += stride) a2[t] = z;
    float4* a1 = reinterpret_cast<float4*>(g_msg1h);
    for (int t = i; t < 2 * NN * 16 / 8; t += stride) a1[t] = z;
    float4* a0 = reinterpret_cast<float4*>(g_msg0);
    for (int t = i; t < 2 * NN * 8 / 4; t += stride) a0[t] = z;
    float4* ac = reinterpret_cast<float4*>(g_cnt);
    for (int t = i; t < 3 * NN / 4; t += stride) ac[t] = z;
}

// ---------------- scatter layer 2: fp16, 4 lanes/edge, v4.f16x2 RED (R7-proven) ----------------
__global__ void __launch_bounds__(256)
k_scatter32h(ESet es, const __half* __restrict__ feat, __half* __restrict__ msg) {
    int lane = threadIdx.x & 31;
    int warp = (blockIdx.x * 256 + threadIdx.x) >> 5;
    int e = warp * 32 + lane;
    int r = blockIdx.y;
    const int* ei = es.e[r];
    int src = __ldg(ei + e);
    int dst = __ldg(ei + NE + e);
    float* cp = es.cnt[r];
    if (cp) red_add_f(cp + dst, 1.0f);
    int sub = lane >> 2;   // edge-within-batch 0..7
    int c   = lane & 3;    // 16B chunk 0..3
#pragma unroll
    for (int j = 0; j < 4; j++) {
        int el = j * 8 + sub;
        int s = __shfl_sync(0xffffffffu, src, el);
        int d = __shfl_sync(0xffffffffu, dst, el);
        float4 v = __ldg(reinterpret_cast<const float4*>(feat + (size_t)s * 32) + c);
        red_add_v4h(msg + ((size_t)r * NN + d) * 32 + 8 * c, v);
    }
}

// ---------------- scatter layer 1: fp16, warp-coop 2 lanes/edge (coalesced lines) ----------------
__global__ void __launch_bounds__(256)
k_scatter16h(ESet es, const __half* __restrict__ feat, __half* __restrict__ msg) {
    int lane = threadIdx.x & 31;
    int warp = (blockIdx.x * 256 + threadIdx.x) >> 5;
    int e = warp * 32 + lane;
    int r = blockIdx.y;
    const int* ei = es.e[r];
    int src = __ldg(ei + e);
    int dst = __ldg(ei + NE + e);
    int sub = lane >> 1;   // edge-within-batch 0..15
    int c   = lane & 1;    // 16B chunk 0..1
#pragma unroll
    for (int j = 0; j < 2; j++) {
        int el = j * 16 + sub;
        int s = __shfl_sync(0xffffffffu, src, el);
        int d = __shfl_sync(0xffffffffu, dst, el);
        float4 v = __ldg(reinterpret_cast<const float4*>(feat + (size_t)s * 16) + c);
        red_add_v4h(msg + ((size_t)r * NN + d) * 16 + 8 * c, v);
    }
}

// ---------------- scatter layer 0: f32 padded rows, warp-coop 2 lanes/edge ----------------
// xp rows are 8 floats (cols 6,7 zero); pad columns accumulate zeros into msg0 pad.
__global__ void __launch_bounds__(256)
k_scatter6p(ESet es, const float* __restrict__ xp, float* __restrict__ msg) {
    int lane = threadIdx.x & 31;
    int warp = (blockIdx.x * 256 + threadIdx.x) >> 5;
    int e = warp * 32 + lane;
    int r = blockIdx.y;
    const int* ei = es.e[r];
    int src = __ldg(ei + e);
    int dst = __ldg(ei + NE + e);
    int sub = lane >> 1;   // edge-within-batch 0..15
    int c   = lane & 1;    // 16B chunk 0..1
#pragma unroll
    for (int j = 0; j < 2; j++) {
        int el = j * 16 + sub;
        int s = __shfl_sync(0xffffffffu, src, el);
        int d = __shfl_sync(0xffffffffu, dst, el);
        float4 v = __ldg(reinterpret_cast<const float4*>(xp + (size_t)s * 8) + c);
        red_add_v4(msg + ((size_t)r * NN + d) * 8 + 4 * c, v);
    }
}

// ---------------- layer-0 GEMM: 3 uniform stride-8 f4 channels (msg0 x2, xp) ----------------
// out = msg0[0]@W0 + msg0[1]@W1 + x@Wself + bias; emits h0 + fp16 h0h.
__global__ void __launch_bounds__(256)
k_gemm0(const float* __restrict__ msg0, const float* __restrict__ xp,
        const float* __restrict__ Wcat, const float* __restrict__ bias,
        float* __restrict__ out, __half* __restrict__ hout) {
    constexpr int OUT = 16, LDT = 9;   // 8 payload (6 used) + 1 pad
    __shared__ __align__(16) float shW[6 * OUT];
    __shared__ float shT[256 * LDT];
    int tid  = threadIdx.x;
    int base = blockIdx.x * 256;
    int node = base + tid;

    const float* chp[3] = { msg0, msg0 + (size_t)NN * 8, xp };

    float acc[OUT];
#pragma unroll
    for (int j = 0; j < OUT; j++) acc[j] = __ldg(bias + j);

    float4 pre[2];
    {
        const float4* m4 = reinterpret_cast<const float4*>(chp[0]);
#pragma unroll
        for (int j = 0; j < 2; j++) {
            int f = j * 256 + tid;
            int g = base * 2 + f;
            pre[j] = __ldg(m4 + (g < NN * 2 ? g : NN * 2 - 1));
        }
    }

    for (int ch = 0; ch < 3; ch++) {
        __syncthreads();   // WAR
#pragma unroll
        for (int j = 0; j < 2; j++) {
            int f = j * 256 + tid;
            int nl = f >> 1, c = f & 1;
            float4 v = pre[j];
            float* t = shT + nl * LDT + 4 * c;
            t[0] = v.x; t[1] = v.y; t[2] = v.z; t[3] = v.w;
        }
        if (tid < 96) shW[tid] = __ldg(Wcat + ch * 96 + tid);
        __syncthreads();   // RAW

        if (ch + 1 < 3) {
            const float4* m4 = reinterpret_cast<const float4*>(chp[ch + 1]);
#pragma unroll
            for (int j = 0; j < 2; j++) {
                int f = j * 256 + tid;
                int g = base * 2 + f;
                pre[j] = __ldg(m4 + (g < NN * 2 ? g : NN * 2 - 1));
            }
        }

#pragma unroll
        for (int k = 0; k < 6; k++) {
            float m = shT[tid * LDT + k];
            const float4* w4 = reinterpret_cast<const float4*>(shW + k * OUT);
#pragma unroll
            for (int j = 0; j < OUT / 4; j++) {
                float4 w = w4[j];
                acc[4 * j + 0] += m * w.x;
                acc[4 * j + 1] += m * w.y;
                acc[4 * j + 2] += m * w.z;
                acc[4 * j + 3] += m * w.w;
            }
        }
    }

    if (node < NN) {
        float4* o4 = reinterpret_cast<float4*>(out + (size_t)node * OUT);
        __half2* h2 = reinterpret_cast<__half2*>(hout + (size_t)node * OUT);
#pragma unroll
        for (int j = 0; j < OUT / 4; j++) {
            float4 v;
            v.x = acc[4 * j + 0]; v.y = acc[4 * j + 1];
            v.z = acc[4 * j + 2]; v.w = acc[4 * j + 3];
            o4[j] = v;
            h2[2 * j]     = __floats2half2_rn(v.x, v.y);
            h2[2 * j + 1] = __floats2half2_rn(v.z, v.w);
        }
    }
}

// ---------------- layer-1 GEMM: 2 fp16 msg channels + f32 self, pipelined (R12-proven) ----------------
__global__ void __launch_bounds__(256)
k_gemm1(const __half* __restrict__ msgh, const float* __restrict__ h0,
        const float* __restrict__ Wcat, const float* __restrict__ bias,
        float* __restrict__ out, __half* __restrict__ hout) {
    constexpr int CHUNK = 16, OUT = 32, LDT = CHUNK + 1;
    __shared__ __align__(16) float shW[CHUNK * OUT];
    __shared__ float shT[256 * LDT];
    int tid  = threadIdx.x;
    int base = blockIdx.x * 256;
    int node = base + tid;

    float acc[OUT];
#pragma unroll
    for (int j = 0; j < OUT; j++) acc[j] = __ldg(bias + j);

    float4 pre[4];
    float4 preW[2];
    {
        const float4* src4 = reinterpret_cast<const float4*>(msgh);
#pragma unroll
        for (int j = 0; j < 2; j++) {
            int f = j * 256 + tid;
            int g = base * 2 + f;
            pre[j] = __ldg(src4 + (g < NN * 2 ? g : NN * 2 - 1));
        }
        const float4* w4 = reinterpret_cast<const float4*>(Wcat);
#pragma unroll
        for (int j = 0; j < 2; j++) {
            int f = j * 256 + tid;
            preW[j] = (f < 128) ? __ldg(w4 + f) : make_float4(0.f, 0.f, 0.f, 0.f);
        }
    }

    for (int ch = 0; ch < 3; ch++) {
        __syncthreads();   // WAR
        if (ch < 2) {
#pragma unroll
            for (int j = 0; j < 2; j++) {
                int f = j * 256 + tid;
                int nl = f >> 1, c = f & 1;
                const __half2* hp = reinterpret_cast<const __half2*>(&pre[j]);
                float* t = shT + nl * LDT + 8 * c;
#pragma unroll
                for (int q = 0; q < 4; q++) {
                    float2 f2 = __half22float2(hp[q]);
                    t[2 * q]     = f2.x;
                    t[2 * q + 1] = f2.y;
                }
            }
        } else {
#pragma unroll
            for (int j = 0; j < 4; j++) {
                int f = j * 256 + tid;
                int nl = f >> 2, c = f & 3;
                float4 v = pre[j];
                float* t = shT + nl * LDT + 4 * c;
                t[0] = v.x; t[1] = v.y; t[2] = v.z; t[3] = v.w;
            }
        }
#pragma unroll
        for (int j = 0; j < 2; j++) {
            int f = j * 256 + tid;
            if (f < 128) reinterpret_cast<float4*>(shW)[f] = preW[j];
        }
        __syncthreads();   // RAW

        if (ch + 1 < 3) {
            if (ch + 1 < 2) {
                const float4* src4 = reinterpret_cast<const float4*>(msgh + (size_t)NN * 16);
#pragma unroll
                for (int j = 0; j < 2; j++) {
                    int f = j * 256 + tid;
                    int g = base * 2 + f;
                    pre[j] = __ldg(src4 + (g < NN * 2 ? g : NN * 2 - 1));
                }
            } else {
                const float4* src4 = reinterpret_cast<const float4*>(h0);
#pragma unroll
                for (int j = 0; j < 4; j++) {
                    int f = j * 256 + tid;
                    int g = base * 4 + f;
                    pre[j] = __ldg(src4 + (g < NN * 4 ? g : NN * 4 - 1));
                }
            }
            const float4* w4 = reinterpret_cast<const float4*>(Wcat + (ch + 1) * CHUNK * OUT);
#pragma unroll
            for (int j = 0; j < 2; j++) {
                int f = j * 256 + tid;
                preW[j] = (f < 128) ? __ldg(w4 + f) : make_float4(0.f, 0.f, 0.f, 0.f);
            }
        }

#pragma unroll 8
        for (int k = 0; k < CHUNK; k++) {
            float m = shT[tid * LDT + k];
            const float4* w4 = reinterpret_cast<const float4*>(shW + k * OUT);
#pragma unroll
            for (int j = 0; j < OUT / 4; j++) {
                float4 w = w4[j];
                acc[4 * j + 0] += m * w.x;
                acc[4 * j + 1] += m * w.y;
                acc[4 * j + 2] += m * w.z;
                acc[4 * j + 3] += m * w.w;
            }
        }
    }

    if (node < NN) {
        float4* o4 = reinterpret_cast<float4*>(out + (size_t)node * OUT);
        __half2* h2 = reinterpret_cast<__half2*>(hout + (size_t)node * OUT);
#pragma unroll
        for (int j = 0; j < OUT / 4; j++) {
            float4 v;
            v.x = fmaxf(acc[4 * j + 0], 0.f);
            v.y = fmaxf(acc[4 * j + 1], 0.f);
            v.z = fmaxf(acc[4 * j + 2], 0.f);
            v.w = fmaxf(acc[4 * j + 3], 0.f);
            o4[j] = v;
            h2[2 * j]     = __floats2half2_rn(v.x, v.y);
            h2[2 * j + 1] = __floats2half2_rn(v.z, v.w);
        }
    }
}

// ---------------- layer-2 GEMM: split-tf32 mma.sync, fp16 msg channels (R7-proven) ----------------
__global__ void __launch_bounds__(256)
k_gemm2_tc(const __half* __restrict__ msgh, const float* __restrict__ h1,
           const float* __restrict__ cnt,
           const float* __restrict__ Whi, const float* __restrict__ Wlo,
           const float* __restrict__ bias, float* __restrict__ out) {
    __shared__ float shA [128 * 36];
    __shared__ float shWh[64 * 36];
    __shared__ float shWl[64 * 36];
    __shared__ float shSc[3][128];
    __shared__ float shB[64];
    int tid  = threadIdx.x;
    int lane = tid & 31;
    int w    = tid >> 5;
    int base = blockIdx.x * 128;

    if (tid < 64) shB[tid] = __ldg(bias + tid);
    if (tid < 128) {
        int node = base + tid;
#pragma unroll
        for (int m = 0; m < 3; m++) {
            float c = (node < NN) ? __ldg(cnt + m * NN + node) : 1.f;
            shSc[m][tid] = 1.f / fmaxf(c, 1.f);
        }
    }

    float d[8][4];
#pragma unroll
    for (int nt = 0; nt < 8; nt++)
#pragma unroll
        for (int j = 0; j < 4; j++) d[nt][j] = 0.f;

    float4 pre[4];
    float4 preW[4];
    {
        const float4* src4 = reinterpret_cast<const float4*>(msgh);
#pragma unroll
        for (int j = 0; j < 2; j++) {
            int f = j * 256 + tid;
            int g = base * 4 + f;
            pre[j] = __ldg(src4 + (g < NN * 4 ? g : NN * 4 - 1));
        }
        const float4* wh4 = reinterpret_cast<const float4*>(Whi);
        const float4* wl4 = reinterpret_cast<const float4*>(Wlo);
#pragma unroll
        for (int j = 0; j < 2; j++) preW[j]     = __ldg(wh4 + j * 256 + tid);
#pragma unroll
        for (int j = 0; j < 2; j++) preW[2 + j] = __ldg(wl4 + j * 256 + tid);
    }

    int rl1 = 16 * w + (lane >> 2);
    int rl2 = rl1 + 8;
    int kc  = lane & 3;
    int nb  = lane >> 2;

    for (int ch = 0; ch < 8; ch++) {
        __syncthreads();   // WAR
        int msel = (ch == 2) ? 0 : (ch == 3) ? 1 : (ch == 6) ? 2 : -1;
        if (ch < 7) {
#pragma unroll
            for (int j = 0; j < 2; j++) {
                int f = j * 256 + tid;
                int nl = f >> 2, c4 = f & 3;
                const __half2* hp = reinterpret_cast<const __half2*>(&pre[j]);
                float sc = (msel >= 0) ? shSc[msel][nl] : 1.f;
                float* t = shA + nl * 36 + 8 * c4;
#pragma unroll
                for (int q = 0; q < 4; q++) {
                    float2 f2 = __half22float2(hp[q]);
                    t[2 * q]     = f2.x * sc;
                    t[2 * q + 1] = f2.y * sc;
                }
            }
        } else {
#pragma unroll
            for (int j = 0; j < 4; j++) {
                int f = j * 256 + tid;
                int nl = f >> 3, c4 = f & 7;
                float4 v = pre[j];
                float* t = shA + nl * 36 + 4 * c4;
                t[0] = v.x; t[1] = v.y; t[2] = v.z; t[3] = v.w;
            }
        }
#pragma unroll
        for (int j = 0; j < 2; j++) {
            int f = j * 256 + tid;
            int n = f >> 3, k4 = f & 7;
            float4 vh = preW[j], vl = preW[2 + j];
            float* th = shWh + n * 36 + 4 * k4;
            float* tl = shWl + n * 36 + 4 * k4;
            th[0] = vh.x; th[1] = vh.y; th[2] = vh.z; th[3] = vh.w;
            tl[0] = vl.x; tl[1] = vl.y; tl[2] = vl.z; tl[3] = vl.w;
        }
        __syncthreads();   // RAW

        if (ch + 1 < 8) {
            if (ch + 1 < 7) {
                const float4* src4 = reinterpret_cast<const float4*>(msgh + (size_t)(ch + 1) * NN * 32);
#pragma unroll
                for (int j = 0; j < 2; j++) {
                    int f = j * 256 + tid;
                    int g = base * 4 + f;
                    pre[j] = __ldg(src4 + (g < NN * 4 ? g : NN * 4 - 1));
                }
            } else {
                const float4* src4 = reinterpret_cast<const float4*>(h1);
#pragma unroll
                for (int j = 0; j < 4; j++) {
                    int f = j * 256 + tid;
                    int g = base * 8 + f;
                    pre[j] = __ldg(src4 + (g < NN * 8 ? g : NN * 8 - 1));
                }
            }
            const float4* wh4 = reinterpret_cast<const float4*>(Whi + (ch + 1) * 2048);
            const float4* wl4 = reinterpret_cast<const float4*>(Wlo + (ch + 1) * 2048);
#pragma unroll
            for (int j = 0; j < 2; j++) preW[j]     = __ldg(wh4 + j * 256 + tid);
#pragma unroll
            for (int j = 0; j < 2; j++) preW[2 + j] = __ldg(wl4 + j * 256 + tid);
        }

        bool needLo = (msel >= 0) || (ch == 7);
#pragma unroll
        for (int k0 = 0; k0 < 32; k0 += 8) {
            int c = k0 + kc;
            float a0f = shA[rl1 * 36 + c];
            float a1f = shA[rl2 * 36 + c];
            float a2f = shA[rl1 * 36 + c + 4];
            float a3f = shA[rl2 * 36 + c + 4];
            unsigned ah0 = tf32_of(a0f), ah1 = tf32_of(a1f);
            unsigned ah2 = tf32_of(a2f), ah3 = tf32_of(a3f);
            unsigned al0 = 0, al1 = 0, al2 = 0, al3 = 0;
            if (needLo) {
                al0 = tf32_of(a0f - __uint_as_float(ah0));
                al1 = tf32_of(a1f - __uint_as_float(ah1));
                al2 = tf32_of(a2f - __uint_as_float(ah2));
                al3 = tf32_of(a3f - __uint_as_float(ah3));
            }
#pragma unroll
            for (int nt = 0; nt < 8; nt++) {
                int wr = (nt * 8 + nb) * 36 + k0 + kc;
                unsigned bh0 = __float_as_uint(shWh[wr]);
                unsigned bh1 = __float_as_uint(shWh[wr + 4]);
                unsigned bl0 = __float_as_uint(shWl[wr]);
                unsigned bl1 = __float_as_uint(shWl[wr + 4]);
                mma_tf32(d[nt], ah0, ah1, ah2, ah3, bh0, bh1);
                mma_tf32(d[nt], ah0, ah1, ah2, ah3, bl0, bl1);
                if (needLo) mma_tf32(d[nt], al0, al1, al2, al3, bh0, bh1);
            }
        }
    }

    int r1 = base + rl1;
    int r2 = base + rl2;
#pragma unroll
    for (int nt = 0; nt < 8; nt++) {
        int c0 = nt * 8 + 2 * kc;
        float b0 = shB[c0], b1 = shB[c0 + 1];
        if (r1 < NN) {
            float2 v;
            v.x = fmaxf(d[nt][0] + b0, 0.f);
            v.y = fmaxf(d[nt][1] + b1, 0.f);
            *reinterpret_cast<float2*>(out + (size_t)r1 * 64 + c0) = v;
        }
        if (r2 < NN) {
            float2 v;
            v.x = fmaxf(d[nt][2] + b0, 0.f);
            v.y = fmaxf(d[nt][3] + b1, 0.f);
            *reinterpret_cast<float2*>(out + (size_t)r2 * 64 + c0) = v;
        }
    }
}

// ---------------- host ----------------
extern "C" void kernel_launch(void* const* d_in, const int* in_sizes, int n_in,
                              void* d_out, int out_size) {
    (void)n_in; (void)out_size;
    const float* x = (const float*)d_in[0];

    int eb, wb;
    if (in_sizes[1] == 2 * NE) { eb = 1; wb = 10; }
    else                        { wb = 1; eb = 14; }

    const int* E[9];
    for (int i = 0; i < 9; i++) E[i] = (const int*)d_in[eb + i];
    const float* W0n = (const float*)d_in[wb + 0];
    const float* W0r = (const float*)d_in[wb + 1];
    const float* b0  = (const float*)d_in[wb + 2];
    const float* W1n = (const float*)d_in[wb + 3];
    const float* W1r = (const float*)d_in[wb + 4];
    const float* b1  = (const float*)d_in[wb + 5];
    const float* P1  = (const float*)d_in[wb + 6];
    const float* pb1 = (const float*)d_in[wb + 7];
    const float* W2n = (const float*)d_in[wb + 8];
    const float* W2r = (const float*)d_in[wb + 9];
    const float* b2  = (const float*)d_in[wb + 10];
    const float* P2  = (const float*)d_in[wb + 11];
    const float* pb2 = (const float*)d_in[wb + 12];

    float *msg0, *xp, *cnt, *h0, *h1, *Wc0, *Wc1, *W2hi, *W2lo, *bc0, *bc1, *bc2;
    __half *msg2h, *msg1h, *h0h, *h1h;
    cudaGetSymbolAddress((void**)&msg2h, g_msg2h);
    cudaGetSymbolAddress((void**)&msg1h, g_msg1h);
    cudaGetSymbolAddress((void**)&msg0, g_msg0);
    cudaGetSymbolAddress((void**)&xp,   g_xp);
    cudaGetSymbolAddress((void**)&cnt,  g_cnt);
    cudaGetSymbolAddress((void**)&h0,   g_h0);
    cudaGetSymbolAddress((void**)&h0h,  g_h0h);
    cudaGetSymbolAddress((void**)&h1,   g_h1);
    cudaGetSymbolAddress((void**)&h1h,  g_h1h);
    cudaGetSymbolAddress((void**)&Wc0,  g_Wc0);
    cudaGetSymbolAddress((void**)&Wc1,  g_Wc1);
    cudaGetSymbolAddress((void**)&W2hi, g_W2hi);
    cudaGetSymbolAddress((void**)&W2lo, g_W2lo);
    cudaGetSymbolAddress((void**)&bc0,  g_bc0);
    cudaGetSymbolAddress((void**)&bc1,  g_bc1);
    cudaGetSymbolAddress((void**)&bc2,  g_bc2);

    k_zero_prep<<<2048, 256>>>(x, W0n, W0r, b0, W1n, W1r, b1, P1, pb1, W2n, W2r, b2, P2, pb2);

    // ---- layer 0: x(6) -> h0(16), relations {connected_to, ordered_next}, sum ----
    ESet es01 = {};
    es01.e[0] = E[0]; es01.e[1] = E[1];
    k_scatter6p<<<dim3(NE / 256, 2), 256>>>(es01, xp, msg0);

    k_gemm0<<<(NN + 255) / 256, 256>>>(msg0, xp, Wc0, bc0, h0, h0h);

    // ---- layer 1: h0(16) -> h1(32), same relations, + P1 residual, relu ----
    k_scatter16h<<<dim3(NE / 256, 2), 256>>>(es01, h0h, msg1h);

    k_gemm1<<<(NN + 255) / 256, 256>>>(msg1h, h0, Wc1, bc1, h1, h1h);

    // ---- layer 2: h1(32) -> out(64), 7 relations (mean at 2,3,6), + P2, relu ----
    ESet es2 = {};
    for (int r = 0; r < 7; r++) es2.e[r] = E[2 + r];
    es2.cnt[2] = cnt; es2.cnt[3] = cnt + NN; es2.cnt[6] = cnt + 2 * NN;
    k_scatter32h<<<dim3(NE / 256, 7), 256>>>(es2, h1h, msg2h);

    k_gemm2_tc<<<(NN + 127) / 128, 256>>>(msg2h, h1, cnt, W2hi, W2lo, bc2, (float*)d_out);
}